// round 9
// baseline (speedup 1.0000x reference)
#include <cuda_runtime.h>
#include <cuda_fp16.h>
#include <cstdint>

#define HD 256
#define HF 512
#define NMAX 50000
#define EMAX 800000
#define SCAN_BLK 512

// ------------------------- scratch (device globals) ------------------------
__device__ __half g_x_h[(size_t)NMAX * HD];
__device__ __half g_ag_h[(size_t)NMAX * HD];
__device__ __half g_h_h[(size_t)NMAX * HD];
__device__ __half g_t_h[(size_t)NMAX * HF];
__device__ __half g_wn_h[HD * HD];
__device__ __half g_wr_h[HD * HD];
__device__ __half g_w1_h[HD * HF];
__device__ __half g_w2_h[HD * HF];
__device__ int g_deg[NMAX];
__device__ int g_off[NMAX + 1];
__device__ int g_cur[NMAX];
__device__ int g_srcl[EMAX];
__device__ int g_bsum[(NMAX + SCAN_BLK - 1) / SCAN_BLK];
__device__ int g_is64;

// ----------------------------- helpers -------------------------------------
__device__ __forceinline__ uint32_t smem_u32(const void* p) {
    uint32_t a;
    asm("{ .reg .u64 t; cvta.to.shared.u64 t, %1; cvt.u32.u64 %0, t; }" : "=r"(a) : "l"(p));
    return a;
}
__device__ __forceinline__ void ldsm_x4(uint32_t* r, uint32_t addr) {
    asm volatile("ldmatrix.sync.aligned.m8n8.x4.shared.b16 {%0,%1,%2,%3}, [%4];"
                 : "=r"(r[0]), "=r"(r[1]), "=r"(r[2]), "=r"(r[3]) : "r"(addr));
}
__device__ __forceinline__ void mma_f16(float* d, const uint32_t* a, const uint32_t* b) {
    asm volatile(
        "mma.sync.aligned.m16n8k16.row.col.f32.f16.f16.f32 "
        "{%0,%1,%2,%3}, {%4,%5,%6,%7}, {%8,%9}, {%0,%1,%2,%3};"
        : "+f"(d[0]), "+f"(d[1]), "+f"(d[2]), "+f"(d[3])
        : "r"(a[0]), "r"(a[1]), "r"(a[2]), "r"(a[3]), "r"(b[0]), "r"(b[1]));
}
__device__ __forceinline__ void cp_async16(uint32_t dst, const void* src, int szr) {
    asm volatile("cp.async.cg.shared.global [%0], [%1], 16, %2;"
                 :: "r"(dst), "l"(src), "r"(szr) : "memory");
}
#define CP_COMMIT() asm volatile("cp.async.commit_group;" ::: "memory")
#define CP_WAIT2()  asm volatile("cp.async.wait_group 2;" ::: "memory")
#define CP_WAIT0()  asm volatile("cp.async.wait_group 0;" ::: "memory")

__device__ __forceinline__ uint32_t packh2(float a, float b) {
    __half2 h = __float22half2_rn(make_float2(a, b));
    return *(uint32_t*)&h;
}

// --------------------------- small kernels ---------------------------------
__global__ void detect_kernel(const int* __restrict__ ei, int twoE) {
    int nz = 0;
    int lim = twoE * 2;
    if (lim > 256) lim = 256;
    for (int i = 1; i < lim; i += 2) nz |= ei[i];
    g_is64 = (nz == 0) ? 1 : 0;
}

__global__ void hist_kernel(const int* __restrict__ ei, int E, int* __restrict__ deg) {
    int t = blockIdx.x * blockDim.x + threadIdx.x;
    if (g_is64) {
        int e0 = t * 2;
        if (e0 >= E) return;
        if (e0 + 2 <= E) {
            int4 d = *(const int4*)(ei + 2 * (E + e0));
            atomicAdd(&deg[d.x], 1);
            atomicAdd(&deg[d.z], 1);
        } else {
            atomicAdd(&deg[ei[2 * (E + e0)]], 1);
        }
    } else {
        int e0 = t * 4;
        if (e0 >= E) return;
        if (e0 + 4 <= E) {
            int4 d = *(const int4*)(ei + E + e0);
            atomicAdd(&deg[d.x], 1);
            atomicAdd(&deg[d.y], 1);
            atomicAdd(&deg[d.z], 1);
            atomicAdd(&deg[d.w], 1);
        } else {
            for (int e = e0; e < E; ++e) atomicAdd(&deg[ei[E + e]], 1);
        }
    }
}

// ---- parallel 3-phase scan ----
__global__ void block_scan_kernel(const int* __restrict__ deg, int* __restrict__ off,
                                  int* __restrict__ bsum, int M) {
    __shared__ int wsum[SCAN_BLK / 32];
    int t = threadIdx.x;
    int i = blockIdx.x * SCAN_BLK + t;
    int lane = t & 31, wid = t >> 5;
    int v = (i < M) ? deg[i] : 0;
    int s = v;
#pragma unroll
    for (int o = 1; o < 32; o <<= 1) {
        int u = __shfl_up_sync(0xFFFFFFFFu, s, o);
        if (lane >= o) s += u;
    }
    if (lane == 31) wsum[wid] = s;
    __syncthreads();
    if (wid == 0) {
        int w = (lane < SCAN_BLK / 32) ? wsum[lane] : 0;
#pragma unroll
        for (int o = 1; o < SCAN_BLK / 32; o <<= 1) {
            int u = __shfl_up_sync(0xFFFFFFFFu, w, o);
            if (lane >= o) w += u;
        }
        if (lane < SCAN_BLK / 32) wsum[lane] = w;
    }
    __syncthreads();
    int excl = s - v + (wid ? wsum[wid - 1] : 0);
    if (i < M) off[i] = excl;
    if (t == SCAN_BLK - 1) bsum[blockIdx.x] = excl + v;
}

__global__ void bscan_kernel(int* __restrict__ bsum, int* __restrict__ offM, int nB) {
    __shared__ int ws[4];
    int t = threadIdx.x;        // 128 threads
    int lane = t & 31, wid = t >> 5;
    int v = (t < nB) ? bsum[t] : 0;
    int s = v;
#pragma unroll
    for (int o = 1; o < 32; o <<= 1) {
        int u = __shfl_up_sync(0xFFFFFFFFu, s, o);
        if (lane >= o) s += u;
    }
    if (lane == 31) ws[wid] = s;
    __syncthreads();
    if (t == 0) {
        int r = 0;
#pragma unroll
        for (int i = 0; i < 4; ++i) { int x = ws[i]; ws[i] = r; r += x; }
        *offM = r;
    }
    __syncthreads();
    int excl = s - v + ws[wid];
    if (t < nB) bsum[t] = excl;
}

__global__ void add_off_kernel(int* __restrict__ off, int* __restrict__ cur,
                               const int* __restrict__ bsum, int M) {
    int i = blockIdx.x * SCAN_BLK + threadIdx.x;
    if (i < M) {
        int v = off[i] + bsum[blockIdx.x];
        off[i] = v;
        cur[i] = v;
    }
}

__global__ void fill_kernel(const int* __restrict__ ei, int E,
                            int* __restrict__ cur, int* __restrict__ srcl) {
    int t = blockIdx.x * blockDim.x + threadIdx.x;
    if (g_is64) {
        int e0 = t * 2;
        if (e0 >= E) return;
        if (e0 + 2 <= E) {
            int4 s = *(const int4*)(ei + 2 * e0);
            int4 d = *(const int4*)(ei + 2 * (E + e0));
            srcl[atomicAdd(&cur[d.x], 1)] = s.x;
            srcl[atomicAdd(&cur[d.z], 1)] = s.z;
        } else {
            srcl[atomicAdd(&cur[ei[2 * (E + e0)]], 1)] = ei[2 * e0];
        }
    } else {
        int e0 = t * 4;
        if (e0 >= E) return;
        if (e0 + 4 <= E) {
            int4 s = *(const int4*)(ei + e0);
            int4 d = *(const int4*)(ei + E + e0);
            srcl[atomicAdd(&cur[d.x], 1)] = s.x;
            srcl[atomicAdd(&cur[d.y], 1)] = s.y;
            srcl[atomicAdd(&cur[d.z], 1)] = s.z;
            srcl[atomicAdd(&cur[d.w], 1)] = s.w;
        } else {
            for (int e = e0; e < E; ++e)
                srcl[atomicAdd(&cur[ei[E + e]], 1)] = ei[e];
        }
    }
}

// gather: one warp per node; unroll-16 neighbor batches (MLP=16); fp16 out
__global__ void __launch_bounds__(256)
gather_kernel(const int* __restrict__ off, const int* __restrict__ srcl,
              const __half* __restrict__ xh, __half* __restrict__ agh, int M) {
    int node = blockIdx.x * 8 + (threadIdx.x >> 5);
    int lane = threadIdx.x & 31;
    if (node >= M) return;
    int j0 = off[node], j1 = off[node + 1];

    float acc[8];
#pragma unroll
    for (int k = 0; k < 8; ++k) acc[k] = 0.f;

    const uint4* xb = (const uint4*)xh;
    int j = j0;
    for (; j + 16 <= j1; j += 16) {
        int srcs[16];
#pragma unroll
        for (int u = 0; u < 16; ++u) srcs[u] = srcl[j + u];
        uint4 v[16];
#pragma unroll
        for (int u = 0; u < 16; ++u) v[u] = xb[(size_t)srcs[u] * 32 + lane];
#pragma unroll
        for (int u = 0; u < 16; ++u) {
            float2 f0 = __half22float2(*(const __half2*)&v[u].x);
            float2 f1 = __half22float2(*(const __half2*)&v[u].y);
            float2 f2 = __half22float2(*(const __half2*)&v[u].z);
            float2 f3 = __half22float2(*(const __half2*)&v[u].w);
            acc[0] += f0.x; acc[1] += f0.y; acc[2] += f1.x; acc[3] += f1.y;
            acc[4] += f2.x; acc[5] += f2.y; acc[6] += f3.x; acc[7] += f3.y;
        }
    }
    for (; j + 4 <= j1; j += 4) {
        int srcs[4];
#pragma unroll
        for (int u = 0; u < 4; ++u) srcs[u] = srcl[j + u];
        uint4 v[4];
#pragma unroll
        for (int u = 0; u < 4; ++u) v[u] = xb[(size_t)srcs[u] * 32 + lane];
#pragma unroll
        for (int u = 0; u < 4; ++u) {
            float2 f0 = __half22float2(*(const __half2*)&v[u].x);
            float2 f1 = __half22float2(*(const __half2*)&v[u].y);
            float2 f2 = __half22float2(*(const __half2*)&v[u].z);
            float2 f3 = __half22float2(*(const __half2*)&v[u].w);
            acc[0] += f0.x; acc[1] += f0.y; acc[2] += f1.x; acc[3] += f1.y;
            acc[4] += f2.x; acc[5] += f2.y; acc[6] += f3.x; acc[7] += f3.y;
        }
    }
    for (; j < j1; ++j) {
        uint4 v = xb[(size_t)srcl[j] * 32 + lane];
        float2 f0 = __half22float2(*(const __half2*)&v.x);
        float2 f1 = __half22float2(*(const __half2*)&v.y);
        float2 f2 = __half22float2(*(const __half2*)&v.z);
        float2 f3 = __half22float2(*(const __half2*)&v.w);
        acc[0] += f0.x; acc[1] += f0.y; acc[2] += f1.x; acc[3] += f1.y;
        acc[4] += f2.x; acc[5] += f2.y; acc[6] += f3.x; acc[7] += f3.y;
    }

    uint32_t hi[4];
#pragma unroll
    for (int k = 0; k < 4; ++k) hi[k] = packh2(acc[2 * k], acc[2 * k + 1]);
    ((uint4*)agh)[(size_t)node * 32 + lane] = make_uint4(hi[0], hi[1], hi[2], hi[3]);
}

__global__ void conv_kernel(const float* __restrict__ in,
                            __half* __restrict__ oh, int n4) {
    int i = blockIdx.x * blockDim.x + threadIdx.x;
    if (i >= n4) return;
    float4 v = ((const float4*)in)[i];
    ((uint2*)oh)[i] = make_uint2(packh2(v.x, v.y), packh2(v.z, v.w));
}

// tiled transpose: W [K,N] fp32 -> out [N,K] fp16
__global__ void ttrans_kernel(const float* __restrict__ W,
                              __half* __restrict__ out, int K, int N) {
    __shared__ float tile[32][33];
    int k0 = blockIdx.x * 32;
    int n0 = blockIdx.y * 32;
    int tx = threadIdx.x, ty = threadIdx.y;   // 32 x 8
#pragma unroll
    for (int i = 0; i < 4; ++i)
        tile[ty + i * 8][tx] = W[(size_t)(k0 + ty + i * 8) * N + n0 + tx];
    __syncthreads();
#pragma unroll
    for (int i = 0; i < 4; ++i)
        out[(size_t)(n0 + ty + i * 8) * K + k0 + tx] =
            __float2half_rn(tile[tx][ty + i * 8]);
}

// ----------------------- fp16 single-term mma.sync GEMM --------------------
// BM=64, BN=256, BK=32, 256 threads, 4-stage cp.async pipeline, 2 CTAs/SM.
#define STAGE_BYTES 25600
#define NSTAGE 4
#define SMEM_TOTAL (NSTAGE * STAGE_BYTES)

__device__ __forceinline__ void load_stage(
    uint32_t sa, int tid, int row0, int col0,
    const __half* A, const __half* B, int K, int kc, int M) {
    {
        int r = tid >> 2, c = tid & 3;
        int row = row0 + r;
        int szr = (row < M) ? 16 : 0;
        size_t roff = (row < M) ? (size_t)row : 0;
        cp_async16(sa + r * 80 + c * 16, A + roff * K + kc + c * 8, szr);
    }
    uint32_t sb = sa + 5120;
#pragma unroll
    for (int j = 0; j < 4; ++j) {
        int id = tid + j * 256;
        int r = id >> 2, c = id & 3;
        cp_async16(sb + r * 80 + c * 16, B + (size_t)(col0 + r) * K + kc + c * 8, 16);
    }
}

// MODE 0: C = A@B(+A1@B1) + bias + resid(fp16) -> LN -> outf(fp32)? / outh(fp16)?
// MODE 1: C = relu(A@B + bias) -> fp16 outh (stride HF)
template <int MODE>
__global__ void __launch_bounds__(256, 2)
gemm_mma(const __half* __restrict__ A0, const __half* __restrict__ B0, int K0,
         const __half* __restrict__ A1, const __half* __restrict__ B1, int K1,
         const float* __restrict__ bias, const __half* __restrict__ resid,
         const float* __restrict__ gamma, const float* __restrict__ beta,
         float* __restrict__ outf, __half* __restrict__ outh, int M) {
    extern __shared__ char smem[];
    const uint32_t sb0 = smem_u32(smem);
    const int tid = threadIdx.x;
    const int lane = tid & 31;
    const int warp = tid >> 5;
    const int warpM = warp >> 2;
    const int warpN = warp & 3;
    const int row0 = blockIdx.x * 64;
    const int col0 = blockIdx.y * 256;

    float acc[2][8][4];
#pragma unroll
    for (int i = 0; i < 2; ++i)
#pragma unroll
        for (int j = 0; j < 8; ++j)
#pragma unroll
            for (int k = 0; k < 4; ++k) acc[i][j][k] = 0.f;

    const int S = (K0 + K1) >> 5;

    const uint32_t aoff = (uint32_t)((warpM * 32 + (lane & 7) + ((lane >> 3) & 1) * 8) * 80
                                     + (lane >> 4) * 16);
    const uint32_t boff4 = (uint32_t)((warpN * 64 + (lane & 7) + (lane >> 4) * 8) * 80
                                      + ((lane >> 3) & 1) * 16);

#define RESOLVE(IT, AH, BH, KK, KC)                             \
    { int kt = (IT) * 32;                                       \
      if (kt < K0) { AH = A0; BH = B0; KK = K0; KC = kt; }      \
      else         { AH = A1; BH = B1; KK = K1; KC = kt - K0; } }

#pragma unroll
    for (int p = 0; p < NSTAGE - 1; ++p) {
        if (p < S) {
            const __half *Ah, *Bh; int KK, KC;
            RESOLVE(p, Ah, Bh, KK, KC);
            load_stage(sb0 + p * STAGE_BYTES, tid, row0, col0, Ah, Bh, KK, KC, M);
        }
        CP_COMMIT();
    }

    int stage = 0;
    for (int it = 0; it < S; ++it) {
        CP_WAIT2();
        __syncthreads();
        if (it + NSTAGE - 1 < S) {
            int s2 = stage + NSTAGE - 1; if (s2 >= NSTAGE) s2 -= NSTAGE;
            const __half *Ah, *Bh; int KK, KC;
            RESOLVE(it + NSTAGE - 1, Ah, Bh, KK, KC);
            load_stage(sb0 + s2 * STAGE_BYTES, tid, row0, col0, Ah, Bh, KK, KC, M);
        }
        CP_COMMIT();

        const uint32_t sa = sb0 + stage * STAGE_BYTES;
        const uint32_t sbB = sa + 5120;
#pragma unroll
        for (int ks = 0; ks < 2; ++ks) {
            uint32_t ah[2][4];
#pragma unroll
            for (int tm = 0; tm < 2; ++tm)
                ldsm_x4(ah[tm], sa + aoff + tm * 1280 + ks * 32);
#pragma unroll
            for (int tnp = 0; tnp < 4; ++tnp) {
                uint32_t bh[4];
                ldsm_x4(bh, sbB + boff4 + tnp * 1280 + ks * 32);
#pragma unroll
                for (int tm = 0; tm < 2; ++tm) {
                    mma_f16(acc[tm][2 * tnp + 0], ah[tm], bh);
                    mma_f16(acc[tm][2 * tnp + 1], ah[tm], bh + 2);
                }
            }
        }
        ++stage; if (stage == NSTAGE) stage = 0;
    }

    CP_WAIT0();
    __syncthreads();

    // ---------------------------- epilogue ---------------------------------
    float* rsum  = (float*)smem;
    float* rsq   = rsum + 64;
    float* sbias = rsq + 64;
    float* sgam  = sbias + 256;
    float* sbet  = sgam + 256;
    if (MODE == 0 && tid < 64) { rsum[tid] = 0.f; rsq[tid] = 0.f; }
    sbias[tid] = bias[col0 + tid];
    if (MODE == 0) { sgam[tid] = gamma[tid]; sbet[tid] = beta[tid]; }
    __syncthreads();

    const int qrow = lane >> 2;
    const int qc = (lane & 3) * 2;

    float vsum[4], vsq[4];
#pragma unroll
    for (int k = 0; k < 4; ++k) { vsum[k] = 0.f; vsq[k] = 0.f; }

#pragma unroll
    for (int tm = 0; tm < 2; ++tm) {
#pragma unroll
        for (int rh = 0; rh < 2; ++rh) {
            int rloc = warpM * 32 + tm * 16 + rh * 8 + qrow;
            int rg = row0 + rloc;
            bool v = rg < M;
#pragma unroll
            for (int tn = 0; tn < 8; ++tn) {
                int c = warpN * 64 + tn * 8 + qc;
                float a0 = acc[tm][tn][rh * 2 + 0] + sbias[c];
                float a1 = acc[tm][tn][rh * 2 + 1] + sbias[c + 1];
                if (MODE == 0) {
                    if (v) {
                        uint32_t rp = ((const uint32_t*)resid)[((size_t)rg * 256 + c) >> 1];
                        float2 q = __half22float2(*(const __half2*)&rp);
                        a0 += q.x; a1 += q.y;
                    }
                    vsum[tm * 2 + rh] += a0 + a1;
                    vsq[tm * 2 + rh] += a0 * a0 + a1 * a1;
                } else {
                    a0 = fmaxf(a0, 0.f); a1 = fmaxf(a1, 0.f);
                }
                acc[tm][tn][rh * 2 + 0] = a0;
                acc[tm][tn][rh * 2 + 1] = a1;
            }
        }
    }

    if (MODE == 0) {
#pragma unroll
        for (int k = 0; k < 4; ++k) {
            vsum[k] += __shfl_xor_sync(0xFFFFFFFFu, vsum[k], 1);
            vsum[k] += __shfl_xor_sync(0xFFFFFFFFu, vsum[k], 2);
            vsq[k]  += __shfl_xor_sync(0xFFFFFFFFu, vsq[k], 1);
            vsq[k]  += __shfl_xor_sync(0xFFFFFFFFu, vsq[k], 2);
        }
        if ((lane & 3) == 0) {
#pragma unroll
            for (int tm = 0; tm < 2; ++tm)
#pragma unroll
                for (int rh = 0; rh < 2; ++rh) {
                    int rloc = warpM * 32 + tm * 16 + rh * 8 + qrow;
                    atomicAdd(&rsum[rloc], vsum[tm * 2 + rh]);
                    atomicAdd(&rsq[rloc], vsq[tm * 2 + rh]);
                }
        }
        __syncthreads();
    }

#pragma unroll
    for (int tm = 0; tm < 2; ++tm) {
#pragma unroll
        for (int rh = 0; rh < 2; ++rh) {
            int rloc = warpM * 32 + tm * 16 + rh * 8 + qrow;
            int rg = row0 + rloc;
            if (rg >= M) continue;
            float mean = 0.f, inv = 1.f;
            if (MODE == 0) {
                mean = rsum[rloc] * (1.f / 256.f);
                inv = rsqrtf(rsq[rloc] * (1.f / 256.f) - mean * mean + 1e-5f);
            }
#pragma unroll
            for (int tn = 0; tn < 8; ++tn) {
                int c = warpN * 64 + tn * 8 + qc;
                float a0 = acc[tm][tn][rh * 2 + 0];
                float a1 = acc[tm][tn][rh * 2 + 1];
                if (MODE == 0) {
                    a0 = (a0 - mean) * inv * sgam[c] + sbet[c];
                    a1 = (a1 - mean) * inv * sgam[c + 1] + sbet[c + 1];
                    if (outf != nullptr)
                        *(float2*)(outf + (size_t)rg * 256 + c) = make_float2(a0, a1);
                    if (outh != nullptr)
                        ((uint32_t*)outh)[((size_t)rg * 256 + c) >> 1] = packh2(a0, a1);
                } else {
                    ((uint32_t*)outh)[((size_t)rg * HF + col0 + c) >> 1] = packh2(a0, a1);
                }
            }
        }
    }
}

// ------------------------------ launch --------------------------------------
extern "C" void kernel_launch(void* const* d_in, const int* in_sizes, int n_in,
                              void* d_out, int out_size) {
    const float* x      = (const float*)d_in[0];
    const int*   ei     = (const int*)d_in[1];
    const float* W_nbr  = (const float*)d_in[2];
    const float* W_root = (const float*)d_in[3];
    const float* b_gnn  = (const float*)d_in[4];
    const float* W1     = (const float*)d_in[5];
    const float* b1     = (const float*)d_in[6];
    const float* W2     = (const float*)d_in[7];
    const float* b2     = (const float*)d_in[8];
    const float* g1     = (const float*)d_in[9];
    const float* be1    = (const float*)d_in[10];
    const float* g2     = (const float*)d_in[11];
    const float* be2    = (const float*)d_in[12];
    float* out = (float*)d_out;

    const int M = in_sizes[0] / HD;
    const int E = in_sizes[1] / 2;

    __half *xh, *agh, *hh, *th, *wnh, *wrh, *w1h, *w2h;
    int *deg, *off, *cur, *srcl, *bsum;
    cudaGetSymbolAddress((void**)&xh, g_x_h);
    cudaGetSymbolAddress((void**)&agh, g_ag_h);
    cudaGetSymbolAddress((void**)&hh, g_h_h);
    cudaGetSymbolAddress((void**)&th, g_t_h);
    cudaGetSymbolAddress((void**)&wnh, g_wn_h);
    cudaGetSymbolAddress((void**)&wrh, g_wr_h);
    cudaGetSymbolAddress((void**)&w1h, g_w1_h);
    cudaGetSymbolAddress((void**)&w2h, g_w2_h);
    cudaGetSymbolAddress((void**)&deg, g_deg);
    cudaGetSymbolAddress((void**)&off, g_off);
    cudaGetSymbolAddress((void**)&cur, g_cur);
    cudaGetSymbolAddress((void**)&srcl, g_srcl);
    cudaGetSymbolAddress((void**)&bsum, g_bsum);

    cudaFuncSetAttribute(gemm_mma<0>, cudaFuncAttributeMaxDynamicSharedMemorySize, SMEM_TOTAL);
    cudaFuncSetAttribute(gemm_mma<1>, cudaFuncAttributeMaxDynamicSharedMemorySize, SMEM_TOTAL);

    int n4 = M * HD / 4;
    conv_kernel<<<(n4 + 255) / 256, 256>>>(x, xh, n4);
    detect_kernel<<<1, 1>>>(ei, 2 * E);

    cudaMemsetAsync(deg, 0, M * sizeof(int));
    hist_kernel<<<(E / 2 + 255) / 256, 256>>>(ei, E, deg);

    int nB = (M + SCAN_BLK - 1) / SCAN_BLK;
    block_scan_kernel<<<nB, SCAN_BLK>>>(deg, off, bsum, M);
    bscan_kernel<<<1, 128>>>(bsum, off + M, nB);
    add_off_kernel<<<nB, SCAN_BLK>>>(off, cur, bsum, M);

    fill_kernel<<<(E / 2 + 255) / 256, 256>>>(ei, E, cur, srcl);
    gather_kernel<<<(M + 7) / 8, 256>>>(off, srcl, xh, agh, M);

    ttrans_kernel<<<dim3(HD / 32, HD / 32), dim3(32, 8)>>>(W_nbr, wnh, HD, HD);
    ttrans_kernel<<<dim3(HD / 32, HD / 32), dim3(32, 8)>>>(W_root, wrh, HD, HD);
    ttrans_kernel<<<dim3(HD / 32, HF / 32), dim3(32, 8)>>>(W1, w1h, HD, HF);
    ttrans_kernel<<<dim3(HF / 32, HD / 32), dim3(32, 8)>>>(W2, w2h, HF, HD);

    int gx = (M + 63) / 64;

    // hh = fp16 LN1(x + agg@Wnbr + x@Wroot + b_gnn)   (resid = xh fp16)
    gemm_mma<0><<<dim3(gx, 1), 256, SMEM_TOTAL>>>(
        agh, wnh, HD, xh, wrh, HD, b_gnn, xh, g1, be1, nullptr, hh, M);

    // th = relu(hh@W1 + b1)
    gemm_mma<1><<<dim3(gx, 2), 256, SMEM_TOTAL>>>(
        hh, w1h, HD, nullptr, nullptr, 0,
        b1, nullptr, nullptr, nullptr, nullptr, th, M);

    // out = LN2(hh + th@W2 + b2)  fp32 to d_out  (resid = hh fp16)
    gemm_mma<0><<<dim3(gx, 1), 256, SMEM_TOTAL>>>(
        th, w2h, HF, nullptr, nullptr, 0,
        b2, hh, g2, be2, out, nullptr, M);
}

// round 10
// speedup vs baseline: 1.0112x; 1.0112x over previous
#include <cuda_runtime.h>
#include <cuda_fp16.h>
#include <cstdint>

#define HD 256
#define HF 512
#define NMAX 50000
#define EMAX 800000
#define SCAN_BLK 512

// ------------------------- scratch (device globals) ------------------------
__device__ __half g_x_h[(size_t)NMAX * HD];
__device__ __half g_ag_h[(size_t)NMAX * HD];
__device__ __half g_h_h[(size_t)NMAX * HD];
__device__ __half g_t_h[(size_t)NMAX * HF];
__device__ __half g_wn_h[HD * HD];
__device__ __half g_wr_h[HD * HD];
__device__ __half g_w1_h[HD * HF];
__device__ __half g_w2_h[HD * HF];
__device__ int g_deg[NMAX];
__device__ int g_off[NMAX + 1];
__device__ int g_cur[NMAX];
__device__ int g_srcl[EMAX];
__device__ int g_bsum[(NMAX + SCAN_BLK - 1) / SCAN_BLK];
__device__ int g_is64;

// ----------------------------- helpers -------------------------------------
__device__ __forceinline__ uint32_t smem_u32(const void* p) {
    uint32_t a;
    asm("{ .reg .u64 t; cvta.to.shared.u64 t, %1; cvt.u32.u64 %0, t; }" : "=r"(a) : "l"(p));
    return a;
}
__device__ __forceinline__ void ldsm_x4(uint32_t* r, uint32_t addr) {
    asm volatile("ldmatrix.sync.aligned.m8n8.x4.shared.b16 {%0,%1,%2,%3}, [%4];"
                 : "=r"(r[0]), "=r"(r[1]), "=r"(r[2]), "=r"(r[3]) : "r"(addr));
}
__device__ __forceinline__ void mma_f16(float* d, const uint32_t* a, const uint32_t* b) {
    asm volatile(
        "mma.sync.aligned.m16n8k16.row.col.f32.f16.f16.f32 "
        "{%0,%1,%2,%3}, {%4,%5,%6,%7}, {%8,%9}, {%0,%1,%2,%3};"
        : "+f"(d[0]), "+f"(d[1]), "+f"(d[2]), "+f"(d[3])
        : "r"(a[0]), "r"(a[1]), "r"(a[2]), "r"(a[3]), "r"(b[0]), "r"(b[1]));
}
__device__ __forceinline__ void cp_async16(uint32_t dst, const void* src, int szr) {
    asm volatile("cp.async.cg.shared.global [%0], [%1], 16, %2;"
                 :: "r"(dst), "l"(src), "r"(szr) : "memory");
}
#define CP_COMMIT() asm volatile("cp.async.commit_group;" ::: "memory")
#define CP_WAIT2()  asm volatile("cp.async.wait_group 2;" ::: "memory")
#define CP_WAIT0()  asm volatile("cp.async.wait_group 0;" ::: "memory")

__device__ __forceinline__ uint32_t packh2(float a, float b) {
    __half2 h = __float22half2_rn(make_float2(a, b));
    return *(uint32_t*)&h;
}

// --------------------------- small kernels ---------------------------------
__global__ void detect_kernel(const int* __restrict__ ei, int twoE) {
    int lim = twoE * 2;
    if (lim > 256) lim = 256;
    int idx = threadIdx.x * 2 + 1;          // odd words
    int nz = (idx < lim) ? ei[idx] : 0;
    int any = __syncthreads_or(nz != 0);
    if (threadIdx.x == 0) g_is64 = (any == 0) ? 1 : 0;
}

__global__ void hist_kernel(const int* __restrict__ ei, int E, int* __restrict__ deg) {
    int t = blockIdx.x * blockDim.x + threadIdx.x;
    if (g_is64) {
        int e0 = t * 2;
        if (e0 >= E) return;
        if (e0 + 2 <= E) {
            int4 d = *(const int4*)(ei + 2 * (E + e0));
            atomicAdd(&deg[d.x], 1);
            atomicAdd(&deg[d.z], 1);
        } else {
            atomicAdd(&deg[ei[2 * (E + e0)]], 1);
        }
    } else {
        int e0 = t * 4;
        if (e0 >= E) return;
        if (e0 + 4 <= E) {
            int4 d = *(const int4*)(ei + E + e0);
            atomicAdd(&deg[d.x], 1);
            atomicAdd(&deg[d.y], 1);
            atomicAdd(&deg[d.z], 1);
            atomicAdd(&deg[d.w], 1);
        } else {
            for (int e = e0; e < E; ++e) atomicAdd(&deg[ei[E + e]], 1);
        }
    }
}

// ---- parallel 3-phase scan ----
__global__ void block_scan_kernel(const int* __restrict__ deg, int* __restrict__ off,
                                  int* __restrict__ bsum, int M) {
    __shared__ int wsum[SCAN_BLK / 32];
    int t = threadIdx.x;
    int i = blockIdx.x * SCAN_BLK + t;
    int lane = t & 31, wid = t >> 5;
    int v = (i < M) ? deg[i] : 0;
    int s = v;
#pragma unroll
    for (int o = 1; o < 32; o <<= 1) {
        int u = __shfl_up_sync(0xFFFFFFFFu, s, o);
        if (lane >= o) s += u;
    }
    if (lane == 31) wsum[wid] = s;
    __syncthreads();
    if (wid == 0) {
        int w = (lane < SCAN_BLK / 32) ? wsum[lane] : 0;
#pragma unroll
        for (int o = 1; o < SCAN_BLK / 32; o <<= 1) {
            int u = __shfl_up_sync(0xFFFFFFFFu, w, o);
            if (lane >= o) w += u;
        }
        if (lane < SCAN_BLK / 32) wsum[lane] = w;
    }
    __syncthreads();
    int excl = s - v + (wid ? wsum[wid - 1] : 0);
    if (i < M) off[i] = excl;
    if (t == SCAN_BLK - 1) bsum[blockIdx.x] = excl + v;
}

__global__ void bscan_kernel(int* __restrict__ bsum, int* __restrict__ offM, int nB) {
    __shared__ int ws[4];
    int t = threadIdx.x;        // 128 threads
    int lane = t & 31, wid = t >> 5;
    int v = (t < nB) ? bsum[t] : 0;
    int s = v;
#pragma unroll
    for (int o = 1; o < 32; o <<= 1) {
        int u = __shfl_up_sync(0xFFFFFFFFu, s, o);
        if (lane >= o) s += u;
    }
    if (lane == 31) ws[wid] = s;
    __syncthreads();
    if (t == 0) {
        int r = 0;
#pragma unroll
        for (int i = 0; i < 4; ++i) { int x = ws[i]; ws[i] = r; r += x; }
        *offM = r;
    }
    __syncthreads();
    int excl = s - v + ws[wid];
    if (t < nB) bsum[t] = excl;
}

__global__ void add_off_kernel(int* __restrict__ off, int* __restrict__ cur,
                               const int* __restrict__ bsum, int M) {
    int i = blockIdx.x * SCAN_BLK + threadIdx.x;
    if (i < M) {
        int v = off[i] + bsum[blockIdx.x];
        off[i] = v;
        cur[i] = v;
    }
}

__global__ void fill_kernel(const int* __restrict__ ei, int E,
                            int* __restrict__ cur, int* __restrict__ srcl) {
    int t = blockIdx.x * blockDim.x + threadIdx.x;
    if (g_is64) {
        int e0 = t * 2;
        if (e0 >= E) return;
        if (e0 + 2 <= E) {
            int4 s = *(const int4*)(ei + 2 * e0);
            int4 d = *(const int4*)(ei + 2 * (E + e0));
            srcl[atomicAdd(&cur[d.x], 1)] = s.x;
            srcl[atomicAdd(&cur[d.z], 1)] = s.z;
        } else {
            srcl[atomicAdd(&cur[ei[2 * (E + e0)]], 1)] = ei[2 * e0];
        }
    } else {
        int e0 = t * 4;
        if (e0 >= E) return;
        if (e0 + 4 <= E) {
            int4 s = *(const int4*)(ei + e0);
            int4 d = *(const int4*)(ei + E + e0);
            srcl[atomicAdd(&cur[d.x], 1)] = s.x;
            srcl[atomicAdd(&cur[d.y], 1)] = s.y;
            srcl[atomicAdd(&cur[d.z], 1)] = s.z;
            srcl[atomicAdd(&cur[d.w], 1)] = s.w;
        } else {
            for (int e = e0; e < E; ++e)
                srcl[atomicAdd(&cur[ei[E + e]], 1)] = ei[e];
        }
    }
}

// gather: one warp per node; unroll-8 neighbor batches (MLP=8); fp16 out
__global__ void __launch_bounds__(256)
gather_kernel(const int* __restrict__ off, const int* __restrict__ srcl,
              const __half* __restrict__ xh, __half* __restrict__ agh, int M) {
    int node = blockIdx.x * 8 + (threadIdx.x >> 5);
    int lane = threadIdx.x & 31;
    if (node >= M) return;
    int j0 = off[node], j1 = off[node + 1];

    float acc[8];
#pragma unroll
    for (int k = 0; k < 8; ++k) acc[k] = 0.f;

    const uint4* xb = (const uint4*)xh;
    int j = j0;
    for (; j + 8 <= j1; j += 8) {
        int srcs[8];
#pragma unroll
        for (int u = 0; u < 8; ++u) srcs[u] = srcl[j + u];
        uint4 v[8];
#pragma unroll
        for (int u = 0; u < 8; ++u) v[u] = xb[(size_t)srcs[u] * 32 + lane];
#pragma unroll
        for (int u = 0; u < 8; ++u) {
            float2 f0 = __half22float2(*(const __half2*)&v[u].x);
            float2 f1 = __half22float2(*(const __half2*)&v[u].y);
            float2 f2 = __half22float2(*(const __half2*)&v[u].z);
            float2 f3 = __half22float2(*(const __half2*)&v[u].w);
            acc[0] += f0.x; acc[1] += f0.y; acc[2] += f1.x; acc[3] += f1.y;
            acc[4] += f2.x; acc[5] += f2.y; acc[6] += f3.x; acc[7] += f3.y;
        }
    }
    for (; j < j1; ++j) {
        uint4 v = xb[(size_t)srcl[j] * 32 + lane];
        float2 f0 = __half22float2(*(const __half2*)&v.x);
        float2 f1 = __half22float2(*(const __half2*)&v.y);
        float2 f2 = __half22float2(*(const __half2*)&v.z);
        float2 f3 = __half22float2(*(const __half2*)&v.w);
        acc[0] += f0.x; acc[1] += f0.y; acc[2] += f1.x; acc[3] += f1.y;
        acc[4] += f2.x; acc[5] += f2.y; acc[6] += f3.x; acc[7] += f3.y;
    }

    uint32_t hi[4];
#pragma unroll
    for (int k = 0; k < 4; ++k) hi[k] = packh2(acc[2 * k], acc[2 * k + 1]);
    ((uint4*)agh)[(size_t)node * 32 + lane] = make_uint4(hi[0], hi[1], hi[2], hi[3]);
}

__global__ void conv_kernel(const float* __restrict__ in,
                            __half* __restrict__ oh, int n4) {
    int i = blockIdx.x * blockDim.x + threadIdx.x;
    if (i >= n4) return;
    float4 v = ((const float4*)in)[i];
    ((uint2*)oh)[i] = make_uint2(packh2(v.x, v.y), packh2(v.z, v.w));
}

// tiled transpose: W [K,N] fp32 -> out [N,K] fp16
__global__ void ttrans_kernel(const float* __restrict__ W,
                              __half* __restrict__ out, int K, int N) {
    __shared__ float tile[32][33];
    int k0 = blockIdx.x * 32;
    int n0 = blockIdx.y * 32;
    int tx = threadIdx.x, ty = threadIdx.y;   // 32 x 8
#pragma unroll
    for (int i = 0; i < 4; ++i)
        tile[ty + i * 8][tx] = W[(size_t)(k0 + ty + i * 8) * N + n0 + tx];
    __syncthreads();
#pragma unroll
    for (int i = 0; i < 4; ++i)
        out[(size_t)(n0 + ty + i * 8) * K + k0 + tx] =
            __float2half_rn(tile[tx][ty + i * 8]);
}

// ----------------------- fp16 single-term mma.sync GEMM --------------------
// BM=64, BN=256, BK=32, 256 threads, 4-stage cp.async pipeline, 2 CTAs/SM.
#define STAGE_BYTES 25600
#define NSTAGE 4
#define SMEM_TOTAL (NSTAGE * STAGE_BYTES)

__device__ __forceinline__ void load_stage(
    uint32_t sa, int tid, int row0, int col0,
    const __half* A, const __half* B, int K, int kc, int M) {
    {
        int r = tid >> 2, c = tid & 3;
        int row = row0 + r;
        int szr = (row < M) ? 16 : 0;
        size_t roff = (row < M) ? (size_t)row : 0;
        cp_async16(sa + r * 80 + c * 16, A + roff * K + kc + c * 8, szr);
    }
    uint32_t sb = sa + 5120;
#pragma unroll
    for (int j = 0; j < 4; ++j) {
        int id = tid + j * 256;
        int r = id >> 2, c = id & 3;
        cp_async16(sb + r * 80 + c * 16, B + (size_t)(col0 + r) * K + kc + c * 8, 16);
    }
}

// MODE 0: C = A@B(+A1@B1) + bias + resid(fp16) -> LN -> outf(fp32)? / outh(fp16)?
// MODE 1: C = relu(A@B + bias) -> fp16 outh (stride HF)
template <int MODE>
__global__ void __launch_bounds__(256, 2)
gemm_mma(const __half* __restrict__ A0, const __half* __restrict__ B0, int K0,
         const __half* __restrict__ A1, const __half* __restrict__ B1, int K1,
         const float* __restrict__ bias, const __half* __restrict__ resid,
         const float* __restrict__ gamma, const float* __restrict__ beta,
         float* __restrict__ outf, __half* __restrict__ outh, int M) {
    extern __shared__ char smem[];
    const uint32_t sb0 = smem_u32(smem);
    const int tid = threadIdx.x;
    const int lane = tid & 31;
    const int warp = tid >> 5;
    const int warpM = warp >> 2;
    const int warpN = warp & 3;
    const int row0 = blockIdx.x * 64;
    const int col0 = blockIdx.y * 256;

    float acc[2][8][4];
#pragma unroll
    for (int i = 0; i < 2; ++i)
#pragma unroll
        for (int j = 0; j < 8; ++j)
#pragma unroll
            for (int k = 0; k < 4; ++k) acc[i][j][k] = 0.f;

    const int S = (K0 + K1) >> 5;

    const uint32_t aoff = (uint32_t)((warpM * 32 + (lane & 7) + ((lane >> 3) & 1) * 8) * 80
                                     + (lane >> 4) * 16);
    const uint32_t boff4 = (uint32_t)((warpN * 64 + (lane & 7) + (lane >> 4) * 8) * 80
                                      + ((lane >> 3) & 1) * 16);

#define RESOLVE(IT, AH, BH, KK, KC)                             \
    { int kt = (IT) * 32;                                       \
      if (kt < K0) { AH = A0; BH = B0; KK = K0; KC = kt; }      \
      else         { AH = A1; BH = B1; KK = K1; KC = kt - K0; } }

#pragma unroll
    for (int p = 0; p < NSTAGE - 1; ++p) {
        if (p < S) {
            const __half *Ah, *Bh; int KK, KC;
            RESOLVE(p, Ah, Bh, KK, KC);
            load_stage(sb0 + p * STAGE_BYTES, tid, row0, col0, Ah, Bh, KK, KC, M);
        }
        CP_COMMIT();
    }

    int stage = 0;
    for (int it = 0; it < S; ++it) {
        CP_WAIT2();
        __syncthreads();
        if (it + NSTAGE - 1 < S) {
            int s2 = stage + NSTAGE - 1; if (s2 >= NSTAGE) s2 -= NSTAGE;
            const __half *Ah, *Bh; int KK, KC;
            RESOLVE(it + NSTAGE - 1, Ah, Bh, KK, KC);
            load_stage(sb0 + s2 * STAGE_BYTES, tid, row0, col0, Ah, Bh, KK, KC, M);
        }
        CP_COMMIT();

        const uint32_t sa = sb0 + stage * STAGE_BYTES;
        const uint32_t sbB = sa + 5120;
#pragma unroll
        for (int ks = 0; ks < 2; ++ks) {
            uint32_t ah[2][4];
#pragma unroll
            for (int tm = 0; tm < 2; ++tm)
                ldsm_x4(ah[tm], sa + aoff + tm * 1280 + ks * 32);
#pragma unroll
            for (int tnp = 0; tnp < 4; ++tnp) {
                uint32_t bh[4];
                ldsm_x4(bh, sbB + boff4 + tnp * 1280 + ks * 32);
#pragma unroll
                for (int tm = 0; tm < 2; ++tm) {
                    mma_f16(acc[tm][2 * tnp + 0], ah[tm], bh);
                    mma_f16(acc[tm][2 * tnp + 1], ah[tm], bh + 2);
                }
            }
        }
        ++stage; if (stage == NSTAGE) stage = 0;
    }

    // prefetch epilogue params into registers BEFORE the drain barrier
    float rbias = bias[col0 + tid];
    float rgam = 0.f, rbet = 0.f;
    if (MODE == 0) { rgam = gamma[tid]; rbet = beta[tid]; }

    CP_WAIT0();
    __syncthreads();

    // ---------------------------- epilogue ---------------------------------
    float* rsum  = (float*)smem;
    float* rsq   = rsum + 64;
    float* sbias = rsq + 64;
    float* sgam  = sbias + 256;
    float* sbet  = sgam + 256;
    if (MODE == 0 && tid < 64) { rsum[tid] = 0.f; rsq[tid] = 0.f; }
    sbias[tid] = rbias;
    if (MODE == 0) { sgam[tid] = rgam; sbet[tid] = rbet; }
    __syncthreads();

    const int qrow = lane >> 2;
    const int qc = (lane & 3) * 2;

    float vsum[4], vsq[4];
#pragma unroll
    for (int k = 0; k < 4; ++k) { vsum[k] = 0.f; vsq[k] = 0.f; }

#pragma unroll
    for (int tm = 0; tm < 2; ++tm) {
#pragma unroll
        for (int rh = 0; rh < 2; ++rh) {
            int rloc = warpM * 32 + tm * 16 + rh * 8 + qrow;
            int rg = row0 + rloc;
            bool v = rg < M;
#pragma unroll
            for (int tn = 0; tn < 8; ++tn) {
                int c = warpN * 64 + tn * 8 + qc;
                float a0 = acc[tm][tn][rh * 2 + 0] + sbias[c];
                float a1 = acc[tm][tn][rh * 2 + 1] + sbias[c + 1];
                if (MODE == 0) {
                    if (v) {
                        uint32_t rp = ((const uint32_t*)resid)[((size_t)rg * 256 + c) >> 1];
                        float2 q = __half22float2(*(const __half2*)&rp);
                        a0 += q.x; a1 += q.y;
                    }
                    vsum[tm * 2 + rh] += a0 + a1;
                    vsq[tm * 2 + rh] += a0 * a0 + a1 * a1;
                } else {
                    a0 = fmaxf(a0, 0.f); a1 = fmaxf(a1, 0.f);
                }
                acc[tm][tn][rh * 2 + 0] = a0;
                acc[tm][tn][rh * 2 + 1] = a1;
            }
        }
    }

    if (MODE == 0) {
#pragma unroll
        for (int k = 0; k < 4; ++k) {
            vsum[k] += __shfl_xor_sync(0xFFFFFFFFu, vsum[k], 1);
            vsum[k] += __shfl_xor_sync(0xFFFFFFFFu, vsum[k], 2);
            vsq[k]  += __shfl_xor_sync(0xFFFFFFFFu, vsq[k], 1);
            vsq[k]  += __shfl_xor_sync(0xFFFFFFFFu, vsq[k], 2);
        }
        if ((lane & 3) == 0) {
#pragma unroll
            for (int tm = 0; tm < 2; ++tm)
#pragma unroll
                for (int rh = 0; rh < 2; ++rh) {
                    int rloc = warpM * 32 + tm * 16 + rh * 8 + qrow;
                    atomicAdd(&rsum[rloc], vsum[tm * 2 + rh]);
                    atomicAdd(&rsq[rloc], vsq[tm * 2 + rh]);
                }
        }
        __syncthreads();
    }

#pragma unroll
    for (int tm = 0; tm < 2; ++tm) {
#pragma unroll
        for (int rh = 0; rh < 2; ++rh) {
            int rloc = warpM * 32 + tm * 16 + rh * 8 + qrow;
            int rg = row0 + rloc;
            if (rg >= M) continue;
            float mean = 0.f, inv = 1.f;
            if (MODE == 0) {
                mean = rsum[rloc] * (1.f / 256.f);
                inv = rsqrtf(rsq[rloc] * (1.f / 256.f) - mean * mean + 1e-5f);
            }
#pragma unroll
            for (int tn = 0; tn < 8; ++tn) {
                int c = warpN * 64 + tn * 8 + qc;
                float a0 = acc[tm][tn][rh * 2 + 0];
                float a1 = acc[tm][tn][rh * 2 + 1];
                if (MODE == 0) {
                    a0 = (a0 - mean) * inv * sgam[c] + sbet[c];
                    a1 = (a1 - mean) * inv * sgam[c + 1] + sbet[c + 1];
                    if (outf != nullptr)
                        *(float2*)(outf + (size_t)rg * 256 + c) = make_float2(a0, a1);
                    if (outh != nullptr)
                        ((uint32_t*)outh)[((size_t)rg * 256 + c) >> 1] = packh2(a0, a1);
                } else {
                    ((uint32_t*)outh)[((size_t)rg * HF + col0 + c) >> 1] = packh2(a0, a1);
                }
            }
        }
    }
}

// ------------------------------ launch --------------------------------------
extern "C" void kernel_launch(void* const* d_in, const int* in_sizes, int n_in,
                              void* d_out, int out_size) {
    const float* x      = (const float*)d_in[0];
    const int*   ei     = (const int*)d_in[1];
    const float* W_nbr  = (const float*)d_in[2];
    const float* W_root = (const float*)d_in[3];
    const float* b_gnn  = (const float*)d_in[4];
    const float* W1     = (const float*)d_in[5];
    const float* b1     = (const float*)d_in[6];
    const float* W2     = (const float*)d_in[7];
    const float* b2     = (const float*)d_in[8];
    const float* g1     = (const float*)d_in[9];
    const float* be1    = (const float*)d_in[10];
    const float* g2     = (const float*)d_in[11];
    const float* be2    = (const float*)d_in[12];
    float* out = (float*)d_out;

    const int M = in_sizes[0] / HD;
    const int E = in_sizes[1] / 2;

    __half *xh, *agh, *hh, *th, *wnh, *wrh, *w1h, *w2h;
    int *deg, *off, *cur, *srcl, *bsum;
    cudaGetSymbolAddress((void**)&xh, g_x_h);
    cudaGetSymbolAddress((void**)&agh, g_ag_h);
    cudaGetSymbolAddress((void**)&hh, g_h_h);
    cudaGetSymbolAddress((void**)&th, g_t_h);
    cudaGetSymbolAddress((void**)&wnh, g_wn_h);
    cudaGetSymbolAddress((void**)&wrh, g_wr_h);
    cudaGetSymbolAddress((void**)&w1h, g_w1_h);
    cudaGetSymbolAddress((void**)&w2h, g_w2_h);
    cudaGetSymbolAddress((void**)&deg, g_deg);
    cudaGetSymbolAddress((void**)&off, g_off);
    cudaGetSymbolAddress((void**)&cur, g_cur);
    cudaGetSymbolAddress((void**)&srcl, g_srcl);
    cudaGetSymbolAddress((void**)&bsum, g_bsum);

    cudaFuncSetAttribute(gemm_mma<0>, cudaFuncAttributeMaxDynamicSharedMemorySize, SMEM_TOTAL);
    cudaFuncSetAttribute(gemm_mma<1>, cudaFuncAttributeMaxDynamicSharedMemorySize, SMEM_TOTAL);

    int n4 = M * HD / 4;
    conv_kernel<<<(n4 + 255) / 256, 256>>>(x, xh, n4);
    detect_kernel<<<1, 128>>>(ei, 2 * E);

    cudaMemsetAsync(deg, 0, M * sizeof(int));
    hist_kernel<<<(E / 2 + 255) / 256, 256>>>(ei, E, deg);

    int nB = (M + SCAN_BLK - 1) / SCAN_BLK;
    block_scan_kernel<<<nB, SCAN_BLK>>>(deg, off, bsum, M);
    bscan_kernel<<<1, 128>>>(bsum, off + M, nB);
    add_off_kernel<<<nB, SCAN_BLK>>>(off, cur, bsum, M);

    fill_kernel<<<(E / 2 + 255) / 256, 256>>>(ei, E, cur, srcl);
    gather_kernel<<<(M + 7) / 8, 256>>>(off, srcl, xh, agh, M);

    ttrans_kernel<<<dim3(HD / 32, HD / 32), dim3(32, 8)>>>(W_nbr, wnh, HD, HD);
    ttrans_kernel<<<dim3(HD / 32, HD / 32), dim3(32, 8)>>>(W_root, wrh, HD, HD);
    ttrans_kernel<<<dim3(HD / 32, HF / 32), dim3(32, 8)>>>(W1, w1h, HD, HF);
    ttrans_kernel<<<dim3(HF / 32, HD / 32), dim3(32, 8)>>>(W2, w2h, HF, HD);

    int gx = (M + 63) / 64;

    // hh = fp16 LN1(x + agg@Wnbr + x@Wroot + b_gnn)   (resid = xh fp16)
    gemm_mma<0><<<dim3(gx, 1), 256, SMEM_TOTAL>>>(
        agh, wnh, HD, xh, wrh, HD, b_gnn, xh, g1, be1, nullptr, hh, M);

    // th = relu(hh@W1 + b1)
    gemm_mma<1><<<dim3(gx, 2), 256, SMEM_TOTAL>>>(
        hh, w1h, HD, nullptr, nullptr, 0,
        b1, nullptr, nullptr, nullptr, nullptr, th, M);

    // out = LN2(hh + th@W2 + b2)  fp32 to d_out  (resid = hh fp16)
    gemm_mma<0><<<dim3(gx, 1), 256, SMEM_TOTAL>>>(
        th, w2h, HF, nullptr, nullptr, 0,
        b2, hh, g2, be2, out, nullptr, M);
}

// round 11
// speedup vs baseline: 1.0529x; 1.0413x over previous
#include <cuda_runtime.h>
#include <cuda_fp16.h>
#include <cstdint>

#define HD 256
#define HF 512
#define NMAX 50000
#define EMAX 800000
#define SCAN_BLK 512

// ------------------------- scratch (device globals) ------------------------
__device__ __half g_x_h[(size_t)NMAX * HD];
__device__ __half g_ag_h[(size_t)NMAX * HD];
__device__ __half g_h_h[(size_t)NMAX * HD];
__device__ __half g_t_h[(size_t)NMAX * HF];
__device__ __half g_wn_h[HD * HD];
__device__ __half g_wr_h[HD * HD];
__device__ __half g_w1_h[HD * HF];
__device__ __half g_w2_h[HD * HF];
__device__ int g_deg[NMAX];
__device__ int g_off[NMAX + 1];
__device__ int g_cur[NMAX];
__device__ int g_srcl[EMAX];
__device__ int g_bsum[(NMAX + SCAN_BLK - 1) / SCAN_BLK];
__device__ int g_is64;

// ----------------------------- helpers -------------------------------------
__device__ __forceinline__ uint32_t smem_u32(const void* p) {
    uint32_t a;
    asm("{ .reg .u64 t; cvta.to.shared.u64 t, %1; cvt.u32.u64 %0, t; }" : "=r"(a) : "l"(p));
    return a;
}
__device__ __forceinline__ void ldsm_x4(uint32_t* r, uint32_t addr) {
    asm volatile("ldmatrix.sync.aligned.m8n8.x4.shared.b16 {%0,%1,%2,%3}, [%4];"
                 : "=r"(r[0]), "=r"(r[1]), "=r"(r[2]), "=r"(r[3]) : "r"(addr));
}
__device__ __forceinline__ void mma_f16(float* d, const uint32_t* a, const uint32_t* b) {
    asm volatile(
        "mma.sync.aligned.m16n8k16.row.col.f32.f16.f16.f32 "
        "{%0,%1,%2,%3}, {%4,%5,%6,%7}, {%8,%9}, {%0,%1,%2,%3};"
        : "+f"(d[0]), "+f"(d[1]), "+f"(d[2]), "+f"(d[3])
        : "r"(a[0]), "r"(a[1]), "r"(a[2]), "r"(a[3]), "r"(b[0]), "r"(b[1]));
}
__device__ __forceinline__ void cp_async16(uint32_t dst, const void* src, int szr) {
    asm volatile("cp.async.cg.shared.global [%0], [%1], 16, %2;"
                 :: "r"(dst), "l"(src), "r"(szr) : "memory");
}
#define CP_COMMIT() asm volatile("cp.async.commit_group;" ::: "memory")
#define CP_WAIT0()  asm volatile("cp.async.wait_group 0;" ::: "memory")

__device__ __forceinline__ uint32_t packh2(float a, float b) {
    __half2 h = __float22half2_rn(make_float2(a, b));
    return *(uint32_t*)&h;
}

// --------------------------- small kernels ---------------------------------
__global__ void detect_kernel(const int* __restrict__ ei, int twoE) {
    int lim = twoE * 2;
    if (lim > 256) lim = 256;
    int idx = threadIdx.x * 2 + 1;          // odd words
    int nz = (idx < lim) ? ei[idx] : 0;
    int any = __syncthreads_or(nz != 0);
    if (threadIdx.x == 0) g_is64 = (any == 0) ? 1 : 0;
}

__global__ void hist_kernel(const int* __restrict__ ei, int E, int* __restrict__ deg) {
    int t = blockIdx.x * blockDim.x + threadIdx.x;
    if (g_is64) {
        int e0 = t * 2;
        if (e0 >= E) return;
        if (e0 + 2 <= E) {
            int4 d = *(const int4*)(ei + 2 * (E + e0));
            atomicAdd(&deg[d.x], 1);
            atomicAdd(&deg[d.z], 1);
        } else {
            atomicAdd(&deg[ei[2 * (E + e0)]], 1);
        }
    } else {
        int e0 = t * 4;
        if (e0 >= E) return;
        if (e0 + 4 <= E) {
            int4 d = *(const int4*)(ei + E + e0);
            atomicAdd(&deg[d.x], 1);
            atomicAdd(&deg[d.y], 1);
            atomicAdd(&deg[d.z], 1);
            atomicAdd(&deg[d.w], 1);
        } else {
            for (int e = e0; e < E; ++e) atomicAdd(&deg[ei[E + e]], 1);
        }
    }
}

// ---- parallel 3-phase scan ----
__global__ void block_scan_kernel(const int* __restrict__ deg, int* __restrict__ off,
                                  int* __restrict__ bsum, int M) {
    __shared__ int wsum[SCAN_BLK / 32];
    int t = threadIdx.x;
    int i = blockIdx.x * SCAN_BLK + t;
    int lane = t & 31, wid = t >> 5;
    int v = (i < M) ? deg[i] : 0;
    int s = v;
#pragma unroll
    for (int o = 1; o < 32; o <<= 1) {
        int u = __shfl_up_sync(0xFFFFFFFFu, s, o);
        if (lane >= o) s += u;
    }
    if (lane == 31) wsum[wid] = s;
    __syncthreads();
    if (wid == 0) {
        int w = (lane < SCAN_BLK / 32) ? wsum[lane] : 0;
#pragma unroll
        for (int o = 1; o < SCAN_BLK / 32; o <<= 1) {
            int u = __shfl_up_sync(0xFFFFFFFFu, w, o);
            if (lane >= o) w += u;
        }
        if (lane < SCAN_BLK / 32) wsum[lane] = w;
    }
    __syncthreads();
    int excl = s - v + (wid ? wsum[wid - 1] : 0);
    if (i < M) off[i] = excl;
    if (t == SCAN_BLK - 1) bsum[blockIdx.x] = excl + v;
}

__global__ void bscan_kernel(int* __restrict__ bsum, int* __restrict__ offM, int nB) {
    __shared__ int ws[4];
    int t = threadIdx.x;        // 128 threads
    int lane = t & 31, wid = t >> 5;
    int v = (t < nB) ? bsum[t] : 0;
    int s = v;
#pragma unroll
    for (int o = 1; o < 32; o <<= 1) {
        int u = __shfl_up_sync(0xFFFFFFFFu, s, o);
        if (lane >= o) s += u;
    }
    if (lane == 31) ws[wid] = s;
    __syncthreads();
    if (t == 0) {
        int r = 0;
#pragma unroll
        for (int i = 0; i < 4; ++i) { int x = ws[i]; ws[i] = r; r += x; }
        *offM = r;
    }
    __syncthreads();
    int excl = s - v + ws[wid];
    if (t < nB) bsum[t] = excl;
}

__global__ void add_off_kernel(int* __restrict__ off, int* __restrict__ cur,
                               const int* __restrict__ bsum, int M) {
    int i = blockIdx.x * SCAN_BLK + threadIdx.x;
    if (i < M) {
        int v = off[i] + bsum[blockIdx.x];
        off[i] = v;
        cur[i] = v;
    }
}

__global__ void fill_kernel(const int* __restrict__ ei, int E,
                            int* __restrict__ cur, int* __restrict__ srcl) {
    int t = blockIdx.x * blockDim.x + threadIdx.x;
    if (g_is64) {
        int e0 = t * 2;
        if (e0 >= E) return;
        if (e0 + 2 <= E) {
            int4 s = *(const int4*)(ei + 2 * e0);
            int4 d = *(const int4*)(ei + 2 * (E + e0));
            srcl[atomicAdd(&cur[d.x], 1)] = s.x;
            srcl[atomicAdd(&cur[d.z], 1)] = s.z;
        } else {
            srcl[atomicAdd(&cur[ei[2 * (E + e0)]], 1)] = ei[2 * e0];
        }
    } else {
        int e0 = t * 4;
        if (e0 >= E) return;
        if (e0 + 4 <= E) {
            int4 s = *(const int4*)(ei + e0);
            int4 d = *(const int4*)(ei + E + e0);
            srcl[atomicAdd(&cur[d.x], 1)] = s.x;
            srcl[atomicAdd(&cur[d.y], 1)] = s.y;
            srcl[atomicAdd(&cur[d.z], 1)] = s.z;
            srcl[atomicAdd(&cur[d.w], 1)] = s.w;
        } else {
            for (int e = e0; e < E; ++e)
                srcl[atomicAdd(&cur[ei[E + e]], 1)] = ei[e];
        }
    }
}

// gather: one warp per node; software-pipelined srcl prefetch; fp16 out
__global__ void __launch_bounds__(256)
gather_kernel(const int* __restrict__ off, const int* __restrict__ srcl,
              const __half* __restrict__ xh, __half* __restrict__ agh, int M) {
    int node = blockIdx.x * 8 + (threadIdx.x >> 5);
    int lane = threadIdx.x & 31;
    if (node >= M) return;
    int j0 = off[node], j1 = off[node + 1];

    float acc[8];
#pragma unroll
    for (int k = 0; k < 8; ++k) acc[k] = 0.f;

    const uint4* xb = (const uint4*)xh;
    int nfull = (j1 - j0) >> 3;
    int srcs[8];
    if (nfull > 0) {
#pragma unroll
        for (int u = 0; u < 8; ++u) srcs[u] = srcl[j0 + u];
    }
    for (int b = 0; b < nfull; ++b) {
        uint4 v[8];
#pragma unroll
        for (int u = 0; u < 8; ++u) v[u] = xb[(size_t)srcs[u] * 32 + lane];
        // prefetch next batch's indices while row loads are in flight
        int nsrcs[8];
        bool more = (b + 1 < nfull);
        if (more) {
            int jn = j0 + (b + 1) * 8;
#pragma unroll
            for (int u = 0; u < 8; ++u) nsrcs[u] = srcl[jn + u];
        }
#pragma unroll
        for (int u = 0; u < 8; ++u) {
            float2 f0 = __half22float2(*(const __half2*)&v[u].x);
            float2 f1 = __half22float2(*(const __half2*)&v[u].y);
            float2 f2 = __half22float2(*(const __half2*)&v[u].z);
            float2 f3 = __half22float2(*(const __half2*)&v[u].w);
            acc[0] += f0.x; acc[1] += f0.y; acc[2] += f1.x; acc[3] += f1.y;
            acc[4] += f2.x; acc[5] += f2.y; acc[6] += f3.x; acc[7] += f3.y;
        }
        if (more) {
#pragma unroll
            for (int u = 0; u < 8; ++u) srcs[u] = nsrcs[u];
        }
    }
    for (int j = j0 + nfull * 8; j < j1; ++j) {
        uint4 v = xb[(size_t)srcl[j] * 32 + lane];
        float2 f0 = __half22float2(*(const __half2*)&v.x);
        float2 f1 = __half22float2(*(const __half2*)&v.y);
        float2 f2 = __half22float2(*(const __half2*)&v.z);
        float2 f3 = __half22float2(*(const __half2*)&v.w);
        acc[0] += f0.x; acc[1] += f0.y; acc[2] += f1.x; acc[3] += f1.y;
        acc[4] += f2.x; acc[5] += f2.y; acc[6] += f3.x; acc[7] += f3.y;
    }

    uint32_t hi[4];
#pragma unroll
    for (int k = 0; k < 4; ++k) hi[k] = packh2(acc[2 * k], acc[2 * k + 1]);
    ((uint4*)agh)[(size_t)node * 32 + lane] = make_uint4(hi[0], hi[1], hi[2], hi[3]);
}

__global__ void conv_kernel(const float* __restrict__ in,
                            __half* __restrict__ oh, int n4) {
    int i = blockIdx.x * blockDim.x + threadIdx.x;
    if (i >= n4) return;
    float4 v = ((const float4*)in)[i];
    ((uint2*)oh)[i] = make_uint2(packh2(v.x, v.y), packh2(v.z, v.w));
}

// tiled transpose: W [K,N] fp32 -> out [N,K] fp16
__global__ void ttrans_kernel(const float* __restrict__ W,
                              __half* __restrict__ out, int K, int N) {
    __shared__ float tile[32][33];
    int k0 = blockIdx.x * 32;
    int n0 = blockIdx.y * 32;
    int tx = threadIdx.x, ty = threadIdx.y;   // 32 x 8
#pragma unroll
    for (int i = 0; i < 4; ++i)
        tile[ty + i * 8][tx] = W[(size_t)(k0 + ty + i * 8) * N + n0 + tx];
    __syncthreads();
#pragma unroll
    for (int i = 0; i < 4; ++i)
        out[(size_t)(n0 + ty + i * 8) * K + k0 + tx] =
            __float2half_rn(tile[tx][ty + i * 8]);
}

// ----------------------- fp16 mma.sync GEMM --------------------------------
// BM=128, BN=256, BK=64, 512 threads, 2-stage cp.async, 1 CTA/SM.
// Row = 128B data + 16B pad = 144B (9x16B; 9 = 1 mod 8 -> conflict-free).
#define RB 144
#define A_TILE (128 * RB)
#define B_TILE (256 * RB)
#define STAGE_BYTES (A_TILE + B_TILE)
#define SMEM_TOTAL (2 * STAGE_BYTES)

__device__ __forceinline__ void load_stage(
    uint32_t sa, int tid, int row0, int col0,
    const __half* A, const __half* B, int K, int kc, int M) {
#pragma unroll
    for (int j = 0; j < 2; ++j) {        // A: 1024 chunks of 16B
        int id = tid + j * 512;
        int r = id >> 3, c = id & 7;
        int row = row0 + r;
        int szr = (row < M) ? 16 : 0;
        size_t roff = (row < M) ? (size_t)row : 0;
        cp_async16(sa + r * RB + c * 16, A + roff * K + kc + c * 8, szr);
    }
    uint32_t sb = sa + A_TILE;
#pragma unroll
    for (int j = 0; j < 4; ++j) {        // B: 2048 chunks
        int id = tid + j * 512;
        int r = id >> 3, c = id & 7;
        cp_async16(sb + r * RB + c * 16, B + (size_t)(col0 + r) * K + kc + c * 8, 16);
    }
}

// MODE 0: C = A@B(+A1@B1) + bias + resid(fp16) -> LN -> outf(fp32)? / outh(fp16)?
// MODE 1: C = relu(A@B + bias) -> fp16 outh (stride HF)
template <int MODE>
__global__ void __launch_bounds__(512, 1)
gemm_mma(const __half* __restrict__ A0, const __half* __restrict__ B0, int K0,
         const __half* __restrict__ A1, const __half* __restrict__ B1, int K1,
         const float* __restrict__ bias, const __half* __restrict__ resid,
         const float* __restrict__ gamma, const float* __restrict__ beta,
         float* __restrict__ outf, __half* __restrict__ outh, int M) {
    extern __shared__ char smem[];
    const uint32_t sb0 = smem_u32(smem);
    const int tid = threadIdx.x;
    const int lane = tid & 31;
    const int warp = tid >> 5;           // 0..15
    const int warpM = warp >> 2;         // 0..3
    const int warpN = warp & 3;          // 0..3
    const int row0 = blockIdx.x * 128;
    const int col0 = blockIdx.y * 256;

    float acc[2][8][4];
#pragma unroll
    for (int i = 0; i < 2; ++i)
#pragma unroll
        for (int j = 0; j < 8; ++j)
#pragma unroll
            for (int k = 0; k < 4; ++k) acc[i][j][k] = 0.f;

    const int S = (K0 + K1) >> 6;

    const uint32_t aoff = (uint32_t)((warpM * 32 + (lane & 7) + ((lane >> 3) & 1) * 8) * RB
                                     + (lane >> 4) * 16);
    const uint32_t boff4 = (uint32_t)((warpN * 64 + (lane & 7) + (lane >> 4) * 8) * RB
                                      + ((lane >> 3) & 1) * 16);

#define RESOLVE(IT, AH, BH, KK, KC)                             \
    { int kt = (IT) * 64;                                       \
      if (kt < K0) { AH = A0; BH = B0; KK = K0; KC = kt; }      \
      else         { AH = A1; BH = B1; KK = K1; KC = kt - K0; } }

    // prologue: stage 0
    {
        const __half *Ah, *Bh; int KK, KC;
        RESOLVE(0, Ah, Bh, KK, KC);
        load_stage(sb0, tid, row0, col0, Ah, Bh, KK, KC, M);
        CP_COMMIT();
    }

    for (int it = 0; it < S; ++it) {
        CP_WAIT0();             // stage it arrived (only its group pending)
        __syncthreads();        // visibility + recycle guard
        if (it + 1 < S) {       // prefetch next into the other buffer
            const __half *Ah, *Bh; int KK, KC;
            RESOLVE(it + 1, Ah, Bh, KK, KC);
            load_stage(sb0 + ((it + 1) & 1) * STAGE_BYTES, tid, row0, col0, Ah, Bh, KK, KC, M);
            CP_COMMIT();
        }

        const uint32_t sa = sb0 + (it & 1) * STAGE_BYTES;
        const uint32_t sbB = sa + A_TILE;
#pragma unroll
        for (int ks = 0; ks < 4; ++ks) {
            uint32_t ah[2][4];
#pragma unroll
            for (int tm = 0; tm < 2; ++tm)
                ldsm_x4(ah[tm], sa + aoff + tm * (16 * RB) + ks * 32);
#pragma unroll
            for (int tnp = 0; tnp < 4; ++tnp) {
                uint32_t bh[4];
                ldsm_x4(bh, sbB + boff4 + tnp * (16 * RB) + ks * 32);
#pragma unroll
                for (int tm = 0; tm < 2; ++tm) {
                    mma_f16(acc[tm][2 * tnp + 0], ah[tm], bh);
                    mma_f16(acc[tm][2 * tnp + 1], ah[tm], bh + 2);
                }
            }
        }
    }

    // prefetch epilogue params before final drain
    float rbias = 0.f, rgam = 0.f, rbet = 0.f;
    if (tid < 256) {
        rbias = bias[col0 + tid];
        if (MODE == 0) { rgam = gamma[tid]; rbet = beta[tid]; }
    }

    __syncthreads();

    // ---------------------------- epilogue ---------------------------------
    float* rsum  = (float*)smem;          // 128
    float* rsq   = rsum + 128;            // 128
    float* sbias = rsq + 128;             // 256
    float* sgam  = sbias + 256;
    float* sbet  = sgam + 256;
    if (MODE == 0 && tid < 128) { rsum[tid] = 0.f; rsq[tid] = 0.f; }
    if (tid < 256) {
        sbias[tid] = rbias;
        if (MODE == 0) { sgam[tid] = rgam; sbet[tid] = rbet; }
    }
    __syncthreads();

    const int qrow = lane >> 2;
    const int qc = (lane & 3) * 2;

    float vsum[4], vsq[4];
#pragma unroll
    for (int k = 0; k < 4; ++k) { vsum[k] = 0.f; vsq[k] = 0.f; }

#pragma unroll
    for (int tm = 0; tm < 2; ++tm) {
#pragma unroll
        for (int rh = 0; rh < 2; ++rh) {
            int rloc = warpM * 32 + tm * 16 + rh * 8 + qrow;
            int rg = row0 + rloc;
            bool v = rg < M;
#pragma unroll
            for (int tn = 0; tn < 8; ++tn) {
                int c = warpN * 64 + tn * 8 + qc;
                float a0 = acc[tm][tn][rh * 2 + 0] + sbias[c];
                float a1 = acc[tm][tn][rh * 2 + 1] + sbias[c + 1];
                if (MODE == 0) {
                    if (v) {
                        uint32_t rp = ((const uint32_t*)resid)[((size_t)rg * 256 + c) >> 1];
                        float2 q = __half22float2(*(const __half2*)&rp);
                        a0 += q.x; a1 += q.y;
                    }
                    vsum[tm * 2 + rh] += a0 + a1;
                    vsq[tm * 2 + rh] += a0 * a0 + a1 * a1;
                } else {
                    a0 = fmaxf(a0, 0.f); a1 = fmaxf(a1, 0.f);
                }
                acc[tm][tn][rh * 2 + 0] = a0;
                acc[tm][tn][rh * 2 + 1] = a1;
            }
        }
    }

    if (MODE == 0) {
#pragma unroll
        for (int k = 0; k < 4; ++k) {
            vsum[k] += __shfl_xor_sync(0xFFFFFFFFu, vsum[k], 1);
            vsum[k] += __shfl_xor_sync(0xFFFFFFFFu, vsum[k], 2);
            vsq[k]  += __shfl_xor_sync(0xFFFFFFFFu, vsq[k], 1);
            vsq[k]  += __shfl_xor_sync(0xFFFFFFFFu, vsq[k], 2);
        }
        if ((lane & 3) == 0) {
#pragma unroll
            for (int tm = 0; tm < 2; ++tm)
#pragma unroll
                for (int rh = 0; rh < 2; ++rh) {
                    int rloc = warpM * 32 + tm * 16 + rh * 8 + qrow;
                    atomicAdd(&rsum[rloc], vsum[tm * 2 + rh]);
                    atomicAdd(&rsq[rloc], vsq[tm * 2 + rh]);
                }
        }
        __syncthreads();
    }

#pragma unroll
    for (int tm = 0; tm < 2; ++tm) {
#pragma unroll
        for (int rh = 0; rh < 2; ++rh) {
            int rloc = warpM * 32 + tm * 16 + rh * 8 + qrow;
            int rg = row0 + rloc;
            if (rg >= M) continue;
            float mean = 0.f, inv = 1.f;
            if (MODE == 0) {
                mean = rsum[rloc] * (1.f / 256.f);
                inv = rsqrtf(rsq[rloc] * (1.f / 256.f) - mean * mean + 1e-5f);
            }
#pragma unroll
            for (int tn = 0; tn < 8; ++tn) {
                int c = warpN * 64 + tn * 8 + qc;
                float a0 = acc[tm][tn][rh * 2 + 0];
                float a1 = acc[tm][tn][rh * 2 + 1];
                if (MODE == 0) {
                    a0 = (a0 - mean) * inv * sgam[c] + sbet[c];
                    a1 = (a1 - mean) * inv * sgam[c + 1] + sbet[c + 1];
                    if (outf != nullptr)
                        *(float2*)(outf + (size_t)rg * 256 + c) = make_float2(a0, a1);
                    if (outh != nullptr)
                        ((uint32_t*)outh)[((size_t)rg * 256 + c) >> 1] = packh2(a0, a1);
                } else {
                    ((uint32_t*)outh)[((size_t)rg * HF + col0 + c) >> 1] = packh2(a0, a1);
                }
            }
        }
    }
}

// ------------------------------ launch --------------------------------------
extern "C" void kernel_launch(void* const* d_in, const int* in_sizes, int n_in,
                              void* d_out, int out_size) {
    const float* x      = (const float*)d_in[0];
    const int*   ei     = (const int*)d_in[1];
    const float* W_nbr  = (const float*)d_in[2];
    const float* W_root = (const float*)d_in[3];
    const float* b_gnn  = (const float*)d_in[4];
    const float* W1     = (const float*)d_in[5];
    const float* b1     = (const float*)d_in[6];
    const float* W2     = (const float*)d_in[7];
    const float* b2     = (const float*)d_in[8];
    const float* g1     = (const float*)d_in[9];
    const float* be1    = (const float*)d_in[10];
    const float* g2     = (const float*)d_in[11];
    const float* be2    = (const float*)d_in[12];
    float* out = (float*)d_out;

    const int M = in_sizes[0] / HD;
    const int E = in_sizes[1] / 2;

    __half *xh, *agh, *hh, *th, *wnh, *wrh, *w1h, *w2h;
    int *deg, *off, *cur, *srcl, *bsum;
    cudaGetSymbolAddress((void**)&xh, g_x_h);
    cudaGetSymbolAddress((void**)&agh, g_ag_h);
    cudaGetSymbolAddress((void**)&hh, g_h_h);
    cudaGetSymbolAddress((void**)&th, g_t_h);
    cudaGetSymbolAddress((void**)&wnh, g_wn_h);
    cudaGetSymbolAddress((void**)&wrh, g_wr_h);
    cudaGetSymbolAddress((void**)&w1h, g_w1_h);
    cudaGetSymbolAddress((void**)&w2h, g_w2_h);
    cudaGetSymbolAddress((void**)&deg, g_deg);
    cudaGetSymbolAddress((void**)&off, g_off);
    cudaGetSymbolAddress((void**)&cur, g_cur);
    cudaGetSymbolAddress((void**)&srcl, g_srcl);
    cudaGetSymbolAddress((void**)&bsum, g_bsum);

    cudaFuncSetAttribute(gemm_mma<0>, cudaFuncAttributeMaxDynamicSharedMemorySize, SMEM_TOTAL);
    cudaFuncSetAttribute(gemm_mma<1>, cudaFuncAttributeMaxDynamicSharedMemorySize, SMEM_TOTAL);

    int n4 = M * HD / 4;
    conv_kernel<<<(n4 + 255) / 256, 256>>>(x, xh, n4);
    detect_kernel<<<1, 128>>>(ei, 2 * E);

    cudaMemsetAsync(deg, 0, M * sizeof(int));
    hist_kernel<<<(E / 2 + 255) / 256, 256>>>(ei, E, deg);

    int nB = (M + SCAN_BLK - 1) / SCAN_BLK;
    block_scan_kernel<<<nB, SCAN_BLK>>>(deg, off, bsum, M);
    bscan_kernel<<<1, 128>>>(bsum, off + M, nB);
    add_off_kernel<<<nB, SCAN_BLK>>>(off, cur, bsum, M);

    fill_kernel<<<(E / 2 + 255) / 256, 256>>>(ei, E, cur, srcl);
    gather_kernel<<<(M + 7) / 8, 256>>>(off, srcl, xh, agh, M);

    ttrans_kernel<<<dim3(HD / 32, HD / 32), dim3(32, 8)>>>(W_nbr, wnh, HD, HD);
    ttrans_kernel<<<dim3(HD / 32, HD / 32), dim3(32, 8)>>>(W_root, wrh, HD, HD);
    ttrans_kernel<<<dim3(HD / 32, HF / 32), dim3(32, 8)>>>(W1, w1h, HD, HF);
    ttrans_kernel<<<dim3(HF / 32, HD / 32), dim3(32, 8)>>>(W2, w2h, HF, HD);

    int gx = (M + 127) / 128;

    // hh = fp16 LN1(x + agg@Wnbr + x@Wroot + b_gnn)   (resid = xh fp16)
    gemm_mma<0><<<dim3(gx, 1), 512, SMEM_TOTAL>>>(
        agh, wnh, HD, xh, wrh, HD, b_gnn, xh, g1, be1, nullptr, hh, M);

    // th = relu(hh@W1 + b1)
    gemm_mma<1><<<dim3(gx, 2), 512, SMEM_TOTAL>>>(
        hh, w1h, HD, nullptr, nullptr, 0,
        b1, nullptr, nullptr, nullptr, nullptr, th, M);

    // out = LN2(hh + th@W2 + b2)  fp32 to d_out  (resid = hh fp16)
    gemm_mma<0><<<dim3(gx, 1), 512, SMEM_TOTAL>>>(
        th, w2h, HF, nullptr, nullptr, 0,
        b2, hh, g2, be2, out, nullptr, M);
}

// round 12
// speedup vs baseline: 1.0612x; 1.0079x over previous
#include <cuda_runtime.h>
#include <cuda_fp16.h>
#include <cstdint>

#define HD 256
#define HF 512
#define NMAX 50000
#define EMAX 800000
#define SCAN_BLK 512

// ------------------------- scratch (device globals) ------------------------
__device__ __half g_x_h[(size_t)NMAX * HD];
__device__ __half g_ag_h[(size_t)NMAX * HD];
__device__ __half g_h_h[(size_t)NMAX * HD];
__device__ __half g_t_h[(size_t)NMAX * HF];
__device__ __half g_wn_h[HD * HD];
__device__ __half g_wr_h[HD * HD];
__device__ __half g_w1_h[HD * HF];
__device__ __half g_w2_h[HD * HF];
__device__ int g_deg[NMAX];
__device__ int g_off[NMAX + 1];
__device__ int g_cur[NMAX];
__device__ int g_srcl[EMAX];
__device__ int g_bsum[(NMAX + SCAN_BLK - 1) / SCAN_BLK];
__device__ int g_is64;

// ----------------------------- helpers -------------------------------------
__device__ __forceinline__ uint32_t smem_u32(const void* p) {
    uint32_t a;
    asm("{ .reg .u64 t; cvta.to.shared.u64 t, %1; cvt.u32.u64 %0, t; }" : "=r"(a) : "l"(p));
    return a;
}
__device__ __forceinline__ void ldsm_x4(uint32_t* r, uint32_t addr) {
    asm volatile("ldmatrix.sync.aligned.m8n8.x4.shared.b16 {%0,%1,%2,%3}, [%4];"
                 : "=r"(r[0]), "=r"(r[1]), "=r"(r[2]), "=r"(r[3]) : "r"(addr));
}
__device__ __forceinline__ void mma_f16(float* d, const uint32_t* a, const uint32_t* b) {
    asm volatile(
        "mma.sync.aligned.m16n8k16.row.col.f32.f16.f16.f32 "
        "{%0,%1,%2,%3}, {%4,%5,%6,%7}, {%8,%9}, {%0,%1,%2,%3};"
        : "+f"(d[0]), "+f"(d[1]), "+f"(d[2]), "+f"(d[3])
        : "r"(a[0]), "r"(a[1]), "r"(a[2]), "r"(a[3]), "r"(b[0]), "r"(b[1]));
}
__device__ __forceinline__ void cp_async16(uint32_t dst, const void* src, int szr) {
    asm volatile("cp.async.cg.shared.global [%0], [%1], 16, %2;"
                 :: "r"(dst), "l"(src), "r"(szr) : "memory");
}
#define CP_COMMIT() asm volatile("cp.async.commit_group;" ::: "memory")
#define CP_WAIT1()  asm volatile("cp.async.wait_group 1;" ::: "memory")

__device__ __forceinline__ uint32_t packh2(float a, float b) {
    __half2 h = __float22half2_rn(make_float2(a, b));
    return *(uint32_t*)&h;
}

// --------------------------- small kernels ---------------------------------
__global__ void detect_kernel(const int* __restrict__ ei, int twoE) {
    int lim = twoE * 2;
    if (lim > 256) lim = 256;
    int idx = threadIdx.x * 2 + 1;          // odd words
    int nz = (idx < lim) ? ei[idx] : 0;
    int any = __syncthreads_or(nz != 0);
    if (threadIdx.x == 0) g_is64 = (any == 0) ? 1 : 0;
}

__global__ void hist_kernel(const int* __restrict__ ei, int E, int* __restrict__ deg) {
    int t = blockIdx.x * blockDim.x + threadIdx.x;
    if (g_is64) {
        int e0 = t * 2;
        if (e0 >= E) return;
        if (e0 + 2 <= E) {
            int4 d = *(const int4*)(ei + 2 * (E + e0));
            atomicAdd(&deg[d.x], 1);
            atomicAdd(&deg[d.z], 1);
        } else {
            atomicAdd(&deg[ei[2 * (E + e0)]], 1);
        }
    } else {
        int e0 = t * 4;
        if (e0 >= E) return;
        if (e0 + 4 <= E) {
            int4 d = *(const int4*)(ei + E + e0);
            atomicAdd(&deg[d.x], 1);
            atomicAdd(&deg[d.y], 1);
            atomicAdd(&deg[d.z], 1);
            atomicAdd(&deg[d.w], 1);
        } else {
            for (int e = e0; e < E; ++e) atomicAdd(&deg[ei[E + e]], 1);
        }
    }
}

// ---- parallel 3-phase scan ----
__global__ void block_scan_kernel(const int* __restrict__ deg, int* __restrict__ off,
                                  int* __restrict__ bsum, int M) {
    __shared__ int wsum[SCAN_BLK / 32];
    int t = threadIdx.x;
    int i = blockIdx.x * SCAN_BLK + t;
    int lane = t & 31, wid = t >> 5;
    int v = (i < M) ? deg[i] : 0;
    int s = v;
#pragma unroll
    for (int o = 1; o < 32; o <<= 1) {
        int u = __shfl_up_sync(0xFFFFFFFFu, s, o);
        if (lane >= o) s += u;
    }
    if (lane == 31) wsum[wid] = s;
    __syncthreads();
    if (wid == 0) {
        int w = (lane < SCAN_BLK / 32) ? wsum[lane] : 0;
#pragma unroll
        for (int o = 1; o < SCAN_BLK / 32; o <<= 1) {
            int u = __shfl_up_sync(0xFFFFFFFFu, w, o);
            if (lane >= o) w += u;
        }
        if (lane < SCAN_BLK / 32) wsum[lane] = w;
    }
    __syncthreads();
    int excl = s - v + (wid ? wsum[wid - 1] : 0);
    if (i < M) off[i] = excl;
    if (t == SCAN_BLK - 1) bsum[blockIdx.x] = excl + v;
}

__global__ void bscan_kernel(int* __restrict__ bsum, int* __restrict__ offM, int nB) {
    __shared__ int ws[4];
    int t = threadIdx.x;        // 128 threads
    int lane = t & 31, wid = t >> 5;
    int v = (t < nB) ? bsum[t] : 0;
    int s = v;
#pragma unroll
    for (int o = 1; o < 32; o <<= 1) {
        int u = __shfl_up_sync(0xFFFFFFFFu, s, o);
        if (lane >= o) s += u;
    }
    if (lane == 31) ws[wid] = s;
    __syncthreads();
    if (t == 0) {
        int r = 0;
#pragma unroll
        for (int i = 0; i < 4; ++i) { int x = ws[i]; ws[i] = r; r += x; }
        *offM = r;
    }
    __syncthreads();
    int excl = s - v + ws[wid];
    if (t < nB) bsum[t] = excl;
}

__global__ void add_off_kernel(int* __restrict__ off, int* __restrict__ cur,
                               const int* __restrict__ bsum, int M) {
    int i = blockIdx.x * SCAN_BLK + threadIdx.x;
    if (i < M) {
        int v = off[i] + bsum[blockIdx.x];
        off[i] = v;
        cur[i] = v;
    }
}

__global__ void fill_kernel(const int* __restrict__ ei, int E,
                            int* __restrict__ cur, int* __restrict__ srcl) {
    int t = blockIdx.x * blockDim.x + threadIdx.x;
    if (g_is64) {
        int e0 = t * 2;
        if (e0 >= E) return;
        if (e0 + 2 <= E) {
            int4 s = *(const int4*)(ei + 2 * e0);
            int4 d = *(const int4*)(ei + 2 * (E + e0));
            srcl[atomicAdd(&cur[d.x], 1)] = s.x;
            srcl[atomicAdd(&cur[d.z], 1)] = s.z;
        } else {
            srcl[atomicAdd(&cur[ei[2 * (E + e0)]], 1)] = ei[2 * e0];
        }
    } else {
        int e0 = t * 4;
        if (e0 >= E) return;
        if (e0 + 4 <= E) {
            int4 s = *(const int4*)(ei + e0);
            int4 d = *(const int4*)(ei + E + e0);
            srcl[atomicAdd(&cur[d.x], 1)] = s.x;
            srcl[atomicAdd(&cur[d.y], 1)] = s.y;
            srcl[atomicAdd(&cur[d.z], 1)] = s.z;
            srcl[atomicAdd(&cur[d.w], 1)] = s.w;
        } else {
            for (int e = e0; e < E; ++e)
                srcl[atomicAdd(&cur[ei[E + e]], 1)] = ei[e];
        }
    }
}

// gather: one warp per node; software-pipelined srcl prefetch; fp16 out
__global__ void __launch_bounds__(256)
gather_kernel(const int* __restrict__ off, const int* __restrict__ srcl,
              const __half* __restrict__ xh, __half* __restrict__ agh, int M) {
    int node = blockIdx.x * 8 + (threadIdx.x >> 5);
    int lane = threadIdx.x & 31;
    if (node >= M) return;
    int j0 = off[node], j1 = off[node + 1];

    float acc[8];
#pragma unroll
    for (int k = 0; k < 8; ++k) acc[k] = 0.f;

    const uint4* xb = (const uint4*)xh;
    int nfull = (j1 - j0) >> 3;
    int srcs[8];
    if (nfull > 0) {
#pragma unroll
        for (int u = 0; u < 8; ++u) srcs[u] = srcl[j0 + u];
    }
    for (int b = 0; b < nfull; ++b) {
        uint4 v[8];
#pragma unroll
        for (int u = 0; u < 8; ++u) v[u] = xb[(size_t)srcs[u] * 32 + lane];
        int nsrcs[8];
        bool more = (b + 1 < nfull);
        if (more) {
            int jn = j0 + (b + 1) * 8;
#pragma unroll
            for (int u = 0; u < 8; ++u) nsrcs[u] = srcl[jn + u];
        }
#pragma unroll
        for (int u = 0; u < 8; ++u) {
            float2 f0 = __half22float2(*(const __half2*)&v[u].x);
            float2 f1 = __half22float2(*(const __half2*)&v[u].y);
            float2 f2 = __half22float2(*(const __half2*)&v[u].z);
            float2 f3 = __half22float2(*(const __half2*)&v[u].w);
            acc[0] += f0.x; acc[1] += f0.y; acc[2] += f1.x; acc[3] += f1.y;
            acc[4] += f2.x; acc[5] += f2.y; acc[6] += f3.x; acc[7] += f3.y;
        }
        if (more) {
#pragma unroll
            for (int u = 0; u < 8; ++u) srcs[u] = nsrcs[u];
        }
    }
    for (int j = j0 + nfull * 8; j < j1; ++j) {
        uint4 v = xb[(size_t)srcl[j] * 32 + lane];
        float2 f0 = __half22float2(*(const __half2*)&v.x);
        float2 f1 = __half22float2(*(const __half2*)&v.y);
        float2 f2 = __half22float2(*(const __half2*)&v.z);
        float2 f3 = __half22float2(*(const __half2*)&v.w);
        acc[0] += f0.x; acc[1] += f0.y; acc[2] += f1.x; acc[3] += f1.y;
        acc[4] += f2.x; acc[5] += f2.y; acc[6] += f3.x; acc[7] += f3.y;
    }

    uint32_t hi[4];
#pragma unroll
    for (int k = 0; k < 4; ++k) hi[k] = packh2(acc[2 * k], acc[2 * k + 1]);
    ((uint4*)agh)[(size_t)node * 32 + lane] = make_uint4(hi[0], hi[1], hi[2], hi[3]);
}

// fused prep: conv (x -> xh) + 4 weight transposes, block-index segmented.
// ttrans segment: W [K,N] fp32 -> out [N,K] fp16, 32x32 smem tile.
__device__ __forceinline__ void ttrans_tile(const float* W, __half* out,
                                            int K, int N, int kb, int nb,
                                            float (*tile)[33], int tid) {
    int tx = tid & 31, ty = tid >> 5;   // 32 x 8
    int k0 = kb * 32, n0 = nb * 32;
#pragma unroll
    for (int i = 0; i < 4; ++i)
        tile[ty + i * 8][tx] = W[(size_t)(k0 + ty + i * 8) * N + n0 + tx];
    __syncthreads();
#pragma unroll
    for (int i = 0; i < 4; ++i)
        out[(size_t)(n0 + ty + i * 8) * K + k0 + tx] =
            __float2half_rn(tile[tx][ty + i * 8]);
}

__global__ void prep_kernel(const float* __restrict__ x, __half* __restrict__ xh,
                            const float* __restrict__ Wn, __half* __restrict__ wnh,
                            const float* __restrict__ Wr, __half* __restrict__ wrh,
                            const float* __restrict__ W1, __half* __restrict__ w1h,
                            const float* __restrict__ W2, __half* __restrict__ w2h,
                            int n4, int nbConv) {
    __shared__ float tile[32][33];
    int b = blockIdx.x;
    int tid = threadIdx.x;
    if (b < nbConv) {
        int i = b * 256 + tid;
        if (i < n4) {
            float4 v = ((const float4*)x)[i];
            ((uint2*)xh)[i] = make_uint2(packh2(v.x, v.y), packh2(v.z, v.w));
        }
        return;
    }
    int t = b - nbConv;
    if (t < 64)        ttrans_tile(Wn, wnh, HD, HD, t & 7, t >> 3, tile, tid);
    else if (t < 128)  { t -= 64;  ttrans_tile(Wr, wrh, HD, HD, t & 7, t >> 3, tile, tid); }
    else if (t < 256)  { t -= 128; ttrans_tile(W1, w1h, HD, HF, t & 7, t >> 3, tile, tid); }
    else               { t -= 256; ttrans_tile(W2, w2h, HF, HD, t & 15, t >> 4, tile, tid); }
}

// ----------------------- fp16 mma.sync GEMM --------------------------------
// BM=128, BN=256, BK=64, 512 threads, 3-stage cp.async ring (wait_group 1).
// Row = 128B data + 16B pad = 144B (9x16B; 9 = 1 mod 8 -> conflict-free).
#define RB 144
#define A_TILE (128 * RB)
#define B_TILE (256 * RB)
#define STAGE_BYTES (A_TILE + B_TILE)
#define NSTAGE 3
#define SMEM_TOTAL (NSTAGE * STAGE_BYTES)

__device__ __forceinline__ void load_stage(
    uint32_t sa, int tid, int row0, int col0,
    const __half* A, const __half* B, int K, int kc, int M) {
#pragma unroll
    for (int j = 0; j < 2; ++j) {        // A: 1024 chunks of 16B
        int id = tid + j * 512;
        int r = id >> 3, c = id & 7;
        int row = row0 + r;
        int szr = (row < M) ? 16 : 0;
        size_t roff = (row < M) ? (size_t)row : 0;
        cp_async16(sa + r * RB + c * 16, A + roff * K + kc + c * 8, szr);
    }
    uint32_t sb = sa + A_TILE;
#pragma unroll
    for (int j = 0; j < 4; ++j) {        // B: 2048 chunks
        int id = tid + j * 512;
        int r = id >> 3, c = id & 7;
        cp_async16(sb + r * RB + c * 16, B + (size_t)(col0 + r) * K + kc + c * 8, 16);
    }
}

// MODE 0: C = A@B(+A1@B1) + bias + resid(fp16) -> LN -> outf(fp32)? / outh(fp16)?
// MODE 1: C = relu(A@B + bias) -> fp16 outh (stride HF)
template <int MODE>
__global__ void __launch_bounds__(512, 1)
gemm_mma(const __half* __restrict__ A0, const __half* __restrict__ B0, int K0,
         const __half* __restrict__ A1, const __half* __restrict__ B1, int K1,
         const float* __restrict__ bias, const __half* __restrict__ resid,
         const float* __restrict__ gamma, const float* __restrict__ beta,
         float* __restrict__ outf, __half* __restrict__ outh, int M) {
    extern __shared__ char smem[];
    const uint32_t sb0 = smem_u32(smem);
    const int tid = threadIdx.x;
    const int lane = tid & 31;
    const int warp = tid >> 5;           // 0..15
    const int warpM = warp >> 2;         // 0..3
    const int warpN = warp & 3;          // 0..3
    const int row0 = blockIdx.x * 128;
    const int col0 = blockIdx.y * 256;

    float acc[2][8][4];
#pragma unroll
    for (int i = 0; i < 2; ++i)
#pragma unroll
        for (int j = 0; j < 8; ++j)
#pragma unroll
            for (int k = 0; k < 4; ++k) acc[i][j][k] = 0.f;

    const int S = (K0 + K1) >> 6;

    const uint32_t aoff = (uint32_t)((warpM * 32 + (lane & 7) + ((lane >> 3) & 1) * 8) * RB
                                     + (lane >> 4) * 16);
    const uint32_t boff4 = (uint32_t)((warpN * 64 + (lane & 7) + (lane >> 4) * 8) * RB
                                      + ((lane >> 3) & 1) * 16);

#define RESOLVE(IT, AH, BH, KK, KC)                             \
    { int kt = (IT) * 64;                                       \
      if (kt < K0) { AH = A0; BH = B0; KK = K0; KC = kt; }      \
      else         { AH = A1; BH = B1; KK = K1; KC = kt - K0; } }

    // prologue: stages 0,1 (uniform commits)
#pragma unroll
    for (int p = 0; p < 2; ++p) {
        if (p < S) {
            const __half *Ah, *Bh; int KK, KC;
            RESOLVE(p, Ah, Bh, KK, KC);
            load_stage(sb0 + p * STAGE_BYTES, tid, row0, col0, Ah, Bh, KK, KC, M);
        }
        CP_COMMIT();
    }

    int stage = 0;
    for (int it = 0; it < S; ++it) {
        CP_WAIT1();             // stage it done; stage it+1 may be in flight
        __syncthreads();
        if (it + 2 < S) {
            int s2 = stage + 2; if (s2 >= NSTAGE) s2 -= NSTAGE;
            const __half *Ah, *Bh; int KK, KC;
            RESOLVE(it + 2, Ah, Bh, KK, KC);
            load_stage(sb0 + s2 * STAGE_BYTES, tid, row0, col0, Ah, Bh, KK, KC, M);
        }
        CP_COMMIT();

        const uint32_t sa = sb0 + stage * STAGE_BYTES;
        const uint32_t sbB = sa + A_TILE;
#pragma unroll
        for (int ks = 0; ks < 4; ++ks) {
            uint32_t ah[2][4];
#pragma unroll
            for (int tm = 0; tm < 2; ++tm)
                ldsm_x4(ah[tm], sa + aoff + tm * (16 * RB) + ks * 32);
#pragma unroll
            for (int tnp = 0; tnp < 4; ++tnp) {
                uint32_t bh[4];
                ldsm_x4(bh, sbB + boff4 + tnp * (16 * RB) + ks * 32);
#pragma unroll
                for (int tm = 0; tm < 2; ++tm) {
                    mma_f16(acc[tm][2 * tnp + 0], ah[tm], bh);
                    mma_f16(acc[tm][2 * tnp + 1], ah[tm], bh + 2);
                }
            }
        }
        ++stage; if (stage == NSTAGE) stage = 0;
    }

    // prefetch epilogue params before final drain
    float rbias = 0.f, rgam = 0.f, rbet = 0.f;
    if (tid < 256) {
        rbias = bias[col0 + tid];
        if (MODE == 0) { rgam = gamma[tid]; rbet = beta[tid]; }
    }

    __syncthreads();

    // ---------------------------- epilogue ---------------------------------
    float* rsum  = (float*)smem;          // 128
    float* rsq   = rsum + 128;            // 128
    float* sbias = rsq + 128;             // 256
    float* sgam  = sbias + 256;
    float* sbet  = sgam + 256;
    if (MODE == 0 && tid < 128) { rsum[tid] = 0.f; rsq[tid] = 0.f; }
    if (tid < 256) {
        sbias[tid] = rbias;
        if (MODE == 0) { sgam[tid] = rgam; sbet[tid] = rbet; }
    }
    __syncthreads();

    const int qrow = lane >> 2;
    const int qc = (lane & 3) * 2;

    float vsum[4], vsq[4];
#pragma unroll
    for (int k = 0; k < 4; ++k) { vsum[k] = 0.f; vsq[k] = 0.f; }

#pragma unroll
    for (int tm = 0; tm < 2; ++tm) {
#pragma unroll
        for (int rh = 0; rh < 2; ++rh) {
            int rloc = warpM * 32 + tm * 16 + rh * 8 + qrow;
            int rg = row0 + rloc;
            bool v = rg < M;
#pragma unroll
            for (int tn = 0; tn < 8; ++tn) {
                int c = warpN * 64 + tn * 8 + qc;
                float a0 = acc[tm][tn][rh * 2 + 0] + sbias[c];
                float a1 = acc[tm][tn][rh * 2 + 1] + sbias[c + 1];
                if (MODE == 0) {
                    if (v) {
                        uint32_t rp = ((const uint32_t*)resid)[((size_t)rg * 256 + c) >> 1];
                        float2 q = __half22float2(*(const __half2*)&rp);
                        a0 += q.x; a1 += q.y;
                    }
                    vsum[tm * 2 + rh] += a0 + a1;
                    vsq[tm * 2 + rh] += a0 * a0 + a1 * a1;
                } else {
                    a0 = fmaxf(a0, 0.f); a1 = fmaxf(a1, 0.f);
                }
                acc[tm][tn][rh * 2 + 0] = a0;
                acc[tm][tn][rh * 2 + 1] = a1;
            }
        }
    }

    if (MODE == 0) {
#pragma unroll
        for (int k = 0; k < 4; ++k) {
            vsum[k] += __shfl_xor_sync(0xFFFFFFFFu, vsum[k], 1);
            vsum[k] += __shfl_xor_sync(0xFFFFFFFFu, vsum[k], 2);
            vsq[k]  += __shfl_xor_sync(0xFFFFFFFFu, vsq[k], 1);
            vsq[k]  += __shfl_xor_sync(0xFFFFFFFFu, vsq[k], 2);
        }
        if ((lane & 3) == 0) {
#pragma unroll
            for (int tm = 0; tm < 2; ++tm)
#pragma unroll
                for (int rh = 0; rh < 2; ++rh) {
                    int rloc = warpM * 32 + tm * 16 + rh * 8 + qrow;
                    atomicAdd(&rsum[rloc], vsum[tm * 2 + rh]);
                    atomicAdd(&rsq[rloc], vsq[tm * 2 + rh]);
                }
        }
        __syncthreads();
    }

#pragma unroll
    for (int tm = 0; tm < 2; ++tm) {
#pragma unroll
        for (int rh = 0; rh < 2; ++rh) {
            int rloc = warpM * 32 + tm * 16 + rh * 8 + qrow;
            int rg = row0 + rloc;
            if (rg >= M) continue;
            float mean = 0.f, inv = 1.f;
            if (MODE == 0) {
                mean = rsum[rloc] * (1.f / 256.f);
                inv = rsqrtf(rsq[rloc] * (1.f / 256.f) - mean * mean + 1e-5f);
            }
#pragma unroll
            for (int tn = 0; tn < 8; ++tn) {
                int c = warpN * 64 + tn * 8 + qc;
                float a0 = acc[tm][tn][rh * 2 + 0];
                float a1 = acc[tm][tn][rh * 2 + 1];
                if (MODE == 0) {
                    a0 = (a0 - mean) * inv * sgam[c] + sbet[c];
                    a1 = (a1 - mean) * inv * sgam[c + 1] + sbet[c + 1];
                    if (outf != nullptr)
                        *(float2*)(outf + (size_t)rg * 256 + c) = make_float2(a0, a1);
                    if (outh != nullptr)
                        ((uint32_t*)outh)[((size_t)rg * 256 + c) >> 1] = packh2(a0, a1);
                } else {
                    ((uint32_t*)outh)[((size_t)rg * HF + col0 + c) >> 1] = packh2(a0, a1);
                }
            }
        }
    }
}

// ------------------------------ launch --------------------------------------
extern "C" void kernel_launch(void* const* d_in, const int* in_sizes, int n_in,
                              void* d_out, int out_size) {
    const float* x      = (const float*)d_in[0];
    const int*   ei     = (const int*)d_in[1];
    const float* W_nbr  = (const float*)d_in[2];
    const float* W_root = (const float*)d_in[3];
    const float* b_gnn  = (const float*)d_in[4];
    const float* W1     = (const float*)d_in[5];
    const float* b1     = (const float*)d_in[6];
    const float* W2     = (const float*)d_in[7];
    const float* b2     = (const float*)d_in[8];
    const float* g1     = (const float*)d_in[9];
    const float* be1    = (const float*)d_in[10];
    const float* g2     = (const float*)d_in[11];
    const float* be2    = (const float*)d_in[12];
    float* out = (float*)d_out;

    const int M = in_sizes[0] / HD;
    const int E = in_sizes[1] / 2;

    __half *xh, *agh, *hh, *th, *wnh, *wrh, *w1h, *w2h;
    int *deg, *off, *cur, *srcl, *bsum;
    cudaGetSymbolAddress((void**)&xh, g_x_h);
    cudaGetSymbolAddress((void**)&agh, g_ag_h);
    cudaGetSymbolAddress((void**)&hh, g_h_h);
    cudaGetSymbolAddress((void**)&th, g_t_h);
    cudaGetSymbolAddress((void**)&wnh, g_wn_h);
    cudaGetSymbolAddress((void**)&wrh, g_wr_h);
    cudaGetSymbolAddress((void**)&w1h, g_w1_h);
    cudaGetSymbolAddress((void**)&w2h, g_w2_h);
    cudaGetSymbolAddress((void**)&deg, g_deg);
    cudaGetSymbolAddress((void**)&off, g_off);
    cudaGetSymbolAddress((void**)&cur, g_cur);
    cudaGetSymbolAddress((void**)&srcl, g_srcl);
    cudaGetSymbolAddress((void**)&bsum, g_bsum);

    cudaFuncSetAttribute(gemm_mma<0>, cudaFuncAttributeMaxDynamicSharedMemorySize, SMEM_TOTAL);
    cudaFuncSetAttribute(gemm_mma<1>, cudaFuncAttributeMaxDynamicSharedMemorySize, SMEM_TOTAL);

    int n4 = M * HD / 4;
    int nbConv = (n4 + 255) / 256;
    prep_kernel<<<nbConv + 384, 256>>>(x, xh, W_nbr, wnh, W_root, wrh,
                                       W1, w1h, W2, w2h, n4, nbConv);
    detect_kernel<<<1, 128>>>(ei, 2 * E);

    cudaMemsetAsync(deg, 0, M * sizeof(int));
    hist_kernel<<<(E / 2 + 255) / 256, 256>>>(ei, E, deg);

    int nB = (M + SCAN_BLK - 1) / SCAN_BLK;
    block_scan_kernel<<<nB, SCAN_BLK>>>(deg, off, bsum, M);
    bscan_kernel<<<1, 128>>>(bsum, off + M, nB);
    add_off_kernel<<<nB, SCAN_BLK>>>(off, cur, bsum, M);

    fill_kernel<<<(E / 2 + 255) / 256, 256>>>(ei, E, cur, srcl);
    gather_kernel<<<(M + 7) / 8, 256>>>(off, srcl, xh, agh, M);

    int gx = (M + 127) / 128;

    // hh = fp16 LN1(x + agg@Wnbr + x@Wroot + b_gnn)   (resid = xh fp16)
    gemm_mma<0><<<dim3(gx, 1), 512, SMEM_TOTAL>>>(
        agh, wnh, HD, xh, wrh, HD, b_gnn, xh, g1, be1, nullptr, hh, M);

    // th = relu(hh@W1 + b1)
    gemm_mma<1><<<dim3(gx, 2), 512, SMEM_TOTAL>>>(
        hh, w1h, HD, nullptr, nullptr, 0,
        b1, nullptr, nullptr, nullptr, nullptr, th, M);

    // out = LN2(hh + th@W2 + b2)  fp32 to d_out  (resid = hh fp16)
    gemm_mma<0><<<dim3(gx, 1), 512, SMEM_TOTAL>>>(
        th, w2h, HF, nullptr, nullptr, 0,
        b2, hh, g2, be2, out, nullptr, M);
}

// round 13
// speedup vs baseline: 1.0696x; 1.0079x over previous
#include <cuda_runtime.h>
#include <cuda_fp16.h>
#include <cstdint>

#define HD 256
#define HF 512
#define NMAX 50000
#define EMAX 800000
#define SCAN_BLK 512

// ------------------------- scratch (device globals) ------------------------
__device__ __half g_x_h[(size_t)NMAX * HD];
__device__ __half g_ag_h[(size_t)NMAX * HD];
__device__ __half g_h_h[(size_t)NMAX * HD];
__device__ __half g_t_h[(size_t)NMAX * HF];
__device__ __half g_wn_h[HD * HD];
__device__ __half g_wr_h[HD * HD];
__device__ __half g_w1_h[HD * HF];
__device__ __half g_w2_h[HD * HF];
__device__ int g_deg[NMAX];
__device__ int g_off[NMAX + 1];
__device__ int g_cur[NMAX];
__device__ int g_srcl[EMAX];
__device__ int g_bsum[(NMAX + SCAN_BLK - 1) / SCAN_BLK];
__device__ int g_is64;

// ----------------------------- helpers -------------------------------------
__device__ __forceinline__ uint32_t smem_u32(const void* p) {
    uint32_t a;
    asm("{ .reg .u64 t; cvta.to.shared.u64 t, %1; cvt.u32.u64 %0, t; }" : "=r"(a) : "l"(p));
    return a;
}
__device__ __forceinline__ void ldsm_x4(uint32_t* r, uint32_t addr) {
    asm volatile("ldmatrix.sync.aligned.m8n8.x4.shared.b16 {%0,%1,%2,%3}, [%4];"
                 : "=r"(r[0]), "=r"(r[1]), "=r"(r[2]), "=r"(r[3]) : "r"(addr));
}
__device__ __forceinline__ void mma_f16(float* d, const uint32_t* a, const uint32_t* b) {
    asm volatile(
        "mma.sync.aligned.m16n8k16.row.col.f32.f16.f16.f32 "
        "{%0,%1,%2,%3}, {%4,%5,%6,%7}, {%8,%9}, {%0,%1,%2,%3};"
        : "+f"(d[0]), "+f"(d[1]), "+f"(d[2]), "+f"(d[3])
        : "r"(a[0]), "r"(a[1]), "r"(a[2]), "r"(a[3]), "r"(b[0]), "r"(b[1]));
}
__device__ __forceinline__ void cp_async16(uint32_t dst, const void* src, int szr) {
    asm volatile("cp.async.cg.shared.global [%0], [%1], 16, %2;"
                 :: "r"(dst), "l"(src), "r"(szr) : "memory");
}
#define CP_COMMIT() asm volatile("cp.async.commit_group;" ::: "memory")
#define CP_WAIT1()  asm volatile("cp.async.wait_group 1;" ::: "memory")

__device__ __forceinline__ uint32_t packh2(float a, float b) {
    __half2 h = __float22half2_rn(make_float2(a, b));
    return *(uint32_t*)&h;
}

// --------------------------- small kernels ---------------------------------
__global__ void detect_kernel(const int* __restrict__ ei, int twoE) {
    int lim = twoE * 2;
    if (lim > 256) lim = 256;
    int idx = threadIdx.x * 2 + 1;          // odd words
    int nz = (idx < lim) ? ei[idx] : 0;
    int any = __syncthreads_or(nz != 0);
    if (threadIdx.x == 0) g_is64 = (any == 0) ? 1 : 0;
}

__global__ void hist_kernel(const int* __restrict__ ei, int E, int* __restrict__ deg) {
    int t = blockIdx.x * blockDim.x + threadIdx.x;
    if (g_is64) {
        int e0 = t * 2;
        if (e0 >= E) return;
        if (e0 + 2 <= E) {
            int4 d = *(const int4*)(ei + 2 * (E + e0));
            atomicAdd(&deg[d.x], 1);
            atomicAdd(&deg[d.z], 1);
        } else {
            atomicAdd(&deg[ei[2 * (E + e0)]], 1);
        }
    } else {
        int e0 = t * 4;
        if (e0 >= E) return;
        if (e0 + 4 <= E) {
            int4 d = *(const int4*)(ei + E + e0);
            atomicAdd(&deg[d.x], 1);
            atomicAdd(&deg[d.y], 1);
            atomicAdd(&deg[d.z], 1);
            atomicAdd(&deg[d.w], 1);
        } else {
            for (int e = e0; e < E; ++e) atomicAdd(&deg[ei[E + e]], 1);
        }
    }
}

// ---- parallel 3-phase scan ----
__global__ void block_scan_kernel(const int* __restrict__ deg, int* __restrict__ off,
                                  int* __restrict__ bsum, int M) {
    __shared__ int wsum[SCAN_BLK / 32];
    int t = threadIdx.x;
    int i = blockIdx.x * SCAN_BLK + t;
    int lane = t & 31, wid = t >> 5;
    int v = (i < M) ? deg[i] : 0;
    int s = v;
#pragma unroll
    for (int o = 1; o < 32; o <<= 1) {
        int u = __shfl_up_sync(0xFFFFFFFFu, s, o);
        if (lane >= o) s += u;
    }
    if (lane == 31) wsum[wid] = s;
    __syncthreads();
    if (wid == 0) {
        int w = (lane < SCAN_BLK / 32) ? wsum[lane] : 0;
#pragma unroll
        for (int o = 1; o < SCAN_BLK / 32; o <<= 1) {
            int u = __shfl_up_sync(0xFFFFFFFFu, w, o);
            if (lane >= o) w += u;
        }
        if (lane < SCAN_BLK / 32) wsum[lane] = w;
    }
    __syncthreads();
    int excl = s - v + (wid ? wsum[wid - 1] : 0);
    if (i < M) off[i] = excl;
    if (t == SCAN_BLK - 1) bsum[blockIdx.x] = excl + v;
}

__global__ void bscan_kernel(int* __restrict__ bsum, int* __restrict__ offM, int nB) {
    __shared__ int ws[4];
    int t = threadIdx.x;        // 128 threads
    int lane = t & 31, wid = t >> 5;
    int v = (t < nB) ? bsum[t] : 0;
    int s = v;
#pragma unroll
    for (int o = 1; o < 32; o <<= 1) {
        int u = __shfl_up_sync(0xFFFFFFFFu, s, o);
        if (lane >= o) s += u;
    }
    if (lane == 31) ws[wid] = s;
    __syncthreads();
    if (t == 0) {
        int r = 0;
#pragma unroll
        for (int i = 0; i < 4; ++i) { int x = ws[i]; ws[i] = r; r += x; }
        *offM = r;
    }
    __syncthreads();
    int excl = s - v + ws[wid];
    if (t < nB) bsum[t] = excl;
}

__global__ void add_off_kernel(int* __restrict__ off, int* __restrict__ cur,
                               const int* __restrict__ bsum, int M) {
    int i = blockIdx.x * SCAN_BLK + threadIdx.x;
    if (i < M) {
        int v = off[i] + bsum[blockIdx.x];
        off[i] = v;
        cur[i] = v;
    }
}

__global__ void fill_kernel(const int* __restrict__ ei, int E,
                            int* __restrict__ cur, int* __restrict__ srcl) {
    int t = blockIdx.x * blockDim.x + threadIdx.x;
    if (g_is64) {
        int e0 = t * 2;
        if (e0 >= E) return;
        if (e0 + 2 <= E) {
            int4 s = *(const int4*)(ei + 2 * e0);
            int4 d = *(const int4*)(ei + 2 * (E + e0));
            srcl[atomicAdd(&cur[d.x], 1)] = s.x;
            srcl[atomicAdd(&cur[d.z], 1)] = s.z;
        } else {
            srcl[atomicAdd(&cur[ei[2 * (E + e0)]], 1)] = ei[2 * e0];
        }
    } else {
        int e0 = t * 4;
        if (e0 >= E) return;
        if (e0 + 4 <= E) {
            int4 s = *(const int4*)(ei + e0);
            int4 d = *(const int4*)(ei + E + e0);
            srcl[atomicAdd(&cur[d.x], 1)] = s.x;
            srcl[atomicAdd(&cur[d.y], 1)] = s.y;
            srcl[atomicAdd(&cur[d.z], 1)] = s.z;
            srcl[atomicAdd(&cur[d.w], 1)] = s.w;
        } else {
            for (int e = e0; e < E; ++e)
                srcl[atomicAdd(&cur[ei[E + e]], 1)] = ei[e];
        }
    }
}

// gather: one warp per node; software-pipelined srcl prefetch; fp16 out
__global__ void __launch_bounds__(256)
gather_kernel(const int* __restrict__ off, const int* __restrict__ srcl,
              const __half* __restrict__ xh, __half* __restrict__ agh, int M) {
    int node = blockIdx.x * 8 + (threadIdx.x >> 5);
    int lane = threadIdx.x & 31;
    if (node >= M) return;
    int j0 = off[node], j1 = off[node + 1];

    float acc[8];
#pragma unroll
    for (int k = 0; k < 8; ++k) acc[k] = 0.f;

    const uint4* xb = (const uint4*)xh;
    int nfull = (j1 - j0) >> 3;
    int srcs[8];
    if (nfull > 0) {
#pragma unroll
        for (int u = 0; u < 8; ++u) srcs[u] = srcl[j0 + u];
    }
    for (int b = 0; b < nfull; ++b) {
        uint4 v[8];
#pragma unroll
        for (int u = 0; u < 8; ++u) v[u] = xb[(size_t)srcs[u] * 32 + lane];
        int nsrcs[8];
        bool more = (b + 1 < nfull);
        if (more) {
            int jn = j0 + (b + 1) * 8;
#pragma unroll
            for (int u = 0; u < 8; ++u) nsrcs[u] = srcl[jn + u];
        }
#pragma unroll
        for (int u = 0; u < 8; ++u) {
            float2 f0 = __half22float2(*(const __half2*)&v[u].x);
            float2 f1 = __half22float2(*(const __half2*)&v[u].y);
            float2 f2 = __half22float2(*(const __half2*)&v[u].z);
            float2 f3 = __half22float2(*(const __half2*)&v[u].w);
            acc[0] += f0.x; acc[1] += f0.y; acc[2] += f1.x; acc[3] += f1.y;
            acc[4] += f2.x; acc[5] += f2.y; acc[6] += f3.x; acc[7] += f3.y;
        }
        if (more) {
#pragma unroll
            for (int u = 0; u < 8; ++u) srcs[u] = nsrcs[u];
        }
    }
    for (int j = j0 + nfull * 8; j < j1; ++j) {
        uint4 v = xb[(size_t)srcl[j] * 32 + lane];
        float2 f0 = __half22float2(*(const __half2*)&v.x);
        float2 f1 = __half22float2(*(const __half2*)&v.y);
        float2 f2 = __half22float2(*(const __half2*)&v.z);
        float2 f3 = __half22float2(*(const __half2*)&v.w);
        acc[0] += f0.x; acc[1] += f0.y; acc[2] += f1.x; acc[3] += f1.y;
        acc[4] += f2.x; acc[5] += f2.y; acc[6] += f3.x; acc[7] += f3.y;
    }

    uint32_t hi[4];
#pragma unroll
    for (int k = 0; k < 4; ++k) hi[k] = packh2(acc[2 * k], acc[2 * k + 1]);
    ((uint4*)agh)[(size_t)node * 32 + lane] = make_uint4(hi[0], hi[1], hi[2], hi[3]);
}

// fused prep: conv (x -> xh) + 4 weight transposes, block-index segmented.
__device__ __forceinline__ void ttrans_tile(const float* W, __half* out,
                                            int K, int N, int kb, int nb,
                                            float (*tile)[33], int tid) {
    int tx = tid & 31, ty = tid >> 5;   // 32 x 8
    int k0 = kb * 32, n0 = nb * 32;
#pragma unroll
    for (int i = 0; i < 4; ++i)
        tile[ty + i * 8][tx] = W[(size_t)(k0 + ty + i * 8) * N + n0 + tx];
    __syncthreads();
#pragma unroll
    for (int i = 0; i < 4; ++i)
        out[(size_t)(n0 + ty + i * 8) * K + k0 + tx] =
            __float2half_rn(tile[tx][ty + i * 8]);
}

__global__ void prep_kernel(const float* __restrict__ x, __half* __restrict__ xh,
                            const float* __restrict__ Wn, __half* __restrict__ wnh,
                            const float* __restrict__ Wr, __half* __restrict__ wrh,
                            const float* __restrict__ W1, __half* __restrict__ w1h,
                            const float* __restrict__ W2, __half* __restrict__ w2h,
                            int n4, int nbConv) {
    __shared__ float tile[32][33];
    int b = blockIdx.x;
    int tid = threadIdx.x;
    if (b < nbConv) {
        int i = b * 256 + tid;
        if (i < n4) {
            float4 v = ((const float4*)x)[i];
            ((uint2*)xh)[i] = make_uint2(packh2(v.x, v.y), packh2(v.z, v.w));
        }
        return;
    }
    int t = b - nbConv;
    if (t < 64)        ttrans_tile(Wn, wnh, HD, HD, t & 7, t >> 3, tile, tid);
    else if (t < 128)  { t -= 64;  ttrans_tile(Wr, wrh, HD, HD, t & 7, t >> 3, tile, tid); }
    else if (t < 256)  { t -= 128; ttrans_tile(W1, w1h, HD, HF, t & 7, t >> 3, tile, tid); }
    else               { t -= 256; ttrans_tile(W2, w2h, HF, HD, t & 15, t >> 4, tile, tid); }
}

// ----------------------- fp16 mma.sync GEMM (persistent tiles) -------------
// BM=128, BN=256, BK=64, 512 threads, 3-stage cp.async ring (wait_group 1).
// Row = 128B data + 16B pad = 144B (9x16B; 9 = 1 mod 8 -> conflict-free).
#define RB 144
#define A_TILE (128 * RB)
#define B_TILE (256 * RB)
#define STAGE_BYTES (A_TILE + B_TILE)
#define NSTAGE 3
#define SMEM_TOTAL (NSTAGE * STAGE_BYTES)

__device__ __forceinline__ void load_stage(
    uint32_t sa, int tid, int row0, int col0,
    const __half* A, const __half* B, int K, int kc, int M) {
#pragma unroll
    for (int j = 0; j < 2; ++j) {        // A: 1024 chunks of 16B
        int id = tid + j * 512;
        int r = id >> 3, c = id & 7;
        int row = row0 + r;
        int szr = (row < M) ? 16 : 0;
        size_t roff = (row < M) ? (size_t)row : 0;
        cp_async16(sa + r * RB + c * 16, A + roff * K + kc + c * 8, szr);
    }
    uint32_t sb = sa + A_TILE;
#pragma unroll
    for (int j = 0; j < 4; ++j) {        // B: 2048 chunks
        int id = tid + j * 512;
        int r = id >> 3, c = id & 7;
        cp_async16(sb + r * RB + c * 16, B + (size_t)(col0 + r) * K + kc + c * 8, 16);
    }
}

// MODE 0: C = A@B(+A1@B1) + bias + resid(fp16) -> LN -> outf(fp32)? / outh(fp16)?
// MODE 1: C = relu(A@B + bias) -> fp16 outh (stride HF)
template <int MODE>
__global__ void __launch_bounds__(512, 1)
gemm_mma(const __half* __restrict__ A0, const __half* __restrict__ B0, int K0,
         const __half* __restrict__ A1, const __half* __restrict__ B1, int K1,
         const float* __restrict__ bias, const __half* __restrict__ resid,
         const float* __restrict__ gamma, const float* __restrict__ beta,
         float* __restrict__ outf, __half* __restrict__ outh, int M,
         int ntX, int ntTotal) {
    extern __shared__ char smem[];
    const uint32_t sb0 = smem_u32(smem);
    const int tid = threadIdx.x;
    const int lane = tid & 31;
    const int warp = tid >> 5;           // 0..15
    const int warpM = warp >> 2;         // 0..3
    const int warpN = warp & 3;          // 0..3

    const int S = (K0 + K1) >> 6;

    const uint32_t aoff = (uint32_t)((warpM * 32 + (lane & 7) + ((lane >> 3) & 1) * 8) * RB
                                     + (lane >> 4) * 16);
    const uint32_t boff4 = (uint32_t)((warpN * 64 + (lane & 7) + (lane >> 4) * 8) * RB
                                      + ((lane >> 3) & 1) * 16);

#define RESOLVE(IT, AH, BH, KK, KC)                             \
    { int kt = (IT) * 64;                                       \
      if (kt < K0) { AH = A0; BH = B0; KK = K0; KC = kt; }      \
      else         { AH = A1; BH = B1; KK = K1; KC = kt - K0; } }

    for (int tile = blockIdx.x; tile < ntTotal; tile += gridDim.x) {
        const int row0 = (tile % ntX) * 128;
        const int col0 = (tile / ntX) * 256;

        float acc[2][8][4];
#pragma unroll
        for (int i = 0; i < 2; ++i)
#pragma unroll
            for (int j = 0; j < 8; ++j)
#pragma unroll
                for (int k = 0; k < 4; ++k) acc[i][j][k] = 0.f;

        __syncthreads();    // protect prior epilogue smem reads from new loads

        // prologue: stages 0,1 (uniform commits)
#pragma unroll
        for (int p = 0; p < 2; ++p) {
            if (p < S) {
                const __half *Ah, *Bh; int KK, KC;
                RESOLVE(p, Ah, Bh, KK, KC);
                load_stage(sb0 + p * STAGE_BYTES, tid, row0, col0, Ah, Bh, KK, KC, M);
            }
            CP_COMMIT();
        }

        int stage = 0;
        for (int it = 0; it < S; ++it) {
            CP_WAIT1();
            __syncthreads();
            if (it + 2 < S) {
                int s2 = stage + 2; if (s2 >= NSTAGE) s2 -= NSTAGE;
                const __half *Ah, *Bh; int KK, KC;
                RESOLVE(it + 2, Ah, Bh, KK, KC);
                load_stage(sb0 + s2 * STAGE_BYTES, tid, row0, col0, Ah, Bh, KK, KC, M);
            }
            CP_COMMIT();

            const uint32_t sa = sb0 + stage * STAGE_BYTES;
            const uint32_t sbB = sa + A_TILE;
#pragma unroll
            for (int ks = 0; ks < 4; ++ks) {
                uint32_t ah[2][4];
#pragma unroll
                for (int tm = 0; tm < 2; ++tm)
                    ldsm_x4(ah[tm], sa + aoff + tm * (16 * RB) + ks * 32);
#pragma unroll
                for (int tnp = 0; tnp < 4; ++tnp) {
                    uint32_t bh[4];
                    ldsm_x4(bh, sbB + boff4 + tnp * (16 * RB) + ks * 32);
#pragma unroll
                    for (int tm = 0; tm < 2; ++tm) {
                        mma_f16(acc[tm][2 * tnp + 0], ah[tm], bh);
                        mma_f16(acc[tm][2 * tnp + 1], ah[tm], bh + 2);
                    }
                }
            }
            ++stage; if (stage == NSTAGE) stage = 0;
        }

        // prefetch epilogue params before final drain
        float rbias = 0.f, rgam = 0.f, rbet = 0.f;
        if (tid < 256) {
            rbias = bias[col0 + tid];
            if (MODE == 0) { rgam = gamma[tid]; rbet = beta[tid]; }
        }

        __syncthreads();

        // ---------------------------- epilogue -----------------------------
        float* rsum  = (float*)smem;          // 128
        float* rsq   = rsum + 128;            // 128
        float* sbias = rsq + 128;             // 256
        float* sgam  = sbias + 256;
        float* sbet  = sgam + 256;
        if (MODE == 0 && tid < 128) { rsum[tid] = 0.f; rsq[tid] = 0.f; }
        if (tid < 256) {
            sbias[tid] = rbias;
            if (MODE == 0) { sgam[tid] = rgam; sbet[tid] = rbet; }
        }
        __syncthreads();

        const int qrow = lane >> 2;
        const int qc = (lane & 3) * 2;

        float vsum[4], vsq[4];
#pragma unroll
        for (int k = 0; k < 4; ++k) { vsum[k] = 0.f; vsq[k] = 0.f; }

#pragma unroll
        for (int tm = 0; tm < 2; ++tm) {
#pragma unroll
            for (int rh = 0; rh < 2; ++rh) {
                int rloc = warpM * 32 + tm * 16 + rh * 8 + qrow;
                int rg = row0 + rloc;
                bool v = rg < M;
#pragma unroll
                for (int tn = 0; tn < 8; ++tn) {
                    int c = warpN * 64 + tn * 8 + qc;
                    float a0 = acc[tm][tn][rh * 2 + 0] + sbias[c];
                    float a1 = acc[tm][tn][rh * 2 + 1] + sbias[c + 1];
                    if (MODE == 0) {
                        if (v) {
                            uint32_t rp = ((const uint32_t*)resid)[((size_t)rg * 256 + c) >> 1];
                            float2 q = __half22float2(*(const __half2*)&rp);
                            a0 += q.x; a1 += q.y;
                        }
                        vsum[tm * 2 + rh] += a0 + a1;
                        vsq[tm * 2 + rh] += a0 * a0 + a1 * a1;
                    } else {
                        a0 = fmaxf(a0, 0.f); a1 = fmaxf(a1, 0.f);
                    }
                    acc[tm][tn][rh * 2 + 0] = a0;
                    acc[tm][tn][rh * 2 + 1] = a1;
                }
            }
        }

        if (MODE == 0) {
#pragma unroll
            for (int k = 0; k < 4; ++k) {
                vsum[k] += __shfl_xor_sync(0xFFFFFFFFu, vsum[k], 1);
                vsum[k] += __shfl_xor_sync(0xFFFFFFFFu, vsum[k], 2);
                vsq[k]  += __shfl_xor_sync(0xFFFFFFFFu, vsq[k], 1);
                vsq[k]  += __shfl_xor_sync(0xFFFFFFFFu, vsq[k], 2);
            }
            if ((lane & 3) == 0) {
#pragma unroll
                for (int tm = 0; tm < 2; ++tm)
#pragma unroll
                    for (int rh = 0; rh < 2; ++rh) {
                        int rloc = warpM * 32 + tm * 16 + rh * 8 + qrow;
                        atomicAdd(&rsum[rloc], vsum[tm * 2 + rh]);
                        atomicAdd(&rsq[rloc], vsq[tm * 2 + rh]);
                    }
            }
            __syncthreads();
        }

#pragma unroll
        for (int tm = 0; tm < 2; ++tm) {
#pragma unroll
            for (int rh = 0; rh < 2; ++rh) {
                int rloc = warpM * 32 + tm * 16 + rh * 8 + qrow;
                int rg = row0 + rloc;
                if (rg >= M) continue;
                float mean = 0.f, inv = 1.f;
                if (MODE == 0) {
                    mean = rsum[rloc] * (1.f / 256.f);
                    inv = rsqrtf(rsq[rloc] * (1.f / 256.f) - mean * mean + 1e-5f);
                }
#pragma unroll
                for (int tn = 0; tn < 8; ++tn) {
                    int c = warpN * 64 + tn * 8 + qc;
                    float a0 = acc[tm][tn][rh * 2 + 0];
                    float a1 = acc[tm][tn][rh * 2 + 1];
                    if (MODE == 0) {
                        a0 = (a0 - mean) * inv * sgam[c] + sbet[c];
                        a1 = (a1 - mean) * inv * sgam[c + 1] + sbet[c + 1];
                        if (outf != nullptr)
                            *(float2*)(outf + (size_t)rg * 256 + c) = make_float2(a0, a1);
                        if (outh != nullptr)
                            ((uint32_t*)outh)[((size_t)rg * 256 + c) >> 1] = packh2(a0, a1);
                    } else {
                        ((uint32_t*)outh)[((size_t)rg * HF + col0 + c) >> 1] = packh2(a0, a1);
                    }
                }
            }
        }
    }
}

// ------------------------------ launch --------------------------------------
extern "C" void kernel_launch(void* const* d_in, const int* in_sizes, int n_in,
                              void* d_out, int out_size) {
    const float* x      = (const float*)d_in[0];
    const int*   ei     = (const int*)d_in[1];
    const float* W_nbr  = (const float*)d_in[2];
    const float* W_root = (const float*)d_in[3];
    const float* b_gnn  = (const float*)d_in[4];
    const float* W1     = (const float*)d_in[5];
    const float* b1     = (const float*)d_in[6];
    const float* W2     = (const float*)d_in[7];
    const float* b2     = (const float*)d_in[8];
    const float* g1     = (const float*)d_in[9];
    const float* be1    = (const float*)d_in[10];
    const float* g2     = (const float*)d_in[11];
    const float* be2    = (const float*)d_in[12];
    float* out = (float*)d_out;

    const int M = in_sizes[0] / HD;
    const int E = in_sizes[1] / 2;

    __half *xh, *agh, *hh, *th, *wnh, *wrh, *w1h, *w2h;
    int *deg, *off, *cur, *srcl, *bsum;
    cudaGetSymbolAddress((void**)&xh, g_x_h);
    cudaGetSymbolAddress((void**)&agh, g_ag_h);
    cudaGetSymbolAddress((void**)&hh, g_h_h);
    cudaGetSymbolAddress((void**)&th, g_t_h);
    cudaGetSymbolAddress((void**)&wnh, g_wn_h);
    cudaGetSymbolAddress((void**)&wrh, g_wr_h);
    cudaGetSymbolAddress((void**)&w1h, g_w1_h);
    cudaGetSymbolAddress((void**)&w2h, g_w2_h);
    cudaGetSymbolAddress((void**)&deg, g_deg);
    cudaGetSymbolAddress((void**)&off, g_off);
    cudaGetSymbolAddress((void**)&cur, g_cur);
    cudaGetSymbolAddress((void**)&srcl, g_srcl);
    cudaGetSymbolAddress((void**)&bsum, g_bsum);

    cudaFuncSetAttribute(gemm_mma<0>, cudaFuncAttributeMaxDynamicSharedMemorySize, SMEM_TOTAL);
    cudaFuncSetAttribute(gemm_mma<1>, cudaFuncAttributeMaxDynamicSharedMemorySize, SMEM_TOTAL);

    int n4 = M * HD / 4;
    int nbConv = (n4 + 255) / 256;
    prep_kernel<<<nbConv + 384, 256>>>(x, xh, W_nbr, wnh, W_root, wrh,
                                       W1, w1h, W2, w2h, n4, nbConv);
    detect_kernel<<<1, 128>>>(ei, 2 * E);

    cudaMemsetAsync(deg, 0, M * sizeof(int));
    hist_kernel<<<(E / 2 + 255) / 256, 256>>>(ei, E, deg);

    int nB = (M + SCAN_BLK - 1) / SCAN_BLK;
    block_scan_kernel<<<nB, SCAN_BLK>>>(deg, off, bsum, M);
    bscan_kernel<<<1, 128>>>(bsum, off + M, nB);
    add_off_kernel<<<nB, SCAN_BLK>>>(off, cur, bsum, M);

    fill_kernel<<<(E / 2 + 255) / 256, 256>>>(ei, E, cur, srcl);
    gather_kernel<<<(M + 7) / 8, 256>>>(off, srcl, xh, agh, M);

    int ntX = (M + 127) / 128;              // 391
    int grid0 = ntX < 148 ? ntX : 148;
    int nt1 = ntX * 2;
    int grid1 = nt1 < 148 ? nt1 : 148;

    // hh = fp16 LN1(x + agg@Wnbr + x@Wroot + b_gnn)   (resid = xh fp16)
    gemm_mma<0><<<grid0, 512, SMEM_TOTAL>>>(
        agh, wnh, HD, xh, wrh, HD, b_gnn, xh, g1, be1, nullptr, hh, M, ntX, ntX);

    // th = relu(hh@W1 + b1)
    gemm_mma<1><<<grid1, 512, SMEM_TOTAL>>>(
        hh, w1h, HD, nullptr, nullptr, 0,
        b1, nullptr, nullptr, nullptr, nullptr, th, M, ntX, nt1);

    // out = LN2(hh + th@W2 + b2)  fp32 to d_out  (resid = hh fp16)
    gemm_mma<0><<<grid0, 512, SMEM_TOTAL>>>(
        th, w2h, HF, nullptr, nullptr, 0,
        b2, hh, g2, be2, out, nullptr, M, ntX, ntX);
}

// round 14
// speedup vs baseline: 1.0826x; 1.0122x over previous
#include <cuda_runtime.h>
#include <cuda_fp16.h>
#include <cstdint>

#define HD 256
#define HF 512
#define NMAX 50000
#define EMAX 800000
#define SCAN_BLK 512
#define NBMAX ((NMAX + SCAN_BLK - 1) / SCAN_BLK)

// ------------------------- scratch (device globals) ------------------------
__device__ __half g_x_h[(size_t)NMAX * HD];
__device__ __half g_ag_h[(size_t)NMAX * HD];
__device__ __half g_h_h[(size_t)NMAX * HD];
__device__ __half g_t_h[(size_t)NMAX * HF];
__device__ __half g_wn_h[HD * HD];
__device__ __half g_wr_h[HD * HD];
__device__ __half g_w1_h[HD * HF];
__device__ __half g_w2_h[HD * HF];
__device__ int g_zb[NMAX + NBMAX];   // [0,NMAX)=deg, [NMAX,NMAX+NBMAX)=lookback state
__device__ int g_off[NMAX + 1];
__device__ int g_cur[NMAX];
__device__ int g_srcl[EMAX];

// ----------------------------- helpers -------------------------------------
__device__ __forceinline__ uint32_t smem_u32(const void* p) {
    uint32_t a;
    asm("{ .reg .u64 t; cvta.to.shared.u64 t, %1; cvt.u32.u64 %0, t; }" : "=r"(a) : "l"(p));
    return a;
}
__device__ __forceinline__ void ldsm_x4(uint32_t* r, uint32_t addr) {
    asm volatile("ldmatrix.sync.aligned.m8n8.x4.shared.b16 {%0,%1,%2,%3}, [%4];"
                 : "=r"(r[0]), "=r"(r[1]), "=r"(r[2]), "=r"(r[3]) : "r"(addr));
}
__device__ __forceinline__ void mma_f16(float* d, const uint32_t* a, const uint32_t* b) {
    asm volatile(
        "mma.sync.aligned.m16n8k16.row.col.f32.f16.f16.f32 "
        "{%0,%1,%2,%3}, {%4,%5,%6,%7}, {%8,%9}, {%0,%1,%2,%3};"
        : "+f"(d[0]), "+f"(d[1]), "+f"(d[2]), "+f"(d[3])
        : "r"(a[0]), "r"(a[1]), "r"(a[2]), "r"(a[3]), "r"(b[0]), "r"(b[1]));
}
__device__ __forceinline__ void cp_async16(uint32_t dst, const void* src, int szr) {
    asm volatile("cp.async.cg.shared.global [%0], [%1], 16, %2;"
                 :: "r"(dst), "l"(src), "r"(szr) : "memory");
}
#define CP_COMMIT() asm volatile("cp.async.commit_group;" ::: "memory")
#define CP_WAIT1()  asm volatile("cp.async.wait_group 1;" ::: "memory")

__device__ __forceinline__ uint32_t packh2(float a, float b) {
    __half2 h = __float22half2_rn(make_float2(a, b));
    return *(uint32_t*)&h;
}

// inline int64/int32 edge-dtype detection: all odd words of first 128 pairs zero
__device__ __forceinline__ int detect_is64_block(const int* __restrict__ ei, int E) {
    int lim = 4 * E;                 // word count if int64; clamp to 256 probes
    if (lim > 256) lim = 256;
    int idx = threadIdx.x * 2 + 1;
    int nz = (threadIdx.x < 128 && idx < lim) ? ei[idx] : 0;
    int any = __syncthreads_or(nz != 0);
    return (any == 0) ? 1 : 0;
}

// --------------------------- small kernels ---------------------------------
__global__ void hist_kernel(const int* __restrict__ ei, int E, int* __restrict__ deg) {
    int is64 = detect_is64_block(ei, E);
    int t = blockIdx.x * blockDim.x + threadIdx.x;
    if (is64) {
        int e0 = t * 2;
        if (e0 >= E) return;
        if (e0 + 2 <= E) {
            int4 d = *(const int4*)(ei + 2 * (E + e0));
            atomicAdd(&deg[d.x], 1);
            atomicAdd(&deg[d.z], 1);
        } else {
            atomicAdd(&deg[ei[2 * (E + e0)]], 1);
        }
    } else {
        int e0 = t * 4;
        if (e0 >= E) return;
        if (e0 + 4 <= E) {
            int4 d = *(const int4*)(ei + E + e0);
            atomicAdd(&deg[d.x], 1);
            atomicAdd(&deg[d.y], 1);
            atomicAdd(&deg[d.z], 1);
            atomicAdd(&deg[d.w], 1);
        } else {
            for (int e = e0; e < E; ++e) atomicAdd(&deg[ei[E + e]], 1);
        }
    }
}

// ---- single-pass decoupled-lookback exclusive scan (nB <= 148 -> 1 wave) ---
#define FLAG_AGG (1 << 30)
#define FLAG_INC (1u << 31)
#define VALMASK  0x3FFFFFFF

__global__ void scan_kernel(const int* __restrict__ deg, int* __restrict__ off,
                            int* __restrict__ cur, int* __restrict__ state, int M) {
    __shared__ int wsum[SCAN_BLK / 32];
    __shared__ int s_pref;
    int b = blockIdx.x;
    int t = threadIdx.x;
    int i = b * SCAN_BLK + t;
    int lane = t & 31, wid = t >> 5;
    int v = (i < M) ? deg[i] : 0;
    int s = v;
#pragma unroll
    for (int o = 1; o < 32; o <<= 1) {
        int u = __shfl_up_sync(0xFFFFFFFFu, s, o);
        if (lane >= o) s += u;
    }
    if (lane == 31) wsum[wid] = s;
    __syncthreads();
    if (wid == 0) {
        int w = (lane < SCAN_BLK / 32) ? wsum[lane] : 0;
#pragma unroll
        for (int o = 1; o < SCAN_BLK / 32; o <<= 1) {
            int u = __shfl_up_sync(0xFFFFFFFFu, w, o);
            if (lane >= o) w += u;
        }
        if (lane < SCAN_BLK / 32) wsum[lane] = w;   // inclusive warp totals
    }
    __syncthreads();
    int excl = s - v + (wid ? wsum[wid - 1] : 0);

    if (t == 0) {
        int tot = wsum[SCAN_BLK / 32 - 1];
        if (b == 0) {
            atomicExch(&state[0], (int)(tot | FLAG_INC));
            s_pref = 0;
        } else {
            atomicExch(&state[b], tot | FLAG_AGG);
            int pref = 0, j = b - 1;
            while (true) {
                int st = atomicAdd(&state[j], 0);
                if ((unsigned)st & FLAG_INC) { pref += st & VALMASK; break; }
                if (st & FLAG_AGG)           { pref += st & VALMASK; --j; }
            }
            atomicExch(&state[b], (int)((tot + pref) | FLAG_INC));
            s_pref = pref;
        }
    }
    __syncthreads();
    int base = s_pref + excl;
    if (i < M) { off[i] = base; cur[i] = base; }
    if (i == M - 1) off[M] = base + v;
}

__global__ void fill_kernel(const int* __restrict__ ei, int E,
                            int* __restrict__ cur, int* __restrict__ srcl) {
    int is64 = detect_is64_block(ei, E);
    int t = blockIdx.x * blockDim.x + threadIdx.x;
    if (is64) {
        int e0 = t * 2;
        if (e0 >= E) return;
        if (e0 + 2 <= E) {
            int4 s = *(const int4*)(ei + 2 * e0);
            int4 d = *(const int4*)(ei + 2 * (E + e0));
            srcl[atomicAdd(&cur[d.x], 1)] = s.x;
            srcl[atomicAdd(&cur[d.z], 1)] = s.z;
        } else {
            srcl[atomicAdd(&cur[ei[2 * (E + e0)]], 1)] = ei[2 * e0];
        }
    } else {
        int e0 = t * 4;
        if (e0 >= E) return;
        if (e0 + 4 <= E) {
            int4 s = *(const int4*)(ei + e0);
            int4 d = *(const int4*)(ei + E + e0);
            srcl[atomicAdd(&cur[d.x], 1)] = s.x;
            srcl[atomicAdd(&cur[d.y], 1)] = s.y;
            srcl[atomicAdd(&cur[d.z], 1)] = s.z;
            srcl[atomicAdd(&cur[d.w], 1)] = s.w;
        } else {
            for (int e = e0; e < E; ++e)
                srcl[atomicAdd(&cur[ei[E + e]], 1)] = ei[e];
        }
    }
}

// gather: one warp per node; software-pipelined srcl prefetch; fp16 out
__global__ void __launch_bounds__(256)
gather_kernel(const int* __restrict__ off, const int* __restrict__ srcl,
              const __half* __restrict__ xh, __half* __restrict__ agh, int M) {
    int node = blockIdx.x * 8 + (threadIdx.x >> 5);
    int lane = threadIdx.x & 31;
    if (node >= M) return;
    int j0 = off[node], j1 = off[node + 1];

    float acc[8];
#pragma unroll
    for (int k = 0; k < 8; ++k) acc[k] = 0.f;

    const uint4* xb = (const uint4*)xh;
    int nfull = (j1 - j0) >> 3;
    int srcs[8];
    if (nfull > 0) {
#pragma unroll
        for (int u = 0; u < 8; ++u) srcs[u] = srcl[j0 + u];
    }
    for (int b = 0; b < nfull; ++b) {
        uint4 v[8];
#pragma unroll
        for (int u = 0; u < 8; ++u) v[u] = xb[(size_t)srcs[u] * 32 + lane];
        int nsrcs[8];
        bool more = (b + 1 < nfull);
        if (more) {
            int jn = j0 + (b + 1) * 8;
#pragma unroll
            for (int u = 0; u < 8; ++u) nsrcs[u] = srcl[jn + u];
        }
#pragma unroll
        for (int u = 0; u < 8; ++u) {
            float2 f0 = __half22float2(*(const __half2*)&v[u].x);
            float2 f1 = __half22float2(*(const __half2*)&v[u].y);
            float2 f2 = __half22float2(*(const __half2*)&v[u].z);
            float2 f3 = __half22float2(*(const __half2*)&v[u].w);
            acc[0] += f0.x; acc[1] += f0.y; acc[2] += f1.x; acc[3] += f1.y;
            acc[4] += f2.x; acc[5] += f2.y; acc[6] += f3.x; acc[7] += f3.y;
        }
        if (more) {
#pragma unroll
            for (int u = 0; u < 8; ++u) srcs[u] = nsrcs[u];
        }
    }
    for (int j = j0 + nfull * 8; j < j1; ++j) {
        uint4 v = xb[(size_t)srcl[j] * 32 + lane];
        float2 f0 = __half22float2(*(const __half2*)&v.x);
        float2 f1 = __half22float2(*(const __half2*)&v.y);
        float2 f2 = __half22float2(*(const __half2*)&v.z);
        float2 f3 = __half22float2(*(const __half2*)&v.w);
        acc[0] += f0.x; acc[1] += f0.y; acc[2] += f1.x; acc[3] += f1.y;
        acc[4] += f2.x; acc[5] += f2.y; acc[6] += f3.x; acc[7] += f3.y;
    }

    uint32_t hi[4];
#pragma unroll
    for (int k = 0; k < 4; ++k) hi[k] = packh2(acc[2 * k], acc[2 * k + 1]);
    ((uint4*)agh)[(size_t)node * 32 + lane] = make_uint4(hi[0], hi[1], hi[2], hi[3]);
}

// fused prep: conv (x -> xh) + 4 weight transposes, block-index segmented.
__device__ __forceinline__ void ttrans_tile(const float* W, __half* out,
                                            int K, int N, int kb, int nb,
                                            float (*tile)[33], int tid) {
    int tx = tid & 31, ty = tid >> 5;   // 32 x 8
    int k0 = kb * 32, n0 = nb * 32;
#pragma unroll
    for (int i = 0; i < 4; ++i)
        tile[ty + i * 8][tx] = W[(size_t)(k0 + ty + i * 8) * N + n0 + tx];
    __syncthreads();
#pragma unroll
    for (int i = 0; i < 4; ++i)
        out[(size_t)(n0 + ty + i * 8) * K + k0 + tx] =
            __float2half_rn(tile[tx][ty + i * 8]);
}

__global__ void prep_kernel(const float* __restrict__ x, __half* __restrict__ xh,
                            const float* __restrict__ Wn, __half* __restrict__ wnh,
                            const float* __restrict__ Wr, __half* __restrict__ wrh,
                            const float* __restrict__ W1, __half* __restrict__ w1h,
                            const float* __restrict__ W2, __half* __restrict__ w2h,
                            int n4, int nbConv) {
    __shared__ float tile[32][33];
    int b = blockIdx.x;
    int tid = threadIdx.x;
    if (b < nbConv) {
        int i = b * 256 + tid;
        if (i < n4) {
            float4 v = ((const float4*)x)[i];
            ((uint2*)xh)[i] = make_uint2(packh2(v.x, v.y), packh2(v.z, v.w));
        }
        return;
    }
    int t = b - nbConv;
    if (t < 64)        ttrans_tile(Wn, wnh, HD, HD, t & 7, t >> 3, tile, tid);
    else if (t < 128)  { t -= 64;  ttrans_tile(Wr, wrh, HD, HD, t & 7, t >> 3, tile, tid); }
    else if (t < 256)  { t -= 128; ttrans_tile(W1, w1h, HD, HF, t & 7, t >> 3, tile, tid); }
    else               { t -= 256; ttrans_tile(W2, w2h, HF, HD, t & 15, t >> 4, tile, tid); }
}

// ----------------------- fp16 mma.sync GEMM (persistent tiles) -------------
// BM=128, BN=256, BK=64, 512 threads, 3-stage cp.async ring (wait_group 1).
// Row = 128B data + 16B pad = 144B (9x16B; 9 = 1 mod 8 -> conflict-free).
#define RB 144
#define A_TILE (128 * RB)
#define B_TILE (256 * RB)
#define STAGE_BYTES (A_TILE + B_TILE)
#define NSTAGE 3
#define SMEM_TOTAL (NSTAGE * STAGE_BYTES)

__device__ __forceinline__ void load_stage(
    uint32_t sa, int tid, int row0, int col0,
    const __half* A, const __half* B, int K, int kc, int M) {
#pragma unroll
    for (int j = 0; j < 2; ++j) {        // A: 1024 chunks of 16B
        int id = tid + j * 512;
        int r = id >> 3, c = id & 7;
        int row = row0 + r;
        int szr = (row < M) ? 16 : 0;
        size_t roff = (row < M) ? (size_t)row : 0;
        cp_async16(sa + r * RB + c * 16, A + roff * K + kc + c * 8, szr);
    }
    uint32_t sb = sa + A_TILE;
#pragma unroll
    for (int j = 0; j < 4; ++j) {        // B: 2048 chunks
        int id = tid + j * 512;
        int r = id >> 3, c = id & 7;
        cp_async16(sb + r * RB + c * 16, B + (size_t)(col0 + r) * K + kc + c * 8, 16);
    }
}

// MODE 0: C = A@B(+A1@B1) + bias + resid(fp16) -> LN -> outf(fp32)? / outh(fp16)?
// MODE 1: C = relu(A@B + bias) -> fp16 outh (stride HF)
template <int MODE>
__global__ void __launch_bounds__(512, 1)
gemm_mma(const __half* __restrict__ A0, const __half* __restrict__ B0, int K0,
         const __half* __restrict__ A1, const __half* __restrict__ B1, int K1,
         const float* __restrict__ bias, const __half* __restrict__ resid,
         const float* __restrict__ gamma, const float* __restrict__ beta,
         float* __restrict__ outf, __half* __restrict__ outh, int M,
         int ntX, int ntTotal) {
    extern __shared__ char smem[];
    const uint32_t sb0 = smem_u32(smem);
    const int tid = threadIdx.x;
    const int lane = tid & 31;
    const int warp = tid >> 5;           // 0..15
    const int warpM = warp >> 2;         // 0..3
    const int warpN = warp & 3;          // 0..3

    const int S = (K0 + K1) >> 6;

    const uint32_t aoff = (uint32_t)((warpM * 32 + (lane & 7) + ((lane >> 3) & 1) * 8) * RB
                                     + (lane >> 4) * 16);
    const uint32_t boff4 = (uint32_t)((warpN * 64 + (lane & 7) + (lane >> 4) * 8) * RB
                                      + ((lane >> 3) & 1) * 16);

#define RESOLVE(IT, AH, BH, KK, KC)                             \
    { int kt = (IT) * 64;                                       \
      if (kt < K0) { AH = A0; BH = B0; KK = K0; KC = kt; }      \
      else         { AH = A1; BH = B1; KK = K1; KC = kt - K0; } }

    for (int tile = blockIdx.x; tile < ntTotal; tile += gridDim.x) {
        const int row0 = (tile % ntX) * 128;
        const int col0 = (tile / ntX) * 256;

        float acc[2][8][4];
#pragma unroll
        for (int i = 0; i < 2; ++i)
#pragma unroll
            for (int j = 0; j < 8; ++j)
#pragma unroll
                for (int k = 0; k < 4; ++k) acc[i][j][k] = 0.f;

        __syncthreads();    // protect prior epilogue smem reads from new loads

        // prologue: stages 0,1 (uniform commits)
#pragma unroll
        for (int p = 0; p < 2; ++p) {
            if (p < S) {
                const __half *Ah, *Bh; int KK, KC;
                RESOLVE(p, Ah, Bh, KK, KC);
                load_stage(sb0 + p * STAGE_BYTES, tid, row0, col0, Ah, Bh, KK, KC, M);
            }
            CP_COMMIT();
        }

        int stage = 0;
        for (int it = 0; it < S; ++it) {
            CP_WAIT1();
            __syncthreads();
            if (it + 2 < S) {
                int s2 = stage + 2; if (s2 >= NSTAGE) s2 -= NSTAGE;
                const __half *Ah, *Bh; int KK, KC;
                RESOLVE(it + 2, Ah, Bh, KK, KC);
                load_stage(sb0 + s2 * STAGE_BYTES, tid, row0, col0, Ah, Bh, KK, KC, M);
            }
            CP_COMMIT();

            const uint32_t sa = sb0 + stage * STAGE_BYTES;
            const uint32_t sbB = sa + A_TILE;
#pragma unroll
            for (int ks = 0; ks < 4; ++ks) {
                uint32_t ah[2][4];
#pragma unroll
                for (int tm = 0; tm < 2; ++tm)
                    ldsm_x4(ah[tm], sa + aoff + tm * (16 * RB) + ks * 32);
#pragma unroll
                for (int tnp = 0; tnp < 4; ++tnp) {
                    uint32_t bh[4];
                    ldsm_x4(bh, sbB + boff4 + tnp * (16 * RB) + ks * 32);
#pragma unroll
                    for (int tm = 0; tm < 2; ++tm) {
                        mma_f16(acc[tm][2 * tnp + 0], ah[tm], bh);
                        mma_f16(acc[tm][2 * tnp + 1], ah[tm], bh + 2);
                    }
                }
            }
            ++stage; if (stage == NSTAGE) stage = 0;
        }

        // prefetch epilogue params before final drain
        float rbias = 0.f, rgam = 0.f, rbet = 0.f;
        if (tid < 256) {
            rbias = bias[col0 + tid];
            if (MODE == 0) { rgam = gamma[tid]; rbet = beta[tid]; }
        }

        __syncthreads();

        // ---------------------------- epilogue -----------------------------
        float* rsum  = (float*)smem;          // 128
        float* rsq   = rsum + 128;            // 128
        float* sbias = rsq + 128;             // 256
        float* sgam  = sbias + 256;
        float* sbet  = sgam + 256;
        if (MODE == 0 && tid < 128) { rsum[tid] = 0.f; rsq[tid] = 0.f; }
        if (tid < 256) {
            sbias[tid] = rbias;
            if (MODE == 0) { sgam[tid] = rgam; sbet[tid] = rbet; }
        }
        __syncthreads();

        const int qrow = lane >> 2;
        const int qc = (lane & 3) * 2;

        float vsum[4], vsq[4];
#pragma unroll
        for (int k = 0; k < 4; ++k) { vsum[k] = 0.f; vsq[k] = 0.f; }

#pragma unroll
        for (int tm = 0; tm < 2; ++tm) {
#pragma unroll
            for (int rh = 0; rh < 2; ++rh) {
                int rloc = warpM * 32 + tm * 16 + rh * 8 + qrow;
                int rg = row0 + rloc;
                bool v = rg < M;
#pragma unroll
                for (int tn = 0; tn < 8; ++tn) {
                    int c = warpN * 64 + tn * 8 + qc;
                    float a0 = acc[tm][tn][rh * 2 + 0] + sbias[c];
                    float a1 = acc[tm][tn][rh * 2 + 1] + sbias[c + 1];
                    if (MODE == 0) {
                        if (v) {
                            uint32_t rp = ((const uint32_t*)resid)[((size_t)rg * 256 + c) >> 1];
                            float2 q = __half22float2(*(const __half2*)&rp);
                            a0 += q.x; a1 += q.y;
                        }
                        vsum[tm * 2 + rh] += a0 + a1;
                        vsq[tm * 2 + rh] += a0 * a0 + a1 * a1;
                    } else {
                        a0 = fmaxf(a0, 0.f); a1 = fmaxf(a1, 0.f);
                    }
                    acc[tm][tn][rh * 2 + 0] = a0;
                    acc[tm][tn][rh * 2 + 1] = a1;
                }
            }
        }

        if (MODE == 0) {
#pragma unroll
            for (int k = 0; k < 4; ++k) {
                vsum[k] += __shfl_xor_sync(0xFFFFFFFFu, vsum[k], 1);
                vsum[k] += __shfl_xor_sync(0xFFFFFFFFu, vsum[k], 2);
                vsq[k]  += __shfl_xor_sync(0xFFFFFFFFu, vsq[k], 1);
                vsq[k]  += __shfl_xor_sync(0xFFFFFFFFu, vsq[k], 2);
            }
            if ((lane & 3) == 0) {
#pragma unroll
                for (int tm = 0; tm < 2; ++tm)
#pragma unroll
                    for (int rh = 0; rh < 2; ++rh) {
                        int rloc = warpM * 32 + tm * 16 + rh * 8 + qrow;
                        atomicAdd(&rsum[rloc], vsum[tm * 2 + rh]);
                        atomicAdd(&rsq[rloc], vsq[tm * 2 + rh]);
                    }
            }
            __syncthreads();
        }

#pragma unroll
        for (int tm = 0; tm < 2; ++tm) {
#pragma unroll
            for (int rh = 0; rh < 2; ++rh) {
                int rloc = warpM * 32 + tm * 16 + rh * 8 + qrow;
                int rg = row0 + rloc;
                if (rg >= M) continue;
                float mean = 0.f, inv = 1.f;
                if (MODE == 0) {
                    mean = rsum[rloc] * (1.f / 256.f);
                    inv = rsqrtf(rsq[rloc] * (1.f / 256.f) - mean * mean + 1e-5f);
                }
#pragma unroll
                for (int tn = 0; tn < 8; ++tn) {
                    int c = warpN * 64 + tn * 8 + qc;
                    float a0 = acc[tm][tn][rh * 2 + 0];
                    float a1 = acc[tm][tn][rh * 2 + 1];
                    if (MODE == 0) {
                        a0 = (a0 - mean) * inv * sgam[c] + sbet[c];
                        a1 = (a1 - mean) * inv * sgam[c + 1] + sbet[c + 1];
                        if (outf != nullptr)
                            *(float2*)(outf + (size_t)rg * 256 + c) = make_float2(a0, a1);
                        if (outh != nullptr)
                            ((uint32_t*)outh)[((size_t)rg * 256 + c) >> 1] = packh2(a0, a1);
                    } else {
                        ((uint32_t*)outh)[((size_t)rg * HF + col0 + c) >> 1] = packh2(a0, a1);
                    }
                }
            }
        }
    }
}

// ------------------------------ launch --------------------------------------
extern "C" void kernel_launch(void* const* d_in, const int* in_sizes, int n_in,
                              void* d_out, int out_size) {
    const float* x      = (const float*)d_in[0];
    const int*   ei     = (const int*)d_in[1];
    const float* W_nbr  = (const float*)d_in[2];
    const float* W_root = (const float*)d_in[3];
    const float* b_gnn  = (const float*)d_in[4];
    const float* W1     = (const float*)d_in[5];
    const float* b1     = (const float*)d_in[6];
    const float* W2     = (const float*)d_in[7];
    const float* b2     = (const float*)d_in[8];
    const float* g1     = (const float*)d_in[9];
    const float* be1    = (const float*)d_in[10];
    const float* g2     = (const float*)d_in[11];
    const float* be2    = (const float*)d_in[12];
    float* out = (float*)d_out;

    const int M = in_sizes[0] / HD;
    const int E = in_sizes[1] / 2;

    __half *xh, *agh, *hh, *th, *wnh, *wrh, *w1h, *w2h;
    int *zb, *off, *cur, *srcl;
    cudaGetSymbolAddress((void**)&xh, g_x_h);
    cudaGetSymbolAddress((void**)&agh, g_ag_h);
    cudaGetSymbolAddress((void**)&hh, g_h_h);
    cudaGetSymbolAddress((void**)&th, g_t_h);
    cudaGetSymbolAddress((void**)&wnh, g_wn_h);
    cudaGetSymbolAddress((void**)&wrh, g_wr_h);
    cudaGetSymbolAddress((void**)&w1h, g_w1_h);
    cudaGetSymbolAddress((void**)&w2h, g_w2_h);
    cudaGetSymbolAddress((void**)&zb, g_zb);
    cudaGetSymbolAddress((void**)&off, g_off);
    cudaGetSymbolAddress((void**)&cur, g_cur);
    cudaGetSymbolAddress((void**)&srcl, g_srcl);

    int* deg = zb;
    int nB = (M + SCAN_BLK - 1) / SCAN_BLK;
    int* state = zb + NMAX;

    cudaFuncSetAttribute(gemm_mma<0>, cudaFuncAttributeMaxDynamicSharedMemorySize, SMEM_TOTAL);
    cudaFuncSetAttribute(gemm_mma<1>, cudaFuncAttributeMaxDynamicSharedMemorySize, SMEM_TOTAL);

    // zero deg + lookback state in one node
    cudaMemsetAsync(zb, 0, (NMAX + NBMAX) * sizeof(int));

    int n4 = M * HD / 4;
    int nbConv = (n4 + 255) / 256;
    prep_kernel<<<nbConv + 384, 256>>>(x, xh, W_nbr, wnh, W_root, wrh,
                                       W1, w1h, W2, w2h, n4, nbConv);

    hist_kernel<<<(E / 2 + 255) / 256, 256>>>(ei, E, deg);
    scan_kernel<<<nB, SCAN_BLK>>>(deg, off, cur, state, M);
    fill_kernel<<<(E / 2 + 255) / 256, 256>>>(ei, E, cur, srcl);
    gather_kernel<<<(M + 7) / 8, 256>>>(off, srcl, xh, agh, M);

    int ntX = (M + 127) / 128;              // 391
    int grid0 = ntX < 148 ? ntX : 148;
    int nt1 = ntX * 2;
    int grid1 = nt1 < 148 ? nt1 : 148;

    // hh = fp16 LN1(x + agg@Wnbr + x@Wroot + b_gnn)   (resid = xh fp16)
    gemm_mma<0><<<grid0, 512, SMEM_TOTAL>>>(
        agh, wnh, HD, xh, wrh, HD, b_gnn, xh, g1, be1, nullptr, hh, M, ntX, ntX);

    // th = relu(hh@W1 + b1)
    gemm_mma<1><<<grid1, 512, SMEM_TOTAL>>>(
        hh, w1h, HD, nullptr, nullptr, 0,
        b1, nullptr, nullptr, nullptr, nullptr, th, M, ntX, nt1);

    // out = LN2(hh + th@W2 + b2)  fp32 to d_out  (resid = hh fp16)
    gemm_mma<0><<<grid0, 512, SMEM_TOTAL>>>(
        th, w2h, HF, nullptr, nullptr, 0,
        b2, hh, g2, be2, out, nullptr, M, ntX, ntX);
}

// round 15
// speedup vs baseline: 1.0848x; 1.0021x over previous
#include <cuda_runtime.h>
#include <cuda_fp16.h>
#include <cstdint>

#define HD 256
#define HF 512
#define NMAX 50000
#define EMAX 800000
#define SCAN_BLK 512
#define NBMAX ((NMAX + SCAN_BLK - 1) / SCAN_BLK)

// ------------------------- scratch (device globals) ------------------------
__device__ __half g_x_h[(size_t)NMAX * HD];
__device__ __half g_ag_h[(size_t)NMAX * HD];
__device__ __half g_h_h[(size_t)NMAX * HD];
__device__ __half g_t_h[(size_t)NMAX * HF];
__device__ __half g_wn_h[HD * HD];
__device__ __half g_wr_h[HD * HD];
__device__ __half g_w1_h[HD * HF];
__device__ __half g_w2_h[HD * HF];
__device__ int g_zb[NMAX + NBMAX];   // [0,NMAX)=deg, [NMAX,..)=lookback state
__device__ int g_off[NMAX + 1];
__device__ int g_cur[NMAX];
__device__ int g_srcl[EMAX];

// ----------------------------- helpers -------------------------------------
__device__ __forceinline__ uint32_t smem_u32(const void* p) {
    uint32_t a;
    asm("{ .reg .u64 t; cvta.to.shared.u64 t, %1; cvt.u32.u64 %0, t; }" : "=r"(a) : "l"(p));
    return a;
}
__device__ __forceinline__ void ldsm_x4(uint32_t* r, uint32_t addr) {
    asm volatile("ldmatrix.sync.aligned.m8n8.x4.shared.b16 {%0,%1,%2,%3}, [%4];"
                 : "=r"(r[0]), "=r"(r[1]), "=r"(r[2]), "=r"(r[3]) : "r"(addr));
}
__device__ __forceinline__ void mma_f16(float* d, const uint32_t* a, const uint32_t* b) {
    asm volatile(
        "mma.sync.aligned.m16n8k16.row.col.f32.f16.f16.f32 "
        "{%0,%1,%2,%3}, {%4,%5,%6,%7}, {%8,%9}, {%0,%1,%2,%3};"
        : "+f"(d[0]), "+f"(d[1]), "+f"(d[2]), "+f"(d[3])
        : "r"(a[0]), "r"(a[1]), "r"(a[2]), "r"(a[3]), "r"(b[0]), "r"(b[1]));
}
__device__ __forceinline__ void cp_async16(uint32_t dst, const void* src, int szr) {
    asm volatile("cp.async.cg.shared.global [%0], [%1], 16, %2;"
                 :: "r"(dst), "l"(src), "r"(szr) : "memory");
}
#define CP_COMMIT() asm volatile("cp.async.commit_group;" ::: "memory")
#define CP_WAIT1()  asm volatile("cp.async.wait_group 1;" ::: "memory")

__device__ __forceinline__ uint32_t packh2(float a, float b) {
    __half2 h = __float22half2_rn(make_float2(a, b));
    return *(uint32_t*)&h;
}

// inline int64/int32 edge-dtype detection: all odd words of first 128 pairs zero
__device__ __forceinline__ int detect_is64_block(const int* __restrict__ ei, int E) {
    int lim = 4 * E;
    if (lim > 256) lim = 256;
    int idx = threadIdx.x * 2 + 1;
    int nz = (threadIdx.x < 128 && idx < lim) ? ei[idx] : 0;
    int any = __syncthreads_or(nz != 0);
    return (any == 0) ? 1 : 0;
}

// ------------------ fused prep + histogram kernel ---------------------------
// blocks [0, nbConv): conv x->xh
// blocks [nbConv, nbConv+384): weight transposes
// blocks [nbConv+384, ...): degree histogram (atomic-latency bound; overlaps
//                           with the DRAM-BW-bound conv blocks)
__device__ __forceinline__ void ttrans_tile(const float* W, __half* out,
                                            int K, int N, int kb, int nb,
                                            float (*tile)[33], int tid) {
    int tx = tid & 31, ty = tid >> 5;   // 32 x 8
    int k0 = kb * 32, n0 = nb * 32;
#pragma unroll
    for (int i = 0; i < 4; ++i)
        tile[ty + i * 8][tx] = W[(size_t)(k0 + ty + i * 8) * N + n0 + tx];
    __syncthreads();
#pragma unroll
    for (int i = 0; i < 4; ++i)
        out[(size_t)(n0 + ty + i * 8) * K + k0 + tx] =
            __float2half_rn(tile[tx][ty + i * 8]);
}

__global__ void prep_hist_kernel(
    const float* __restrict__ x, __half* __restrict__ xh,
    const float* __restrict__ Wn, __half* __restrict__ wnh,
    const float* __restrict__ Wr, __half* __restrict__ wrh,
    const float* __restrict__ W1, __half* __restrict__ w1h,
    const float* __restrict__ W2, __half* __restrict__ w2h,
    int n4, int nbConv,
    const int* __restrict__ ei, int E, int* __restrict__ deg) {
    __shared__ float tile[32][33];
    int b = blockIdx.x;
    int tid = threadIdx.x;
    if (b < nbConv) {
        int i = b * 256 + tid;
        if (i < n4) {
            float4 v = ((const float4*)x)[i];
            ((uint2*)xh)[i] = make_uint2(packh2(v.x, v.y), packh2(v.z, v.w));
        }
        return;
    }
    int t = b - nbConv;
    if (t < 384) {
        if (t < 64)        ttrans_tile(Wn, wnh, HD, HD, t & 7, t >> 3, tile, tid);
        else if (t < 128)  { t -= 64;  ttrans_tile(Wr, wrh, HD, HD, t & 7, t >> 3, tile, tid); }
        else if (t < 256)  { t -= 128; ttrans_tile(W1, w1h, HD, HF, t & 7, t >> 3, tile, tid); }
        else               { t -= 256; ttrans_tile(W2, w2h, HF, HD, t & 15, t >> 4, tile, tid); }
        return;
    }
    // ---- histogram segment ----
    int is64 = detect_is64_block(ei, E);
    int tt = (b - nbConv - 384) * 256 + tid;
    if (is64) {
        int e0 = tt * 2;
        if (e0 >= E) return;
        if (e0 + 2 <= E) {
            int4 d = *(const int4*)(ei + 2 * (E + e0));
            atomicAdd(&deg[d.x], 1);
            atomicAdd(&deg[d.z], 1);
        } else {
            atomicAdd(&deg[ei[2 * (E + e0)]], 1);
        }
    } else {
        int e0 = tt * 4;
        if (e0 >= E) return;
        if (e0 + 4 <= E) {
            int4 d = *(const int4*)(ei + E + e0);
            atomicAdd(&deg[d.x], 1);
            atomicAdd(&deg[d.y], 1);
            atomicAdd(&deg[d.z], 1);
            atomicAdd(&deg[d.w], 1);
        } else {
            for (int e = e0; e < E; ++e) atomicAdd(&deg[ei[E + e]], 1);
        }
    }
}

// ---- single-pass decoupled-lookback exclusive scan (nB <= 148 -> 1 wave) ---
#define FLAG_AGG (1 << 30)
#define FLAG_INC (1u << 31)
#define VALMASK  0x3FFFFFFF

__global__ void scan_kernel(const int* __restrict__ deg, int* __restrict__ off,
                            int* __restrict__ cur, int* __restrict__ state, int M) {
    __shared__ int wsum[SCAN_BLK / 32];
    __shared__ int s_pref;
    int b = blockIdx.x;
    int t = threadIdx.x;
    int i = b * SCAN_BLK + t;
    int lane = t & 31, wid = t >> 5;
    int v = (i < M) ? deg[i] : 0;
    int s = v;
#pragma unroll
    for (int o = 1; o < 32; o <<= 1) {
        int u = __shfl_up_sync(0xFFFFFFFFu, s, o);
        if (lane >= o) s += u;
    }
    if (lane == 31) wsum[wid] = s;
    __syncthreads();
    if (wid == 0) {
        int w = (lane < SCAN_BLK / 32) ? wsum[lane] : 0;
#pragma unroll
        for (int o = 1; o < SCAN_BLK / 32; o <<= 1) {
            int u = __shfl_up_sync(0xFFFFFFFFu, w, o);
            if (lane >= o) w += u;
        }
        if (lane < SCAN_BLK / 32) wsum[lane] = w;
    }
    __syncthreads();
    int excl = s - v + (wid ? wsum[wid - 1] : 0);

    if (t == 0) {
        int tot = wsum[SCAN_BLK / 32 - 1];
        if (b == 0) {
            atomicExch(&state[0], (int)(tot | FLAG_INC));
            s_pref = 0;
        } else {
            atomicExch(&state[b], tot | FLAG_AGG);
            int pref = 0, j = b - 1;
            while (true) {
                int st = atomicAdd(&state[j], 0);
                if ((unsigned)st & FLAG_INC) { pref += st & VALMASK; break; }
                if (st & FLAG_AGG)           { pref += st & VALMASK; --j; }
            }
            atomicExch(&state[b], (int)((tot + pref) | FLAG_INC));
            s_pref = pref;
        }
    }
    __syncthreads();
    int base = s_pref + excl;
    if (i < M) { off[i] = base; cur[i] = base; }
    if (i == M - 1) off[M] = base + v;
}

__global__ void fill_kernel(const int* __restrict__ ei, int E,
                            int* __restrict__ cur, int* __restrict__ srcl) {
    int is64 = detect_is64_block(ei, E);
    int t = blockIdx.x * blockDim.x + threadIdx.x;
    if (is64) {
        int e0 = t * 2;
        if (e0 >= E) return;
        if (e0 + 2 <= E) {
            int4 s = *(const int4*)(ei + 2 * e0);
            int4 d = *(const int4*)(ei + 2 * (E + e0));
            srcl[atomicAdd(&cur[d.x], 1)] = s.x;
            srcl[atomicAdd(&cur[d.z], 1)] = s.z;
        } else {
            srcl[atomicAdd(&cur[ei[2 * (E + e0)]], 1)] = ei[2 * e0];
        }
    } else {
        int e0 = t * 4;
        if (e0 >= E) return;
        if (e0 + 4 <= E) {
            int4 s = *(const int4*)(ei + e0);
            int4 d = *(const int4*)(ei + E + e0);
            srcl[atomicAdd(&cur[d.x], 1)] = s.x;
            srcl[atomicAdd(&cur[d.y], 1)] = s.y;
            srcl[atomicAdd(&cur[d.z], 1)] = s.z;
            srcl[atomicAdd(&cur[d.w], 1)] = s.w;
        } else {
            for (int e = e0; e < E; ++e)
                srcl[atomicAdd(&cur[ei[E + e]], 1)] = ei[e];
        }
    }
}

// gather: one warp per node; software-pipelined srcl prefetch; fp16 out
__global__ void __launch_bounds__(256)
gather_kernel(const int* __restrict__ off, const int* __restrict__ srcl,
              const __half* __restrict__ xh, __half* __restrict__ agh, int M) {
    int node = blockIdx.x * 8 + (threadIdx.x >> 5);
    int lane = threadIdx.x & 31;
    if (node >= M) return;
    int j0 = off[node], j1 = off[node + 1];

    float acc[8];
#pragma unroll
    for (int k = 0; k < 8; ++k) acc[k] = 0.f;

    const uint4* xb = (const uint4*)xh;
    int nfull = (j1 - j0) >> 3;
    int srcs[8];
    if (nfull > 0) {
#pragma unroll
        for (int u = 0; u < 8; ++u) srcs[u] = srcl[j0 + u];
    }
    for (int b = 0; b < nfull; ++b) {
        uint4 v[8];
#pragma unroll
        for (int u = 0; u < 8; ++u) v[u] = xb[(size_t)srcs[u] * 32 + lane];
        int nsrcs[8];
        bool more = (b + 1 < nfull);
        if (more) {
            int jn = j0 + (b + 1) * 8;
#pragma unroll
            for (int u = 0; u < 8; ++u) nsrcs[u] = srcl[jn + u];
        }
#pragma unroll
        for (int u = 0; u < 8; ++u) {
            float2 f0 = __half22float2(*(const __half2*)&v[u].x);
            float2 f1 = __half22float2(*(const __half2*)&v[u].y);
            float2 f2 = __half22float2(*(const __half2*)&v[u].z);
            float2 f3 = __half22float2(*(const __half2*)&v[u].w);
            acc[0] += f0.x; acc[1] += f0.y; acc[2] += f1.x; acc[3] += f1.y;
            acc[4] += f2.x; acc[5] += f2.y; acc[6] += f3.x; acc[7] += f3.y;
        }
        if (more) {
#pragma unroll
            for (int u = 0; u < 8; ++u) srcs[u] = nsrcs[u];
        }
    }
    for (int j = j0 + nfull * 8; j < j1; ++j) {
        uint4 v = xb[(size_t)srcl[j] * 32 + lane];
        float2 f0 = __half22float2(*(const __half2*)&v.x);
        float2 f1 = __half22float2(*(const __half2*)&v.y);
        float2 f2 = __half22float2(*(const __half2*)&v.z);
        float2 f3 = __half22float2(*(const __half2*)&v.w);
        acc[0] += f0.x; acc[1] += f0.y; acc[2] += f1.x; acc[3] += f1.y;
        acc[4] += f2.x; acc[5] += f2.y; acc[6] += f3.x; acc[7] += f3.y;
    }

    uint32_t hi[4];
#pragma unroll
    for (int k = 0; k < 4; ++k) hi[k] = packh2(acc[2 * k], acc[2 * k + 1]);
    ((uint4*)agh)[(size_t)node * 32 + lane] = make_uint4(hi[0], hi[1], hi[2], hi[3]);
}

// ----------------------- fp16 mma.sync GEMM (persistent tiles) -------------
// BM=128, BN=256, BK=64, 512 threads, 3-stage cp.async ring (wait_group 1).
// Row = 128B data + 16B pad = 144B (9x16B; 9 = 1 mod 8 -> conflict-free).
#define RB 144
#define A_TILE (128 * RB)
#define B_TILE (256 * RB)
#define STAGE_BYTES (A_TILE + B_TILE)
#define NSTAGE 3
#define SMEM_TOTAL (NSTAGE * STAGE_BYTES)

__device__ __forceinline__ void load_stage(
    uint32_t sa, int tid, int row0, int col0,
    const __half* A, const __half* B, int K, int kc, int M) {
#pragma unroll
    for (int j = 0; j < 2; ++j) {        // A: 1024 chunks of 16B
        int id = tid + j * 512;
        int r = id >> 3, c = id & 7;
        int row = row0 + r;
        int szr = (row < M) ? 16 : 0;
        size_t roff = (row < M) ? (size_t)row : 0;
        cp_async16(sa + r * RB + c * 16, A + roff * K + kc + c * 8, szr);
    }
    uint32_t sb = sa + A_TILE;
#pragma unroll
    for (int j = 0; j < 4; ++j) {        // B: 2048 chunks
        int id = tid + j * 512;
        int r = id >> 3, c = id & 7;
        cp_async16(sb + r * RB + c * 16, B + (size_t)(col0 + r) * K + kc + c * 8, 16);
    }
}

// MODE 0: C = A@B(+A1@B1) + bias + resid(fp16) -> LN -> outf(fp32)? / outh(fp16)?
// MODE 1: C = relu(A@B + bias) -> fp16 outh (stride HF)
template <int MODE>
__global__ void __launch_bounds__(512, 1)
gemm_mma(const __half* __restrict__ A0, const __half* __restrict__ B0, int K0,
         const __half* __restrict__ A1, const __half* __restrict__ B1, int K1,
         const float* __restrict__ bias, const __half* __restrict__ resid,
         const float* __restrict__ gamma, const float* __restrict__ beta,
         float* __restrict__ outf, __half* __restrict__ outh, int M,
         int ntX, int ntTotal) {
    extern __shared__ char smem[];
    const uint32_t sb0 = smem_u32(smem);
    const int tid = threadIdx.x;
    const int lane = tid & 31;
    const int warp = tid >> 5;           // 0..15
    const int warpM = warp >> 2;         // 0..3
    const int warpN = warp & 3;          // 0..3

    const int S = (K0 + K1) >> 6;

    const uint32_t aoff = (uint32_t)((warpM * 32 + (lane & 7) + ((lane >> 3) & 1) * 8) * RB
                                     + (lane >> 4) * 16);
    const uint32_t boff4 = (uint32_t)((warpN * 64 + (lane & 7) + (lane >> 4) * 8) * RB
                                      + ((lane >> 3) & 1) * 16);

#define RESOLVE(IT, AH, BH, KK, KC)                             \
    { int kt = (IT) * 64;                                       \
      if (kt < K0) { AH = A0; BH = B0; KK = K0; KC = kt; }      \
      else         { AH = A1; BH = B1; KK = K1; KC = kt - K0; } }

    for (int tile = blockIdx.x; tile < ntTotal; tile += gridDim.x) {
        const int row0 = (tile % ntX) * 128;
        const int col0 = (tile / ntX) * 256;

        float acc[2][8][4];
#pragma unroll
        for (int i = 0; i < 2; ++i)
#pragma unroll
            for (int j = 0; j < 8; ++j)
#pragma unroll
                for (int k = 0; k < 4; ++k) acc[i][j][k] = 0.f;

        __syncthreads();    // protect prior epilogue smem reads from new loads

        // prologue: stages 0,1 (uniform commits)
#pragma unroll
        for (int p = 0; p < 2; ++p) {
            if (p < S) {
                const __half *Ah, *Bh; int KK, KC;
                RESOLVE(p, Ah, Bh, KK, KC);
                load_stage(sb0 + p * STAGE_BYTES, tid, row0, col0, Ah, Bh, KK, KC, M);
            }
            CP_COMMIT();
        }

        int stage = 0;
        for (int it = 0; it < S; ++it) {
            CP_WAIT1();
            __syncthreads();
            if (it + 2 < S) {
                int s2 = stage + 2; if (s2 >= NSTAGE) s2 -= NSTAGE;
                const __half *Ah, *Bh; int KK, KC;
                RESOLVE(it + 2, Ah, Bh, KK, KC);
                load_stage(sb0 + s2 * STAGE_BYTES, tid, row0, col0, Ah, Bh, KK, KC, M);
            }
            CP_COMMIT();

            const uint32_t sa = sb0 + stage * STAGE_BYTES;
            const uint32_t sbB = sa + A_TILE;
#pragma unroll
            for (int ks = 0; ks < 4; ++ks) {
                uint32_t ah[2][4];
#pragma unroll
                for (int tm = 0; tm < 2; ++tm)
                    ldsm_x4(ah[tm], sa + aoff + tm * (16 * RB) + ks * 32);
#pragma unroll
                for (int tnp = 0; tnp < 4; ++tnp) {
                    uint32_t bh[4];
                    ldsm_x4(bh, sbB + boff4 + tnp * (16 * RB) + ks * 32);
#pragma unroll
                    for (int tm = 0; tm < 2; ++tm) {
                        mma_f16(acc[tm][2 * tnp + 0], ah[tm], bh);
                        mma_f16(acc[tm][2 * tnp + 1], ah[tm], bh + 2);
                    }
                }
            }
            ++stage; if (stage == NSTAGE) stage = 0;
        }

        // prefetch epilogue params before final drain
        float rbias = 0.f, rgam = 0.f, rbet = 0.f;
        if (tid < 256) {
            rbias = bias[col0 + tid];
            if (MODE == 0) { rgam = gamma[tid]; rbet = beta[tid]; }
        }

        __syncthreads();

        // ---------------------------- epilogue -----------------------------
        float* rsum  = (float*)smem;          // 128
        float* rsq   = rsum + 128;            // 128
        float* sbias = rsq + 128;             // 256
        float* sgam  = sbias + 256;
        float* sbet  = sgam + 256;
        if (MODE == 0 && tid < 128) { rsum[tid] = 0.f; rsq[tid] = 0.f; }
        if (tid < 256) {
            sbias[tid] = rbias;
            if (MODE == 0) { sgam[tid] = rgam; sbet[tid] = rbet; }
        }
        __syncthreads();

        const int qrow = lane >> 2;
        const int qc = (lane & 3) * 2;

        float vsum[4], vsq[4];
#pragma unroll
        for (int k = 0; k < 4; ++k) { vsum[k] = 0.f; vsq[k] = 0.f; }

#pragma unroll
        for (int tm = 0; tm < 2; ++tm) {
#pragma unroll
            for (int rh = 0; rh < 2; ++rh) {
                int rloc = warpM * 32 + tm * 16 + rh * 8 + qrow;
                int rg = row0 + rloc;
                bool v = rg < M;
#pragma unroll
                for (int tn = 0; tn < 8; ++tn) {
                    int c = warpN * 64 + tn * 8 + qc;
                    float a0 = acc[tm][tn][rh * 2 + 0] + sbias[c];
                    float a1 = acc[tm][tn][rh * 2 + 1] + sbias[c + 1];
                    if (MODE == 0) {
                        if (v) {
                            uint32_t rp = ((const uint32_t*)resid)[((size_t)rg * 256 + c) >> 1];
                            float2 q = __half22float2(*(const __half2*)&rp);
                            a0 += q.x; a1 += q.y;
                        }
                        vsum[tm * 2 + rh] += a0 + a1;
                        vsq[tm * 2 + rh] += a0 * a0 + a1 * a1;
                    } else {
                        a0 = fmaxf(a0, 0.f); a1 = fmaxf(a1, 0.f);
                    }
                    acc[tm][tn][rh * 2 + 0] = a0;
                    acc[tm][tn][rh * 2 + 1] = a1;
                }
            }
        }

        if (MODE == 0) {
#pragma unroll
            for (int k = 0; k < 4; ++k) {
                vsum[k] += __shfl_xor_sync(0xFFFFFFFFu, vsum[k], 1);
                vsum[k] += __shfl_xor_sync(0xFFFFFFFFu, vsum[k], 2);
                vsq[k]  += __shfl_xor_sync(0xFFFFFFFFu, vsq[k], 1);
                vsq[k]  += __shfl_xor_sync(0xFFFFFFFFu, vsq[k], 2);
            }
            if ((lane & 3) == 0) {
#pragma unroll
                for (int tm = 0; tm < 2; ++tm)
#pragma unroll
                    for (int rh = 0; rh < 2; ++rh) {
                        int rloc = warpM * 32 + tm * 16 + rh * 8 + qrow;
                        atomicAdd(&rsum[rloc], vsum[tm * 2 + rh]);
                        atomicAdd(&rsq[rloc], vsq[tm * 2 + rh]);
                    }
            }
            __syncthreads();
        }

#pragma unroll
        for (int tm = 0; tm < 2; ++tm) {
#pragma unroll
            for (int rh = 0; rh < 2; ++rh) {
                int rloc = warpM * 32 + tm * 16 + rh * 8 + qrow;
                int rg = row0 + rloc;
                if (rg >= M) continue;
                float mean = 0.f, inv = 1.f;
                if (MODE == 0) {
                    mean = rsum[rloc] * (1.f / 256.f);
                    inv = rsqrtf(rsq[rloc] * (1.f / 256.f) - mean * mean + 1e-5f);
                }
#pragma unroll
                for (int tn = 0; tn < 8; ++tn) {
                    int c = warpN * 64 + tn * 8 + qc;
                    float a0 = acc[tm][tn][rh * 2 + 0];
                    float a1 = acc[tm][tn][rh * 2 + 1];
                    if (MODE == 0) {
                        a0 = (a0 - mean) * inv * sgam[c] + sbet[c];
                        a1 = (a1 - mean) * inv * sgam[c + 1] + sbet[c + 1];
                        if (outf != nullptr)
                            *(float2*)(outf + (size_t)rg * 256 + c) = make_float2(a0, a1);
                        if (outh != nullptr)
                            ((uint32_t*)outh)[((size_t)rg * 256 + c) >> 1] = packh2(a0, a1);
                    } else {
                        ((uint32_t*)outh)[((size_t)rg * HF + col0 + c) >> 1] = packh2(a0, a1);
                    }
                }
            }
        }
    }
}

// ------------------------------ launch --------------------------------------
extern "C" void kernel_launch(void* const* d_in, const int* in_sizes, int n_in,
                              void* d_out, int out_size) {
    const float* x      = (const float*)d_in[0];
    const int*   ei     = (const int*)d_in[1];
    const float* W_nbr  = (const float*)d_in[2];
    const float* W_root = (const float*)d_in[3];
    const float* b_gnn  = (const float*)d_in[4];
    const float* W1     = (const float*)d_in[5];
    const float* b1     = (const float*)d_in[6];
    const float* W2     = (const float*)d_in[7];
    const float* b2     = (const float*)d_in[8];
    const float* g1     = (const float*)d_in[9];
    const float* be1    = (const float*)d_in[10];
    const float* g2     = (const float*)d_in[11];
    const float* be2    = (const float*)d_in[12];
    float* out = (float*)d_out;

    const int M = in_sizes[0] / HD;
    const int E = in_sizes[1] / 2;

    __half *xh, *agh, *hh, *th, *wnh, *wrh, *w1h, *w2h;
    int *zb, *off, *cur, *srcl;
    cudaGetSymbolAddress((void**)&xh, g_x_h);
    cudaGetSymbolAddress((void**)&agh, g_ag_h);
    cudaGetSymbolAddress((void**)&hh, g_h_h);
    cudaGetSymbolAddress((void**)&th, g_t_h);
    cudaGetSymbolAddress((void**)&wnh, g_wn_h);
    cudaGetSymbolAddress((void**)&wrh, g_wr_h);
    cudaGetSymbolAddress((void**)&w1h, g_w1_h);
    cudaGetSymbolAddress((void**)&w2h, g_w2_h);
    cudaGetSymbolAddress((void**)&zb, g_zb);
    cudaGetSymbolAddress((void**)&off, g_off);
    cudaGetSymbolAddress((void**)&cur, g_cur);
    cudaGetSymbolAddress((void**)&srcl, g_srcl);

    int* deg = zb;
    int nB = (M + SCAN_BLK - 1) / SCAN_BLK;
    int* state = zb + NMAX;

    cudaFuncSetAttribute(gemm_mma<0>, cudaFuncAttributeMaxDynamicSharedMemorySize, SMEM_TOTAL);
    cudaFuncSetAttribute(gemm_mma<1>, cudaFuncAttributeMaxDynamicSharedMemorySize, SMEM_TOTAL);

    // zero deg + lookback state in one node
    cudaMemsetAsync(zb, 0, (NMAX + NBMAX) * sizeof(int));

    int n4 = M * HD / 4;
    int nbConv = (n4 + 255) / 256;
    int nbHist = (E / 2 + 255) / 256;

    // fused: conv + weight transposes + degree histogram (independent work)
    prep_hist_kernel<<<nbConv + 384 + nbHist, 256>>>(
        x, xh, W_nbr, wnh, W_root, wrh, W1, w1h, W2, w2h,
        n4, nbConv, ei, E, deg);

    scan_kernel<<<nB, SCAN_BLK>>>(deg, off, cur, state, M);
    fill_kernel<<<nbHist, 256>>>(ei, E, cur, srcl);
    gather_kernel<<<(M + 7) / 8, 256>>>(off, srcl, xh, agh, M);

    int ntX = (M + 127) / 128;              // 391
    int grid0 = ntX < 148 ? ntX : 148;
    int nt1 = ntX * 2;
    int grid1 = nt1 < 148 ? nt1 : 148;

    // hh = fp16 LN1(x + agg@Wnbr + x@Wroot + b_gnn)   (resid = xh fp16)
    gemm_mma<0><<<grid0, 512, SMEM_TOTAL>>>(
        agh, wnh, HD, xh, wrh, HD, b_gnn, xh, g1, be1, nullptr, hh, M, ntX, ntX);

    // th = relu(hh@W1 + b1)
    gemm_mma<1><<<grid1, 512, SMEM_TOTAL>>>(
        hh, w1h, HD, nullptr, nullptr, 0,
        b1, nullptr, nullptr, nullptr, nullptr, th, M, ntX, nt1);

    // out = LN2(hh + th@W2 + b2)  fp32 to d_out  (resid = hh fp16)
    gemm_mma<0><<<grid0, 512, SMEM_TOTAL>>>(
        th, w2h, HF, nullptr, nullptr, 0,
        b2, hh, g2, be2, out, nullptr, M, ntX, ntX);
}

// round 16
// speedup vs baseline: 1.0868x; 1.0018x over previous
#include <cuda_runtime.h>
#include <cuda_fp16.h>
#include <cstdint>

#define HD 256
#define HF 512
#define NMAX 50000
#define EMAX 800000
#define SCAN_BLK 512
#define NBMAX ((NMAX + SCAN_BLK - 1) / SCAN_BLK)

// ------------------------- scratch (device globals) ------------------------
__device__ __half g_x_h[(size_t)NMAX * HD];
__device__ __half g_ag_h[(size_t)NMAX * HD];
__device__ __half g_h_h[(size_t)NMAX * HD];
__device__ __half g_t_h[(size_t)NMAX * HF];
__device__ __half g_wn_h[HD * HD];
__device__ __half g_wr_h[HD * HD];
__device__ __half g_w1_h[HD * HF];
__device__ __half g_w2_h[HD * HF];
__device__ int g_zb[NMAX + NBMAX];   // [0,NMAX)=deg, [NMAX,..)=lookback state
__device__ int g_off[NMAX + 1];
__device__ int g_cur[NMAX];
__device__ int g_srcl[EMAX];

// ----------------------------- helpers -------------------------------------
__device__ __forceinline__ uint32_t smem_u32(const void* p) {
    uint32_t a;
    asm("{ .reg .u64 t; cvta.to.shared.u64 t, %1; cvt.u32.u64 %0, t; }" : "=r"(a) : "l"(p));
    return a;
}
__device__ __forceinline__ void ldsm_x4(uint32_t* r, uint32_t addr) {
    asm volatile("ldmatrix.sync.aligned.m8n8.x4.shared.b16 {%0,%1,%2,%3}, [%4];"
                 : "=r"(r[0]), "=r"(r[1]), "=r"(r[2]), "=r"(r[3]) : "r"(addr));
}
__device__ __forceinline__ void mma_f16(float* d, const uint32_t* a, const uint32_t* b) {
    asm volatile(
        "mma.sync.aligned.m16n8k16.row.col.f32.f16.f16.f32 "
        "{%0,%1,%2,%3}, {%4,%5,%6,%7}, {%8,%9}, {%0,%1,%2,%3};"
        : "+f"(d[0]), "+f"(d[1]), "+f"(d[2]), "+f"(d[3])
        : "r"(a[0]), "r"(a[1]), "r"(a[2]), "r"(a[3]), "r"(b[0]), "r"(b[1]));
}
__device__ __forceinline__ void cp_async16(uint32_t dst, const void* src, int szr) {
    asm volatile("cp.async.cg.shared.global [%0], [%1], 16, %2;"
                 :: "r"(dst), "l"(src), "r"(szr) : "memory");
}
#define CP_COMMIT() asm volatile("cp.async.commit_group;" ::: "memory")
#define CP_WAIT1()  asm volatile("cp.async.wait_group 1;" ::: "memory")

__device__ __forceinline__ uint32_t packh2(float a, float b) {
    __half2 h = __float22half2_rn(make_float2(a, b));
    return *(uint32_t*)&h;
}

// inline int64/int32 edge-dtype detection: all odd words of first 128 pairs zero
__device__ __forceinline__ int detect_is64_block(const int* __restrict__ ei, int E) {
    int lim = 4 * E;
    if (lim > 256) lim = 256;
    int idx = threadIdx.x * 2 + 1;
    int nz = (threadIdx.x < 128 && idx < lim) ? ei[idx] : 0;
    int any = __syncthreads_or(nz != 0);
    return (any == 0) ? 1 : 0;
}

// ------------------ fused prep + histogram kernel ---------------------------
__device__ __forceinline__ void ttrans_tile(const float* W, __half* out,
                                            int K, int N, int kb, int nb,
                                            float (*tile)[33], int tid) {
    int tx = tid & 31, ty = tid >> 5;   // 32 x 8
    int k0 = kb * 32, n0 = nb * 32;
#pragma unroll
    for (int i = 0; i < 4; ++i)
        tile[ty + i * 8][tx] = W[(size_t)(k0 + ty + i * 8) * N + n0 + tx];
    __syncthreads();
#pragma unroll
    for (int i = 0; i < 4; ++i)
        out[(size_t)(n0 + ty + i * 8) * K + k0 + tx] =
            __float2half_rn(tile[tx][ty + i * 8]);
}

__global__ void prep_hist_kernel(
    const float* __restrict__ x, __half* __restrict__ xh,
    const float* __restrict__ Wn, __half* __restrict__ wnh,
    const float* __restrict__ Wr, __half* __restrict__ wrh,
    const float* __restrict__ W1, __half* __restrict__ w1h,
    const float* __restrict__ W2, __half* __restrict__ w2h,
    int n4, int nbConv,
    const int* __restrict__ ei, int E, int* __restrict__ deg) {
    __shared__ float tile[32][33];
    int b = blockIdx.x;
    int tid = threadIdx.x;
    if (b < nbConv) {
        int i = b * 256 + tid;
        if (i < n4) {
            float4 v = ((const float4*)x)[i];
            ((uint2*)xh)[i] = make_uint2(packh2(v.x, v.y), packh2(v.z, v.w));
        }
        return;
    }
    int t = b - nbConv;
    if (t < 384) {
        if (t < 64)        ttrans_tile(Wn, wnh, HD, HD, t & 7, t >> 3, tile, tid);
        else if (t < 128)  { t -= 64;  ttrans_tile(Wr, wrh, HD, HD, t & 7, t >> 3, tile, tid); }
        else if (t < 256)  { t -= 128; ttrans_tile(W1, w1h, HD, HF, t & 7, t >> 3, tile, tid); }
        else               { t -= 256; ttrans_tile(W2, w2h, HF, HD, t & 15, t >> 4, tile, tid); }
        return;
    }
    // ---- histogram segment ----
    int is64 = detect_is64_block(ei, E);
    int tt = (b - nbConv - 384) * 256 + tid;
    if (is64) {
        int e0 = tt * 2;
        if (e0 >= E) return;
        if (e0 + 2 <= E) {
            int4 d = *(const int4*)(ei + 2 * (E + e0));
            atomicAdd(&deg[d.x], 1);
            atomicAdd(&deg[d.z], 1);
        } else {
            atomicAdd(&deg[ei[2 * (E + e0)]], 1);
        }
    } else {
        int e0 = tt * 4;
        if (e0 >= E) return;
        if (e0 + 4 <= E) {
            int4 d = *(const int4*)(ei + E + e0);
            atomicAdd(&deg[d.x], 1);
            atomicAdd(&deg[d.y], 1);
            atomicAdd(&deg[d.z], 1);
            atomicAdd(&deg[d.w], 1);
        } else {
            for (int e = e0; e < E; ++e) atomicAdd(&deg[ei[E + e]], 1);
        }
    }
}

// ---- single-pass decoupled-lookback exclusive scan (nB <= 148 -> 1 wave) ---
#define FLAG_AGG (1 << 30)
#define FLAG_INC (1u << 31)
#define VALMASK  0x3FFFFFFF

__global__ void scan_kernel(const int* __restrict__ deg, int* __restrict__ off,
                            int* __restrict__ cur, int* __restrict__ state, int M) {
    __shared__ int wsum[SCAN_BLK / 32];
    __shared__ int s_pref;
    int b = blockIdx.x;
    int t = threadIdx.x;
    int i = b * SCAN_BLK + t;
    int lane = t & 31, wid = t >> 5;
    int v = (i < M) ? deg[i] : 0;
    int s = v;
#pragma unroll
    for (int o = 1; o < 32; o <<= 1) {
        int u = __shfl_up_sync(0xFFFFFFFFu, s, o);
        if (lane >= o) s += u;
    }
    if (lane == 31) wsum[wid] = s;
    __syncthreads();
    if (wid == 0) {
        int w = (lane < SCAN_BLK / 32) ? wsum[lane] : 0;
#pragma unroll
        for (int o = 1; o < SCAN_BLK / 32; o <<= 1) {
            int u = __shfl_up_sync(0xFFFFFFFFu, w, o);
            if (lane >= o) w += u;
        }
        if (lane < SCAN_BLK / 32) wsum[lane] = w;
    }
    __syncthreads();
    int excl = s - v + (wid ? wsum[wid - 1] : 0);

    if (t == 0) {
        int tot = wsum[SCAN_BLK / 32 - 1];
        if (b == 0) {
            atomicExch(&state[0], (int)(tot | FLAG_INC));
            s_pref = 0;
        } else {
            atomicExch(&state[b], tot | FLAG_AGG);
            int pref = 0, j = b - 1;
            while (true) {
                int st = atomicAdd(&state[j], 0);
                if ((unsigned)st & FLAG_INC) { pref += st & VALMASK; break; }
                if (st & FLAG_AGG)           { pref += st & VALMASK; --j; }
            }
            atomicExch(&state[b], (int)((tot + pref) | FLAG_INC));
            s_pref = pref;
        }
    }
    __syncthreads();
    int base = s_pref + excl;
    if (i < M) { off[i] = base; cur[i] = base; }
    if (i == M - 1) off[M] = base + v;
}

__global__ void fill_kernel(const int* __restrict__ ei, int E,
                            int* __restrict__ cur, int* __restrict__ srcl) {
    int is64 = detect_is64_block(ei, E);
    int t = blockIdx.x * blockDim.x + threadIdx.x;
    if (is64) {
        int e0 = t * 2;
        if (e0 >= E) return;
        if (e0 + 2 <= E) {
            int4 s = *(const int4*)(ei + 2 * e0);
            int4 d = *(const int4*)(ei + 2 * (E + e0));
            srcl[atomicAdd(&cur[d.x], 1)] = s.x;
            srcl[atomicAdd(&cur[d.z], 1)] = s.z;
        } else {
            srcl[atomicAdd(&cur[ei[2 * (E + e0)]], 1)] = ei[2 * e0];
        }
    } else {
        int e0 = t * 4;
        if (e0 >= E) return;
        if (e0 + 4 <= E) {
            int4 s = *(const int4*)(ei + e0);
            int4 d = *(const int4*)(ei + E + e0);
            srcl[atomicAdd(&cur[d.x], 1)] = s.x;
            srcl[atomicAdd(&cur[d.y], 1)] = s.y;
            srcl[atomicAdd(&cur[d.z], 1)] = s.z;
            srcl[atomicAdd(&cur[d.w], 1)] = s.w;
        } else {
            for (int e = e0; e < E; ++e)
                srcl[atomicAdd(&cur[ei[E + e]], 1)] = ei[e];
        }
    }
}

// gather: one warp per node; pipelined srcl prefetch; pairwise HADD2
// pre-reduction (2 neighbors per fp16 add) then fp32 accumulate.
__global__ void __launch_bounds__(256)
gather_kernel(const int* __restrict__ off, const int* __restrict__ srcl,
              const __half* __restrict__ xh, __half* __restrict__ agh, int M) {
    int node = blockIdx.x * 8 + (threadIdx.x >> 5);
    int lane = threadIdx.x & 31;
    if (node >= M) return;
    int j0 = off[node], j1 = off[node + 1];

    float acc[8];
#pragma unroll
    for (int k = 0; k < 8; ++k) acc[k] = 0.f;

    const uint4* xb = (const uint4*)xh;
    int nfull = (j1 - j0) >> 3;
    int srcs[8];
    if (nfull > 0) {
#pragma unroll
        for (int u = 0; u < 8; ++u) srcs[u] = srcl[j0 + u];
    }
    for (int b = 0; b < nfull; ++b) {
        uint4 v[8];
#pragma unroll
        for (int u = 0; u < 8; ++u) v[u] = xb[(size_t)srcs[u] * 32 + lane];
        int nsrcs[8];
        bool more = (b + 1 < nfull);
        if (more) {
            int jn = j0 + (b + 1) * 8;
#pragma unroll
            for (int u = 0; u < 8; ++u) nsrcs[u] = srcl[jn + u];
        }
#pragma unroll
        for (int u = 0; u < 8; u += 2) {
            const __half2* pa = (const __half2*)&v[u];
            const __half2* pb = (const __half2*)&v[u + 1];
#pragma unroll
            for (int w = 0; w < 4; ++w) {
                float2 f = __half22float2(__hadd2(pa[w], pb[w]));
                acc[2 * w]     += f.x;
                acc[2 * w + 1] += f.y;
            }
        }
        if (more) {
#pragma unroll
            for (int u = 0; u < 8; ++u) srcs[u] = nsrcs[u];
        }
    }
    for (int j = j0 + nfull * 8; j < j1; ++j) {
        uint4 v = xb[(size_t)srcl[j] * 32 + lane];
        float2 f0 = __half22float2(*(const __half2*)&v.x);
        float2 f1 = __half22float2(*(const __half2*)&v.y);
        float2 f2 = __half22float2(*(const __half2*)&v.z);
        float2 f3 = __half22float2(*(const __half2*)&v.w);
        acc[0] += f0.x; acc[1] += f0.y; acc[2] += f1.x; acc[3] += f1.y;
        acc[4] += f2.x; acc[5] += f2.y; acc[6] += f3.x; acc[7] += f3.y;
    }

    uint32_t hi[4];
#pragma unroll
    for (int k = 0; k < 4; ++k) hi[k] = packh2(acc[2 * k], acc[2 * k + 1]);
    ((uint4*)agh)[(size_t)node * 32 + lane] = make_uint4(hi[0], hi[1], hi[2], hi[3]);
}

// ----------------------- fp16 mma.sync GEMM (persistent tiles) -------------
// BM=128, BN=256, BK=64, 512 threads, 3-stage cp.async ring (wait_group 1).
// Row = 128B data + 16B pad = 144B (9x16B; 9 = 1 mod 8 -> conflict-free).
#define RB 144
#define A_TILE (128 * RB)
#define B_TILE (256 * RB)
#define STAGE_BYTES (A_TILE + B_TILE)
#define NSTAGE 3
#define SMEM_TOTAL (NSTAGE * STAGE_BYTES)

__device__ __forceinline__ void load_stage(
    uint32_t sa, int tid, int row0, int col0,
    const __half* A, const __half* B, int K, int kc, int M) {
#pragma unroll
    for (int j = 0; j < 2; ++j) {        // A: 1024 chunks of 16B
        int id = tid + j * 512;
        int r = id >> 3, c = id & 7;
        int row = row0 + r;
        int szr = (row < M) ? 16 : 0;
        size_t roff = (row < M) ? (size_t)row : 0;
        cp_async16(sa + r * RB + c * 16, A + roff * K + kc + c * 8, szr);
    }
    uint32_t sb = sa + A_TILE;
#pragma unroll
    for (int j = 0; j < 4; ++j) {        // B: 2048 chunks
        int id = tid + j * 512;
        int r = id >> 3, c = id & 7;
        cp_async16(sb + r * RB + c * 16, B + (size_t)(col0 + r) * K + kc + c * 8, 16);
    }
}

// MODE 0: C = A@B(+A1@B1) + bias + resid(fp16) -> LN -> outf(fp32)? / outh(fp16)?
// MODE 1: C = relu(A@B + bias) -> fp16 outh (stride HF)
template <int MODE>
__global__ void __launch_bounds__(512, 1)
gemm_mma(const __half* __restrict__ A0, const __half* __restrict__ B0, int K0,
         const __half* __restrict__ A1, const __half* __restrict__ B1, int K1,
         const float* __restrict__ bias, const __half* __restrict__ resid,
         const float* __restrict__ gamma, const float* __restrict__ beta,
         float* __restrict__ outf, __half* __restrict__ outh, int M,
         int ntX, int ntTotal) {
    extern __shared__ char smem[];
    const uint32_t sb0 = smem_u32(smem);
    const int tid = threadIdx.x;
    const int lane = tid & 31;
    const int warp = tid >> 5;           // 0..15
    const int warpM = warp >> 2;         // 0..3
    const int warpN = warp & 3;          // 0..3

    const int S = (K0 + K1) >> 6;

    const uint32_t aoff = (uint32_t)((warpM * 32 + (lane & 7) + ((lane >> 3) & 1) * 8) * RB
                                     + (lane >> 4) * 16);
    const uint32_t boff4 = (uint32_t)((warpN * 64 + (lane & 7) + (lane >> 4) * 8) * RB
                                      + ((lane >> 3) & 1) * 16);

#define RESOLVE(IT, AH, BH, KK, KC)                             \
    { int kt = (IT) * 64;                                       \
      if (kt < K0) { AH = A0; BH = B0; KK = K0; KC = kt; }      \
      else         { AH = A1; BH = B1; KK = K1; KC = kt - K0; } }

    for (int tile = blockIdx.x; tile < ntTotal; tile += gridDim.x) {
        const int row0 = (tile % ntX) * 128;
        const int col0 = (tile / ntX) * 256;

        float acc[2][8][4];
#pragma unroll
        for (int i = 0; i < 2; ++i)
#pragma unroll
            for (int j = 0; j < 8; ++j)
#pragma unroll
                for (int k = 0; k < 4; ++k) acc[i][j][k] = 0.f;

        __syncthreads();    // protect prior epilogue smem reads from new loads

        // prologue: stages 0,1 (uniform commits)
#pragma unroll
        for (int p = 0; p < 2; ++p) {
            if (p < S) {
                const __half *Ah, *Bh; int KK, KC;
                RESOLVE(p, Ah, Bh, KK, KC);
                load_stage(sb0 + p * STAGE_BYTES, tid, row0, col0, Ah, Bh, KK, KC, M);
            }
            CP_COMMIT();
        }

        int stage = 0;
        for (int it = 0; it < S; ++it) {
            CP_WAIT1();
            __syncthreads();
            if (it + 2 < S) {
                int s2 = stage + 2; if (s2 >= NSTAGE) s2 -= NSTAGE;
                const __half *Ah, *Bh; int KK, KC;
                RESOLVE(it + 2, Ah, Bh, KK, KC);
                load_stage(sb0 + s2 * STAGE_BYTES, tid, row0, col0, Ah, Bh, KK, KC, M);
            }
            CP_COMMIT();

            const uint32_t sa = sb0 + stage * STAGE_BYTES;
            const uint32_t sbB = sa + A_TILE;
#pragma unroll
            for (int ks = 0; ks < 4; ++ks) {
                uint32_t ah[2][4];
#pragma unroll
                for (int tm = 0; tm < 2; ++tm)
                    ldsm_x4(ah[tm], sa + aoff + tm * (16 * RB) + ks * 32);
#pragma unroll
                for (int tnp = 0; tnp < 4; ++tnp) {
                    uint32_t bh[4];
                    ldsm_x4(bh, sbB + boff4 + tnp * (16 * RB) + ks * 32);
#pragma unroll
                    for (int tm = 0; tm < 2; ++tm) {
                        mma_f16(acc[tm][2 * tnp + 0], ah[tm], bh);
                        mma_f16(acc[tm][2 * tnp + 1], ah[tm], bh + 2);
                    }
                }
            }
            ++stage; if (stage == NSTAGE) stage = 0;
        }

        // prefetch epilogue params before final drain
        float rbias = 0.f, rgam = 0.f, rbet = 0.f;
        if (tid < 256) {
            rbias = bias[col0 + tid];
            if (MODE == 0) { rgam = gamma[tid]; rbet = beta[tid]; }
        }

        __syncthreads();

        // ---------------------------- epilogue -----------------------------
        float* rsum  = (float*)smem;          // 128
        float* rsq   = rsum + 128;            // 128
        float* sbias = rsq + 128;             // 256
        float* sgam  = sbias + 256;
        float* sbet  = sgam + 256;
        if (MODE == 0 && tid < 128) { rsum[tid] = 0.f; rsq[tid] = 0.f; }
        if (tid < 256) {
            sbias[tid] = rbias;
            if (MODE == 0) { sgam[tid] = rgam; sbet[tid] = rbet; }
        }
        __syncthreads();

        const int qrow = lane >> 2;
        const int qc = (lane & 3) * 2;

        float vsum[4], vsq[4];
#pragma unroll
        for (int k = 0; k < 4; ++k) { vsum[k] = 0.f; vsq[k] = 0.f; }

#pragma unroll
        for (int tm = 0; tm < 2; ++tm) {
#pragma unroll
            for (int rh = 0; rh < 2; ++rh) {
                int rloc = warpM * 32 + tm * 16 + rh * 8 + qrow;
                int rg = row0 + rloc;
                bool v = rg < M;
#pragma unroll
                for (int tn = 0; tn < 8; ++tn) {
                    int c = warpN * 64 + tn * 8 + qc;
                    float a0 = acc[tm][tn][rh * 2 + 0] + sbias[c];
                    float a1 = acc[tm][tn][rh * 2 + 1] + sbias[c + 1];
                    if (MODE == 0) {
                        if (v) {
                            uint32_t rp = ((const uint32_t*)resid)[((size_t)rg * 256 + c) >> 1];
                            float2 q = __half22float2(*(const __half2*)&rp);
                            a0 += q.x; a1 += q.y;
                        }
                        vsum[tm * 2 + rh] += a0 + a1;
                        vsq[tm * 2 + rh] += a0 * a0 + a1 * a1;
                    } else {
                        a0 = fmaxf(a0, 0.f); a1 = fmaxf(a1, 0.f);
                    }
                    acc[tm][tn][rh * 2 + 0] = a0;
                    acc[tm][tn][rh * 2 + 1] = a1;
                }
            }
        }

        if (MODE == 0) {
#pragma unroll
            for (int k = 0; k < 4; ++k) {
                vsum[k] += __shfl_xor_sync(0xFFFFFFFFu, vsum[k], 1);
                vsum[k] += __shfl_xor_sync(0xFFFFFFFFu, vsum[k], 2);
                vsq[k]  += __shfl_xor_sync(0xFFFFFFFFu, vsq[k], 1);
                vsq[k]  += __shfl_xor_sync(0xFFFFFFFFu, vsq[k], 2);
            }
            if ((lane & 3) == 0) {
#pragma unroll
                for (int tm = 0; tm < 2; ++tm)
#pragma unroll
                    for (int rh = 0; rh < 2; ++rh) {
                        int rloc = warpM * 32 + tm * 16 + rh * 8 + qrow;
                        atomicAdd(&rsum[rloc], vsum[tm * 2 + rh]);
                        atomicAdd(&rsq[rloc], vsq[tm * 2 + rh]);
                    }
            }
            __syncthreads();
        }

#pragma unroll
        for (int tm = 0; tm < 2; ++tm) {
#pragma unroll
            for (int rh = 0; rh < 2; ++rh) {
                int rloc = warpM * 32 + tm * 16 + rh * 8 + qrow;
                int rg = row0 + rloc;
                if (rg >= M) continue;
                float mean = 0.f, inv = 1.f;
                if (MODE == 0) {
                    mean = rsum[rloc] * (1.f / 256.f);
                    inv = rsqrtf(rsq[rloc] * (1.f / 256.f) - mean * mean + 1e-5f);
                }
#pragma unroll
                for (int tn = 0; tn < 8; ++tn) {
                    int c = warpN * 64 + tn * 8 + qc;
                    float a0 = acc[tm][tn][rh * 2 + 0];
                    float a1 = acc[tm][tn][rh * 2 + 1];
                    if (MODE == 0) {
                        a0 = (a0 - mean) * inv * sgam[c] + sbet[c];
                        a1 = (a1 - mean) * inv * sgam[c + 1] + sbet[c + 1];
                        if (outf != nullptr)
                            *(float2*)(outf + (size_t)rg * 256 + c) = make_float2(a0, a1);
                        if (outh != nullptr)
                            ((uint32_t*)outh)[((size_t)rg * 256 + c) >> 1] = packh2(a0, a1);
                    } else {
                        ((uint32_t*)outh)[((size_t)rg * HF + col0 + c) >> 1] = packh2(a0, a1);
                    }
                }
            }
        }
    }
}

// ------------------------------ launch --------------------------------------
extern "C" void kernel_launch(void* const* d_in, const int* in_sizes, int n_in,
                              void* d_out, int out_size) {
    const float* x      = (const float*)d_in[0];
    const int*   ei     = (const int*)d_in[1];
    const float* W_nbr  = (const float*)d_in[2];
    const float* W_root = (const float*)d_in[3];
    const float* b_gnn  = (const float*)d_in[4];
    const float* W1     = (const float*)d_in[5];
    const float* b1     = (const float*)d_in[6];
    const float* W2     = (const float*)d_in[7];
    const float* b2     = (const float*)d_in[8];
    const float* g1     = (const float*)d_in[9];
    const float* be1    = (const float*)d_in[10];
    const float* g2     = (const float*)d_in[11];
    const float* be2    = (const float*)d_in[12];
    float* out = (float*)d_out;

    const int M = in_sizes[0] / HD;
    const int E = in_sizes[1] / 2;

    __half *xh, *agh, *hh, *th, *wnh, *wrh, *w1h, *w2h;
    int *zb, *off, *cur, *srcl;
    cudaGetSymbolAddress((void**)&xh, g_x_h);
    cudaGetSymbolAddress((void**)&agh, g_ag_h);
    cudaGetSymbolAddress((void**)&hh, g_h_h);
    cudaGetSymbolAddress((void**)&th, g_t_h);
    cudaGetSymbolAddress((void**)&wnh, g_wn_h);
    cudaGetSymbolAddress((void**)&wrh, g_wr_h);
    cudaGetSymbolAddress((void**)&w1h, g_w1_h);
    cudaGetSymbolAddress((void**)&w2h, g_w2_h);
    cudaGetSymbolAddress((void**)&zb, g_zb);
    cudaGetSymbolAddress((void**)&off, g_off);
    cudaGetSymbolAddress((void**)&cur, g_cur);
    cudaGetSymbolAddress((void**)&srcl, g_srcl);

    int* deg = zb;
    int nB = (M + SCAN_BLK - 1) / SCAN_BLK;
    int* state = zb + NMAX;

    cudaFuncSetAttribute(gemm_mma<0>, cudaFuncAttributeMaxDynamicSharedMemorySize, SMEM_TOTAL);
    cudaFuncSetAttribute(gemm_mma<1>, cudaFuncAttributeMaxDynamicSharedMemorySize, SMEM_TOTAL);

    // zero deg + lookback state in one node
    cudaMemsetAsync(zb, 0, (NMAX + NBMAX) * sizeof(int));

    int n4 = M * HD / 4;
    int nbConv = (n4 + 255) / 256;
    int nbHist = (E / 2 + 255) / 256;

    // fused: conv + weight transposes + degree histogram (independent work)
    prep_hist_kernel<<<nbConv + 384 + nbHist, 256>>>(
        x, xh, W_nbr, wnh, W_root, wrh, W1, w1h, W2, w2h,
        n4, nbConv, ei, E, deg);

    scan_kernel<<<nB, SCAN_BLK>>>(deg, off, cur, state, M);
    fill_kernel<<<nbHist, 256>>>(ei, E, cur, srcl);
    gather_kernel<<<(M + 7) / 8, 256>>>(off, srcl, xh, agh, M);

    int ntX = (M + 127) / 128;              // 391
    int grid0 = ntX < 148 ? ntX : 148;
    int nt1 = ntX * 2;
    int grid1 = nt1 < 148 ? nt1 : 148;

    // hh = fp16 LN1(x + agg@Wnbr + x@Wroot + b_gnn)   (resid = xh fp16)
    gemm_mma<0><<<grid0, 512, SMEM_TOTAL>>>(
        agh, wnh, HD, xh, wrh, HD, b_gnn, xh, g1, be1, nullptr, hh, M, ntX, ntX);

    // th = relu(hh@W1 + b1)
    gemm_mma<1><<<grid1, 512, SMEM_TOTAL>>>(
        hh, w1h, HD, nullptr, nullptr, 0,
        b1, nullptr, nullptr, nullptr, nullptr, th, M, ntX, nt1);

    // out = LN2(hh + th@W2 + b2)  fp32 to d_out  (resid = hh fp16)
    gemm_mma<0><<<grid0, 512, SMEM_TOTAL>>>(
        th, w2h, HF, nullptr, nullptr, 0,
        b2, hh, g2, be2, out, nullptr, M, ntX, ntX);
}

// round 17
// speedup vs baseline: 1.1012x; 1.0133x over previous
#include <cuda_runtime.h>
#include <cuda_fp16.h>
#include <cstdint>

#define HD 256
#define HF 512
#define NMAX 50000
#define EMAX 800000
#define SCAN_BLK 512
#define NBMAX ((NMAX + SCAN_BLK - 1) / SCAN_BLK)

// ------------------------- scratch (device globals) ------------------------
__device__ __half g_x_h[(size_t)NMAX * HD];
__device__ __half g_ag_h[(size_t)NMAX * HD];
__device__ __half g_h_h[(size_t)NMAX * HD];
__device__ __half g_t_h[(size_t)NMAX * HF];
__device__ __half g_wn_h[HD * HD];
__device__ __half g_wr_h[HD * HD];
__device__ __half g_w1_h[HD * HF];
__device__ __half g_w2_h[HD * HF];
__device__ int g_zb[NMAX + NBMAX];   // [0,NMAX)=deg, [NMAX,..)=lookback state
__device__ int g_off[NMAX + 1];
__device__ int g_cur[NMAX];
__device__ int g_srcl[EMAX];

// ----------------------------- helpers -------------------------------------
__device__ __forceinline__ uint32_t smem_u32(const void* p) {
    uint32_t a;
    asm("{ .reg .u64 t; cvta.to.shared.u64 t, %1; cvt.u32.u64 %0, t; }" : "=r"(a) : "l"(p));
    return a;
}
__device__ __forceinline__ void ldsm_x4(uint32_t* r, uint32_t addr) {
    asm volatile("ldmatrix.sync.aligned.m8n8.x4.shared.b16 {%0,%1,%2,%3}, [%4];"
                 : "=r"(r[0]), "=r"(r[1]), "=r"(r[2]), "=r"(r[3]) : "r"(addr));
}
__device__ __forceinline__ void mma_f16(float* d, const uint32_t* a, const uint32_t* b) {
    asm volatile(
        "mma.sync.aligned.m16n8k16.row.col.f32.f16.f16.f32 "
        "{%0,%1,%2,%3}, {%4,%5,%6,%7}, {%8,%9}, {%0,%1,%2,%3};"
        : "+f"(d[0]), "+f"(d[1]), "+f"(d[2]), "+f"(d[3])
        : "r"(a[0]), "r"(a[1]), "r"(a[2]), "r"(a[3]), "r"(b[0]), "r"(b[1]));
}
__device__ __forceinline__ void cp_async16(uint32_t dst, const void* src, int szr) {
    asm volatile("cp.async.cg.shared.global [%0], [%1], 16, %2;"
                 :: "r"(dst), "l"(src), "r"(szr) : "memory");
}
#define CP_COMMIT() asm volatile("cp.async.commit_group;" ::: "memory")
#define CP_WAIT2()  asm volatile("cp.async.wait_group 2;" ::: "memory")

__device__ __forceinline__ uint32_t packh2(float a, float b) {
    __half2 h = __float22half2_rn(make_float2(a, b));
    return *(uint32_t*)&h;
}

// inline int64/int32 edge-dtype detection: all odd words of first 128 pairs zero
__device__ __forceinline__ int detect_is64_block(const int* __restrict__ ei, int E) {
    int lim = 4 * E;
    if (lim > 256) lim = 256;
    int idx = threadIdx.x * 2 + 1;
    int nz = (threadIdx.x < 128 && idx < lim) ? ei[idx] : 0;
    int any = __syncthreads_or(nz != 0);
    return (any == 0) ? 1 : 0;
}

// ------------------ fused prep + histogram kernel ---------------------------
__device__ __forceinline__ void ttrans_tile(const float* W, __half* out,
                                            int K, int N, int kb, int nb,
                                            float (*tile)[33], int tid) {
    int tx = tid & 31, ty = tid >> 5;   // 32 x 8
    int k0 = kb * 32, n0 = nb * 32;
#pragma unroll
    for (int i = 0; i < 4; ++i)
        tile[ty + i * 8][tx] = W[(size_t)(k0 + ty + i * 8) * N + n0 + tx];
    __syncthreads();
#pragma unroll
    for (int i = 0; i < 4; ++i)
        out[(size_t)(n0 + ty + i * 8) * K + k0 + tx] =
            __float2half_rn(tile[tx][ty + i * 8]);
}

__global__ void prep_hist_kernel(
    const float* __restrict__ x, __half* __restrict__ xh,
    const float* __restrict__ Wn, __half* __restrict__ wnh,
    const float* __restrict__ Wr, __half* __restrict__ wrh,
    const float* __restrict__ W1, __half* __restrict__ w1h,
    const float* __restrict__ W2, __half* __restrict__ w2h,
    int n4, int nbConv,
    const int* __restrict__ ei, int E, int* __restrict__ deg) {
    __shared__ float tile[32][33];
    int b = blockIdx.x;
    int tid = threadIdx.x;
    if (b < nbConv) {
        int i = b * 256 + tid;
        if (i < n4) {
            float4 v = ((const float4*)x)[i];
            ((uint2*)xh)[i] = make_uint2(packh2(v.x, v.y), packh2(v.z, v.w));
        }
        return;
    }
    int t = b - nbConv;
    if (t < 384) {
        if (t < 64)        ttrans_tile(Wn, wnh, HD, HD, t & 7, t >> 3, tile, tid);
        else if (t < 128)  { t -= 64;  ttrans_tile(Wr, wrh, HD, HD, t & 7, t >> 3, tile, tid); }
        else if (t < 256)  { t -= 128; ttrans_tile(W1, w1h, HD, HF, t & 7, t >> 3, tile, tid); }
        else               { t -= 256; ttrans_tile(W2, w2h, HF, HD, t & 15, t >> 4, tile, tid); }
        return;
    }
    // ---- histogram segment ----
    int is64 = detect_is64_block(ei, E);
    int tt = (b - nbConv - 384) * 256 + tid;
    if (is64) {
        int e0 = tt * 2;
        if (e0 >= E) return;
        if (e0 + 2 <= E) {
            int4 d = *(const int4*)(ei + 2 * (E + e0));
            atomicAdd(&deg[d.x], 1);
            atomicAdd(&deg[d.z], 1);
        } else {
            atomicAdd(&deg[ei[2 * (E + e0)]], 1);
        }
    } else {
        int e0 = tt * 4;
        if (e0 >= E) return;
        if (e0 + 4 <= E) {
            int4 d = *(const int4*)(ei + E + e0);
            atomicAdd(&deg[d.x], 1);
            atomicAdd(&deg[d.y], 1);
            atomicAdd(&deg[d.z], 1);
            atomicAdd(&deg[d.w], 1);
        } else {
            for (int e = e0; e < E; ++e) atomicAdd(&deg[ei[E + e]], 1);
        }
    }
}

// ---- single-pass decoupled-lookback exclusive scan (nB <= 148 -> 1 wave) ---
#define FLAG_AGG (1 << 30)
#define FLAG_INC (1u << 31)
#define VALMASK  0x3FFFFFFF

__global__ void scan_kernel(const int* __restrict__ deg, int* __restrict__ off,
                            int* __restrict__ cur, int* __restrict__ state, int M) {
    __shared__ int wsum[SCAN_BLK / 32];
    __shared__ int s_pref;
    int b = blockIdx.x;
    int t = threadIdx.x;
    int i = b * SCAN_BLK + t;
    int lane = t & 31, wid = t >> 5;
    int v = (i < M) ? deg[i] : 0;
    int s = v;
#pragma unroll
    for (int o = 1; o < 32; o <<= 1) {
        int u = __shfl_up_sync(0xFFFFFFFFu, s, o);
        if (lane >= o) s += u;
    }
    if (lane == 31) wsum[wid] = s;
    __syncthreads();
    if (wid == 0) {
        int w = (lane < SCAN_BLK / 32) ? wsum[lane] : 0;
#pragma unroll
        for (int o = 1; o < SCAN_BLK / 32; o <<= 1) {
            int u = __shfl_up_sync(0xFFFFFFFFu, w, o);
            if (lane >= o) w += u;
        }
        if (lane < SCAN_BLK / 32) wsum[lane] = w;
    }
    __syncthreads();
    int excl = s - v + (wid ? wsum[wid - 1] : 0);

    if (t == 0) {
        int tot = wsum[SCAN_BLK / 32 - 1];
        if (b == 0) {
            atomicExch(&state[0], (int)(tot | FLAG_INC));
            s_pref = 0;
        } else {
            atomicExch(&state[b], tot | FLAG_AGG);
            int pref = 0, j = b - 1;
            while (true) {
                int st = atomicAdd(&state[j], 0);
                if ((unsigned)st & FLAG_INC) { pref += st & VALMASK; break; }
                if (st & FLAG_AGG)           { pref += st & VALMASK; --j; }
            }
            atomicExch(&state[b], (int)((tot + pref) | FLAG_INC));
            s_pref = pref;
        }
    }
    __syncthreads();
    int base = s_pref + excl;
    if (i < M) { off[i] = base; cur[i] = base; }
    if (i == M - 1) off[M] = base + v;
}

__global__ void fill_kernel(const int* __restrict__ ei, int E,
                            int* __restrict__ cur, int* __restrict__ srcl) {
    int is64 = detect_is64_block(ei, E);
    int t = blockIdx.x * blockDim.x + threadIdx.x;
    if (is64) {
        int e0 = t * 2;
        if (e0 >= E) return;
        if (e0 + 2 <= E) {
            int4 s = *(const int4*)(ei + 2 * e0);
            int4 d = *(const int4*)(ei + 2 * (E + e0));
            srcl[atomicAdd(&cur[d.x], 1)] = s.x;
            srcl[atomicAdd(&cur[d.z], 1)] = s.z;
        } else {
            srcl[atomicAdd(&cur[ei[2 * (E + e0)]], 1)] = ei[2 * e0];
        }
    } else {
        int e0 = t * 4;
        if (e0 >= E) return;
        if (e0 + 4 <= E) {
            int4 s = *(const int4*)(ei + e0);
            int4 d = *(const int4*)(ei + E + e0);
            srcl[atomicAdd(&cur[d.x], 1)] = s.x;
            srcl[atomicAdd(&cur[d.y], 1)] = s.y;
            srcl[atomicAdd(&cur[d.z], 1)] = s.z;
            srcl[atomicAdd(&cur[d.w], 1)] = s.w;
        } else {
            for (int e = e0; e < E; ++e)
                srcl[atomicAdd(&cur[ei[E + e]], 1)] = ei[e];
        }
    }
}

// gather: one warp per node; pipelined srcl prefetch; pairwise HADD2
// pre-reduction (2 neighbors per fp16 add) then fp32 accumulate.
__global__ void __launch_bounds__(256)
gather_kernel(const int* __restrict__ off, const int* __restrict__ srcl,
              const __half* __restrict__ xh, __half* __restrict__ agh, int M) {
    int node = blockIdx.x * 8 + (threadIdx.x >> 5);
    int lane = threadIdx.x & 31;
    if (node >= M) return;
    int j0 = off[node], j1 = off[node + 1];

    float acc[8];
#pragma unroll
    for (int k = 0; k < 8; ++k) acc[k] = 0.f;

    const uint4* xb = (const uint4*)xh;
    int nfull = (j1 - j0) >> 3;
    int srcs[8];
    if (nfull > 0) {
#pragma unroll
        for (int u = 0; u < 8; ++u) srcs[u] = srcl[j0 + u];
    }
    for (int b = 0; b < nfull; ++b) {
        uint4 v[8];
#pragma unroll
        for (int u = 0; u < 8; ++u) v[u] = xb[(size_t)srcs[u] * 32 + lane];
        int nsrcs[8];
        bool more = (b + 1 < nfull);
        if (more) {
            int jn = j0 + (b + 1) * 8;
#pragma unroll
            for (int u = 0; u < 8; ++u) nsrcs[u] = srcl[jn + u];
        }
#pragma unroll
        for (int u = 0; u < 8; u += 2) {
            const __half2* pa = (const __half2*)&v[u];
            const __half2* pb = (const __half2*)&v[u + 1];
#pragma unroll
            for (int w = 0; w < 4; ++w) {
                float2 f = __half22float2(__hadd2(pa[w], pb[w]));
                acc[2 * w]     += f.x;
                acc[2 * w + 1] += f.y;
            }
        }
        if (more) {
#pragma unroll
            for (int u = 0; u < 8; ++u) srcs[u] = nsrcs[u];
        }
    }
    for (int j = j0 + nfull * 8; j < j1; ++j) {
        uint4 v = xb[(size_t)srcl[j] * 32 + lane];
        float2 f0 = __half22float2(*(const __half2*)&v.x);
        float2 f1 = __half22float2(*(const __half2*)&v.y);
        float2 f2 = __half22float2(*(const __half2*)&v.z);
        float2 f3 = __half22float2(*(const __half2*)&v.w);
        acc[0] += f0.x; acc[1] += f0.y; acc[2] += f1.x; acc[3] += f1.y;
        acc[4] += f2.x; acc[5] += f2.y; acc[6] += f3.x; acc[7] += f3.y;
    }

    uint32_t hi[4];
#pragma unroll
    for (int k = 0; k < 4; ++k) hi[k] = packh2(acc[2 * k], acc[2 * k + 1]);
    ((uint4*)agh)[(size_t)node * 32 + lane] = make_uint4(hi[0], hi[1], hi[2], hi[3]);
}

// ----------------------- fp16 mma.sync GEMM (persistent tiles) -------------
// BM=128, BN=256, BK=64, 512 threads, 4-stage cp.async ring (wait_group 2).
// Row = 128B data + 16B pad = 144B (9x16B; 9 = 1 mod 8 -> conflict-free).
#define RB 144
#define A_TILE (128 * RB)
#define B_TILE (256 * RB)
#define STAGE_BYTES (A_TILE + B_TILE)
#define NSTAGE 4
#define SMEM_TOTAL (NSTAGE * STAGE_BYTES)

__device__ __forceinline__ void load_stage(
    uint32_t sa, int tid, int row0, int col0,
    const __half* A, const __half* B, int K, int kc, int M) {
#pragma unroll
    for (int j = 0; j < 2; ++j) {        // A: 1024 chunks of 16B
        int id = tid + j * 512;
        int r = id >> 3, c = id & 7;
        int row = row0 + r;
        int szr = (row < M) ? 16 : 0;
        size_t roff = (row < M) ? (size_t)row : 0;
        cp_async16(sa + r * RB + c * 16, A + roff * K + kc + c * 8, szr);
    }
    uint32_t sb = sa + A_TILE;
#pragma unroll
    for (int j = 0; j < 4; ++j) {        // B: 2048 chunks
        int id = tid + j * 512;
        int r = id >> 3, c = id & 7;
        cp_async16(sb + r * RB + c * 16, B + (size_t)(col0 + r) * K + kc + c * 8, 16);
    }
}

// MODE 0: C = A@B(+A1@B1) + bias + resid(fp16) -> LN -> outf(fp32)? / outh(fp16)?
// MODE 1: C = relu(A@B + bias) -> fp16 outh (stride HF)
template <int MODE>
__global__ void __launch_bounds__(512, 1)
gemm_mma(const __half* __restrict__ A0, const __half* __restrict__ B0, int K0,
         const __half* __restrict__ A1, const __half* __restrict__ B1, int K1,
         const float* __restrict__ bias, const __half* __restrict__ resid,
         const float* __restrict__ gamma, const float* __restrict__ beta,
         float* __restrict__ outf, __half* __restrict__ outh, int M,
         int ntX, int ntTotal) {
    extern __shared__ char smem[];
    const uint32_t sb0 = smem_u32(smem);
    const int tid = threadIdx.x;
    const int lane = tid & 31;
    const int warp = tid >> 5;           // 0..15
    const int warpM = warp >> 2;         // 0..3
    const int warpN = warp & 3;          // 0..3

    const int S = (K0 + K1) >> 6;

    const uint32_t aoff = (uint32_t)((warpM * 32 + (lane & 7) + ((lane >> 3) & 1) * 8) * RB
                                     + (lane >> 4) * 16);
    const uint32_t boff4 = (uint32_t)((warpN * 64 + (lane & 7) + (lane >> 4) * 8) * RB
                                      + ((lane >> 3) & 1) * 16);

#define RESOLVE(IT, AH, BH, KK, KC)                             \
    { int kt = (IT) * 64;                                       \
      if (kt < K0) { AH = A0; BH = B0; KK = K0; KC = kt; }      \
      else         { AH = A1; BH = B1; KK = K1; KC = kt - K0; } }

    for (int tile = blockIdx.x; tile < ntTotal; tile += gridDim.x) {
        const int row0 = (tile % ntX) * 128;
        const int col0 = (tile / ntX) * 256;

        float acc[2][8][4];
#pragma unroll
        for (int i = 0; i < 2; ++i)
#pragma unroll
            for (int j = 0; j < 8; ++j)
#pragma unroll
                for (int k = 0; k < 4; ++k) acc[i][j][k] = 0.f;

        __syncthreads();    // protect prior epilogue smem reads from new loads

        // prologue: stages 0..2 (uniform commits)
#pragma unroll
        for (int p = 0; p < NSTAGE - 1; ++p) {
            if (p < S) {
                const __half *Ah, *Bh; int KK, KC;
                RESOLVE(p, Ah, Bh, KK, KC);
                load_stage(sb0 + p * STAGE_BYTES, tid, row0, col0, Ah, Bh, KK, KC, M);
            }
            CP_COMMIT();
        }

        int stage = 0;
        for (int it = 0; it < S; ++it) {
            CP_WAIT2();
            __syncthreads();
            if (it + NSTAGE - 1 < S) {
                int s2 = stage + NSTAGE - 1; if (s2 >= NSTAGE) s2 -= NSTAGE;
                const __half *Ah, *Bh; int KK, KC;
                RESOLVE(it + NSTAGE - 1, Ah, Bh, KK, KC);
                load_stage(sb0 + s2 * STAGE_BYTES, tid, row0, col0, Ah, Bh, KK, KC, M);
            }
            CP_COMMIT();

            const uint32_t sa = sb0 + stage * STAGE_BYTES;
            const uint32_t sbB = sa + A_TILE;
#pragma unroll
            for (int ks = 0; ks < 4; ++ks) {
                uint32_t ah[2][4];
#pragma unroll
                for (int tm = 0; tm < 2; ++tm)
                    ldsm_x4(ah[tm], sa + aoff + tm * (16 * RB) + ks * 32);
#pragma unroll
                for (int tnp = 0; tnp < 4; ++tnp) {
                    uint32_t bh[4];
                    ldsm_x4(bh, sbB + boff4 + tnp * (16 * RB) + ks * 32);
#pragma unroll
                    for (int tm = 0; tm < 2; ++tm) {
                        mma_f16(acc[tm][2 * tnp + 0], ah[tm], bh);
                        mma_f16(acc[tm][2 * tnp + 1], ah[tm], bh + 2);
                    }
                }
            }
            ++stage; if (stage == NSTAGE) stage = 0;
        }

        // prefetch epilogue params before final drain
        float rbias = 0.f, rgam = 0.f, rbet = 0.f;
        if (tid < 256) {
            rbias = bias[col0 + tid];
            if (MODE == 0) { rgam = gamma[tid]; rbet = beta[tid]; }
        }

        __syncthreads();

        // ---------------------------- epilogue -----------------------------
        float* rsum  = (float*)smem;          // 128
        float* rsq   = rsum + 128;            // 128
        float* sbias = rsq + 128;             // 256
        float* sgam  = sbias + 256;
        float* sbet  = sgam + 256;
        if (MODE == 0 && tid < 128) { rsum[tid] = 0.f; rsq[tid] = 0.f; }
        if (tid < 256) {
            sbias[tid] = rbias;
            if (MODE == 0) { sgam[tid] = rgam; sbet[tid] = rbet; }
        }
        __syncthreads();

        const int qrow = lane >> 2;
        const int qc = (lane & 3) * 2;

        float vsum[4], vsq[4];
#pragma unroll
        for (int k = 0; k < 4; ++k) { vsum[k] = 0.f; vsq[k] = 0.f; }

#pragma unroll
        for (int tm = 0; tm < 2; ++tm) {
#pragma unroll
            for (int rh = 0; rh < 2; ++rh) {
                int rloc = warpM * 32 + tm * 16 + rh * 8 + qrow;
                int rg = row0 + rloc;
                bool v = rg < M;
#pragma unroll
                for (int tn = 0; tn < 8; ++tn) {
                    int c = warpN * 64 + tn * 8 + qc;
                    float a0 = acc[tm][tn][rh * 2 + 0] + sbias[c];
                    float a1 = acc[tm][tn][rh * 2 + 1] + sbias[c + 1];
                    if (MODE == 0) {
                        if (v) {
                            uint32_t rp = ((const uint32_t*)resid)[((size_t)rg * 256 + c) >> 1];
                            float2 q = __half22float2(*(const __half2*)&rp);
                            a0 += q.x; a1 += q.y;
                        }
                        vsum[tm * 2 + rh] += a0 + a1;
                        vsq[tm * 2 + rh] += a0 * a0 + a1 * a1;
                    } else {
                        a0 = fmaxf(a0, 0.f); a1 = fmaxf(a1, 0.f);
                    }
                    acc[tm][tn][rh * 2 + 0] = a0;
                    acc[tm][tn][rh * 2 + 1] = a1;
                }
            }
        }

        if (MODE == 0) {
#pragma unroll
            for (int k = 0; k < 4; ++k) {
                vsum[k] += __shfl_xor_sync(0xFFFFFFFFu, vsum[k], 1);
                vsum[k] += __shfl_xor_sync(0xFFFFFFFFu, vsum[k], 2);
                vsq[k]  += __shfl_xor_sync(0xFFFFFFFFu, vsq[k], 1);
                vsq[k]  += __shfl_xor_sync(0xFFFFFFFFu, vsq[k], 2);
            }
            if ((lane & 3) == 0) {
#pragma unroll
                for (int tm = 0; tm < 2; ++tm)
#pragma unroll
                    for (int rh = 0; rh < 2; ++rh) {
                        int rloc = warpM * 32 + tm * 16 + rh * 8 + qrow;
                        atomicAdd(&rsum[rloc], vsum[tm * 2 + rh]);
                        atomicAdd(&rsq[rloc], vsq[tm * 2 + rh]);
                    }
            }
            __syncthreads();
        }

#pragma unroll
        for (int tm = 0; tm < 2; ++tm) {
#pragma unroll
            for (int rh = 0; rh < 2; ++rh) {
                int rloc = warpM * 32 + tm * 16 + rh * 8 + qrow;
                int rg = row0 + rloc;
                if (rg >= M) continue;
                float mean = 0.f, inv = 1.f;
                if (MODE == 0) {
                    mean = rsum[rloc] * (1.f / 256.f);
                    inv = rsqrtf(rsq[rloc] * (1.f / 256.f) - mean * mean + 1e-5f);
                }
#pragma unroll
                for (int tn = 0; tn < 8; ++tn) {
                    int c = warpN * 64 + tn * 8 + qc;
                    float a0 = acc[tm][tn][rh * 2 + 0];
                    float a1 = acc[tm][tn][rh * 2 + 1];
                    if (MODE == 0) {
                        a0 = (a0 - mean) * inv * sgam[c] + sbet[c];
                        a1 = (a1 - mean) * inv * sgam[c + 1] + sbet[c + 1];
                        if (outf != nullptr)
                            *(float2*)(outf + (size_t)rg * 256 + c) = make_float2(a0, a1);
                        if (outh != nullptr)
                            ((uint32_t*)outh)[((size_t)rg * 256 + c) >> 1] = packh2(a0, a1);
                    } else {
                        ((uint32_t*)outh)[((size_t)rg * HF + col0 + c) >> 1] = packh2(a0, a1);
                    }
                }
            }
        }
    }
}

// ------------------------------ launch --------------------------------------
extern "C" void kernel_launch(void* const* d_in, const int* in_sizes, int n_in,
                              void* d_out, int out_size) {
    const float* x      = (const float*)d_in[0];
    const int*   ei     = (const int*)d_in[1];
    const float* W_nbr  = (const float*)d_in[2];
    const float* W_root = (const float*)d_in[3];
    const float* b_gnn  = (const float*)d_in[4];
    const float* W1     = (const float*)d_in[5];
    const float* b1     = (const float*)d_in[6];
    const float* W2     = (const float*)d_in[7];
    const float* b2     = (const float*)d_in[8];
    const float* g1     = (const float*)d_in[9];
    const float* be1    = (const float*)d_in[10];
    const float* g2     = (const float*)d_in[11];
    const float* be2    = (const float*)d_in[12];
    float* out = (float*)d_out;

    const int M = in_sizes[0] / HD;
    const int E = in_sizes[1] / 2;

    __half *xh, *agh, *hh, *th, *wnh, *wrh, *w1h, *w2h;
    int *zb, *off, *cur, *srcl;
    cudaGetSymbolAddress((void**)&xh, g_x_h);
    cudaGetSymbolAddress((void**)&agh, g_ag_h);
    cudaGetSymbolAddress((void**)&hh, g_h_h);
    cudaGetSymbolAddress((void**)&th, g_t_h);
    cudaGetSymbolAddress((void**)&wnh, g_wn_h);
    cudaGetSymbolAddress((void**)&wrh, g_wr_h);
    cudaGetSymbolAddress((void**)&w1h, g_w1_h);
    cudaGetSymbolAddress((void**)&w2h, g_w2_h);
    cudaGetSymbolAddress((void**)&zb, g_zb);
    cudaGetSymbolAddress((void**)&off, g_off);
    cudaGetSymbolAddress((void**)&cur, g_cur);
    cudaGetSymbolAddress((void**)&srcl, g_srcl);

    int* deg = zb;
    int nB = (M + SCAN_BLK - 1) / SCAN_BLK;
    int* state = zb + NMAX;

    cudaFuncSetAttribute(gemm_mma<0>, cudaFuncAttributeMaxDynamicSharedMemorySize, SMEM_TOTAL);
    cudaFuncSetAttribute(gemm_mma<1>, cudaFuncAttributeMaxDynamicSharedMemorySize, SMEM_TOTAL);

    // zero deg + lookback state in one node
    cudaMemsetAsync(zb, 0, (NMAX + NBMAX) * sizeof(int));

    int n4 = M * HD / 4;
    int nbConv = (n4 + 255) / 256;
    int nbHist = (E / 2 + 255) / 256;

    // fused: conv + weight transposes + degree histogram (independent work)
    prep_hist_kernel<<<nbConv + 384 + nbHist, 256>>>(
        x, xh, W_nbr, wnh, W_root, wrh, W1, w1h, W2, w2h,
        n4, nbConv, ei, E, deg);

    scan_kernel<<<nB, SCAN_BLK>>>(deg, off, cur, state, M);
    fill_kernel<<<nbHist, 256>>>(ei, E, cur, srcl);
    gather_kernel<<<(M + 7) / 8, 256>>>(off, srcl, xh, agh, M);

    int ntX = (M + 127) / 128;              // 391
    int grid0 = ntX < 148 ? ntX : 148;
    int nt1 = ntX * 2;
    int grid1 = nt1 < 148 ? nt1 : 148;

    // hh = fp16 LN1(x + agg@Wnbr + x@Wroot + b_gnn)   (resid = xh fp16)
    gemm_mma<0><<<grid0, 512, SMEM_TOTAL>>>(
        agh, wnh, HD, xh, wrh, HD, b_gnn, xh, g1, be1, nullptr, hh, M, ntX, ntX);

    // th = relu(hh@W1 + b1)
    gemm_mma<1><<<grid1, 512, SMEM_TOTAL>>>(
        hh, w1h, HD, nullptr, nullptr, 0,
        b1, nullptr, nullptr, nullptr, nullptr, th, M, ntX, nt1);

    // out = LN2(hh + th@W2 + b2)  fp32 to d_out  (resid = hh fp16)
    gemm_mma<0><<<grid0, 512, SMEM_TOTAL>>>(
        th, w2h, HF, nullptr, nullptr, 0,
        b2, hh, g2, be2, out, nullptr, M, ntX, ntX);
}